// round 8
// baseline (speedup 1.0000x reference)
#include <cuda_runtime.h>
#include <cuda_bf16.h>
#include <cstdint>

#define SEQ   2048
#define NTOK  8192

// ---------------- scratch (device globals: no runtime allocation) ----------
// interleaved split layout: [row][k/32][32 hi bf16 | 32 lo bf16]  (128B rows)
__device__ __nv_bfloat16 g_qlat_s [(size_t)NTOK * 128];
__device__ __nv_bfloat16 g_kvlat_s[(size_t)NTOK * 128];
__device__ __nv_bfloat16 g_wq_s   [(size_t)1024 * 128];
__device__ __nv_bfloat16 g_wkv_s  [(size_t)2048 * 128];
__device__ __nv_bfloat16 g_wproj_s[(size_t)1024 * 2048];
__device__ __nv_bfloat16 g_ys     [(size_t)NTOK * 2048];
// per-head split tensors for attention [(b*16+h)][seq][64]
__device__ __nv_bfloat16 g_qh[(size_t)NTOK * 1024];
__device__ __nv_bfloat16 g_ql[(size_t)NTOK * 1024];
__device__ __nv_bfloat16 g_kh[(size_t)NTOK * 1024];
__device__ __nv_bfloat16 g_kl[(size_t)NTOK * 1024];
__device__ __nv_bfloat16 g_vh[(size_t)NTOK * 1024];
__device__ __nv_bfloat16 g_vl[(size_t)NTOK * 1024];

#define QSCALE (0.125f * 1.4426950408889634f)   // fold softmax scale * log2e

// ---------------- helpers ---------------------------------------------------
static __device__ __forceinline__ uint32_t smem_u32(const void* p) {
    uint32_t a;
    asm("{ .reg .u64 t; cvta.to.shared.u64 t, %1; cvt.u32.u64 %0, t; }"
        : "=r"(a) : "l"(p));
    return a;
}
static __device__ __forceinline__ uint32_t bfpack(float lo, float hi) {
    uint32_t r;
    asm("cvt.rn.bf16x2.f32 %0, %1, %2;" : "=r"(r) : "f"(hi), "f"(lo));
    return r;
}
static __device__ __forceinline__ void split2(float x, float y,
                                              uint32_t& h, uint32_t& l) {
    h = bfpack(x, y);
    __nv_bfloat162 hb = *reinterpret_cast<__nv_bfloat162*>(&h);
    l = bfpack(x - __bfloat162float(hb.x), y - __bfloat162float(hb.y));
}
static __device__ __forceinline__ float ex2f(float x) {
    float y; asm("ex2.approx.f32 %0, %1;" : "=f"(y) : "f"(x)); return y;
}
// swizzled smem addr: 128B rows of 8 x 16B chunks, chunk ^= row&7
static __device__ __forceinline__ uint32_t lda(uint32_t base, int row, int ch) {
    return base + row * 128 + (((uint32_t)ch ^ ((uint32_t)row & 7u)) << 4);
}

#define MMAB(c, a0, a1, a2, a3, b0, b1)                                        \
    asm volatile("mma.sync.aligned.m16n8k16.row.col.f32.bf16.bf16.f32 "        \
        "{%0,%1,%2,%3},{%4,%5,%6,%7},{%8,%9},{%0,%1,%2,%3};"                   \
        : "+f"((c)[0]), "+f"((c)[1]), "+f"((c)[2]), "+f"((c)[3])               \
        : "r"(a0), "r"(a1), "r"(a2), "r"(a3), "r"(b0), "r"(b1))

#define MMAX3(c, ah, al, bh0, bh1, bl0, bl1) do {                              \
    MMAB(c, (ah)[0], (ah)[1], (ah)[2], (ah)[3], bh0, bh1);                     \
    MMAB(c, (ah)[0], (ah)[1], (ah)[2], (ah)[3], bl0, bl1);                     \
    MMAB(c, (al)[0], (al)[1], (al)[2], (al)[3], bh0, bh1);                     \
} while (0)

#define LDSM4(r, addr)                                                         \
    asm volatile("ldmatrix.sync.aligned.m8n8.x4.shared.b16 {%0,%1,%2,%3}, [%4];" \
        : "=r"((r)[0]), "=r"((r)[1]), "=r"((r)[2]), "=r"((r)[3]) : "r"(addr))
#define LDSM4T(r, addr)                                                        \
    asm volatile("ldmatrix.sync.aligned.m8n8.x4.trans.shared.b16 {%0,%1,%2,%3}, [%4];" \
        : "=r"((r)[0]), "=r"((r)[1]), "=r"((r)[2]), "=r"((r)[3]) : "r"(addr))
#define CPA16(dst, src)                                                        \
    asm volatile("cp.async.cg.shared.global [%0], [%1], 16;" :: "r"(dst), "l"(src))
#define CPCOMMIT() asm volatile("cp.async.commit_group;" ::: "memory")
#define CPWAIT(n)  asm volatile("cp.async.wait_group %0;" :: "n"(n) : "memory")

// ======================================================================
// wsplit: W[n][K] fp32 -> O[n][K/32][32h|32l] bf16
// ======================================================================
__global__ __launch_bounds__(256) void wsplit(
    const float* __restrict__ W, __nv_bfloat16* __restrict__ O,
    int K, int nf4)
{
    int idx = blockIdx.x * 256 + threadIdx.x;
    if (idx >= nf4) return;
    int K4 = K >> 2;
    int n = idx / K4, k4 = idx - n * K4;
    float4 v = *(const float4*)&W[(size_t)n * K + k4 * 4];
    int k = k4 * 4, kc = k >> 5, p = k & 31;
    size_t o = ((size_t)n * (K >> 5) + kc) * 64 + p;
    uint32_t h0, l0, h1, l1;
    split2(v.x, v.y, h0, l0); split2(v.z, v.w, h1, l1);
    *(uint32_t*)&O[o]      = h0;  *(uint32_t*)&O[o + 2]  = h1;
    *(uint32_t*)&O[o + 32] = l0;  *(uint32_t*)&O[o + 34] = l1;
}

// ======================================================================
// gemm_bf<MODE>: C = A[M,K] @ B[N,K]^T, both pre-split interleaved bf16.
// BK=32, cp.async 3-STAGE ring, ldmatrix, x3 MMA. 2 CTAs/SM.
// MODE 0: q-up (scale QSCALE -> qh/ql per-head)
// MODE 1: kv-up (k->H,L / v->H2,L2)      MODE 2: fp32 out (Cf)
// ======================================================================
#define GEMMBF_SMEM 98304

template<int MODE>
__global__ __launch_bounds__(256, 2) void gemm_bf(
    const __nv_bfloat16* __restrict__ A, const __nv_bfloat16* __restrict__ B,
    float* __restrict__ Cf,
    __nv_bfloat16* __restrict__ H,  __nv_bfloat16* __restrict__ L,
    __nv_bfloat16* __restrict__ H2, __nv_bfloat16* __restrict__ L2,
    int K, int N)
{
    extern __shared__ char smraw[];
    const uint32_t base = smem_u32(smraw);
    // stage s: A at base + s*32768, B at +16384

    const int tid = threadIdx.x;
    const int w = tid >> 5, lane = tid & 31;
    const int g = lane >> 2, tig = lane & 3;
    const int l8 = lane & 7, sub = lane >> 3;
    const int wm = w & 1, wn = w >> 1;
    const int m0 = blockIdx.y * 128, n0 = blockIdx.x * 128;
    const int KC = K >> 5, CH = KC;

    float c[4][4][4] = {};

    // stage chunks 0,1,2 (empty commits keep group counting uniform)
    #pragma unroll
    for (int s = 0; s < 3; s++) {
        if (s < CH) {
            #pragma unroll
            for (int p = 0; p < 4; p++) {
                int idx = tid + p * 256, row = idx >> 3, ch = idx & 7;
                CPA16(lda(base + s * 32768, row, ch),
                      A + ((size_t)(m0 + row) * KC + s) * 64 + ch * 8);
                CPA16(lda(base + s * 32768 + 16384, row, ch),
                      B + ((size_t)(n0 + row) * KC + s) * 64 + ch * 8);
            }
        }
        CPCOMMIT();
    }

    int rb = 0;   // ring buffer index = cc % 3
    for (int cc = 0; cc < CH; cc++) {
        const uint32_t Ab = base + rb * 32768;
        const uint32_t Bb = Ab + 16384;
        CPWAIT(2);
        __syncthreads();

        #pragma unroll
        for (int ks = 0; ks < 2; ks++) {
            uint32_t ah[4][4], al[4][4];
            #pragma unroll
            for (int mt = 0; mt < 4; mt++) {
                int arow = wm * 64 + mt * 16 + l8 + ((sub & 1) << 3);
                int hch  = 2 * ks + (sub >> 1);
                LDSM4(ah[mt], lda(Ab, arow, hch));
                LDSM4(al[mt], lda(Ab, arow, hch + 4));
            }
            #pragma unroll
            for (int np = 0; np < 2; np++) {
                int brow = wn * 32 + np * 16 + ((sub >> 1) << 3) + l8;
                int bch  = 2 * ks + (sub & 1);
                uint32_t bhf[4], blf[4];
                LDSM4(bhf, lda(Bb, brow, bch));
                LDSM4(blf, lda(Bb, brow, bch + 4));
                #pragma unroll
                for (int mt = 0; mt < 4; mt++) {
                    MMAX3(c[mt][2*np],   ah[mt], al[mt], bhf[0], bhf[1], blf[0], blf[1]);
                    MMAX3(c[mt][2*np+1], ah[mt], al[mt], bhf[2], bhf[3], blf[2], blf[3]);
                }
            }
        }

        __syncthreads();
        if (cc + 3 < CH) {
            #pragma unroll
            for (int p = 0; p < 4; p++) {
                int idx = tid + p * 256, row = idx >> 3, ch = idx & 7;
                CPA16(lda(Ab, row, ch),
                      A + ((size_t)(m0 + row) * KC + cc + 3) * 64 + ch * 8);
                CPA16(lda(Bb, row, ch),
                      B + ((size_t)(n0 + row) * KC + cc + 3) * 64 + ch * 8);
            }
        }
        CPCOMMIT();
        if (++rb == 3) rb = 0;
    }

    if (MODE == 2) {
        #pragma unroll
        for (int mt = 0; mt < 4; mt++)
            #pragma unroll
            for (int nt = 0; nt < 4; nt++) {
                int r0 = m0 + wm * 64 + mt * 16 + g;
                int col = n0 + wn * 32 + nt * 8 + 2 * tig;
                *(float2*)&Cf[(size_t)r0 * N + col]       = make_float2(c[mt][nt][0], c[mt][nt][1]);
                *(float2*)&Cf[(size_t)(r0 + 8) * N + col] = make_float2(c[mt][nt][2], c[mt][nt][3]);
            }
    } else {
        const float sc = (MODE == 0) ? QSCALE : 1.0f;
        #pragma unroll
        for (int mt = 0; mt < 4; mt++)
            #pragma unroll
            for (int nt = 0; nt < 4; nt++) {
                int tok = m0 + wm * 64 + mt * 16 + g;
                int col = n0 + wn * 32 + nt * 8 + 2 * tig;
                int b = tok >> 11, tn = tok & 2047;
                int h, d;
                __nv_bfloat16 *DH, *DL;
                if (MODE == 0) {
                    h = col >> 6; d = col & 63; DH = H; DL = L;
                } else {
                    h = col >> 7; int rr = col & 127; d = rr & 63;
                    if (rr < 64) { DH = H; DL = L; } else { DH = H2; DL = L2; }
                }
                size_t a0 = (((size_t)b * 16 + h) * SEQ + tn) * 64 + d;
                size_t a1 = a0 + 8 * 64;
                uint32_t hp, lp;
                split2(c[mt][nt][0] * sc, c[mt][nt][1] * sc, hp, lp);
                *(uint32_t*)&DH[a0] = hp;  *(uint32_t*)&DL[a0] = lp;
                split2(c[mt][nt][2] * sc, c[mt][nt][3] * sc, hp, lp);
                *(uint32_t*)&DH[a1] = hp;  *(uint32_t*)&DL[a1] = lp;
            }
    }
}

// ======================================================================
// gemm_lat2: BOTH latent projections in one launch (blockIdx.y selects).
// out = rmsnorm(A @ W^T) * nw, written split-interleaved [tok][2][64]
// DISTANCE-2 register prefetch (1 CTA/SM at grid 128, regs are free).
// ======================================================================
__global__ __launch_bounds__(256, 2) void gemm_lat2(
    const float* __restrict__ A,
    const float* __restrict__ Wq, const float* __restrict__ Wkv,
    const float* __restrict__ nwq, const float* __restrict__ nwkv,
    __nv_bfloat16* __restrict__ Cq, __nv_bfloat16* __restrict__ Ckv)
{
    __shared__ uint32_t AsW[2][128 * 20];
    __shared__ uint32_t BsW[2][64 * 20];
    __shared__ float ssm[2][128];
    __shared__ float nws[64];
    const float* W  = blockIdx.y ? Wkv  : Wq;
    const float* nw = blockIdx.y ? nwkv : nwq;
    __nv_bfloat16* C = blockIdx.y ? Ckv : Cq;

    const int tid = threadIdx.x;
    const int w = tid >> 5, lane = tid & 31;
    const int g = lane >> 2, tig = lane & 3;
    const int wm = w >> 1, wn = w & 1;
    const int m0 = blockIdx.x * 128;

    if (tid < 64) nws[tid] = nw[tid];

    float c[2][4][4] = {};
    float4 pa[2][2], pbv[2];   // [set = chunk&1]

    // stage chunk 0 directly into smem buf 0
    #pragma unroll
    for (int p = 0; p < 2; p++) {
        int f = tid + p * 256, r = f >> 2, c4 = f & 3;
        float4 va = *(const float4*)&A[(size_t)(m0 + r) * 1024 + c4 * 4];
        uint32_t h0, h1, l0, l1;
        split2(va.x, va.y, h0, l0); split2(va.z, va.w, h1, l1);
        AsW[0][r*20+2*c4] = h0;     AsW[0][r*20+2*c4+1] = h1;
        AsW[0][r*20+8+2*c4] = l0;   AsW[0][r*20+9+2*c4] = l1;
    }
    {
        int r = tid >> 2, c4 = tid & 3;
        float4 vb = *(const float4*)&W[(size_t)r * 1024 + c4 * 4];
        uint32_t h0, h1, l0, l1;
        split2(vb.x, vb.y, h0, l0); split2(vb.z, vb.w, h1, l1);
        BsW[0][r*20+2*c4] = h0;     BsW[0][r*20+2*c4+1] = h1;
        BsW[0][r*20+8+2*c4] = l0;   BsW[0][r*20+9+2*c4] = l1;
    }
    // preload chunk 1 into reg set 1
    #pragma unroll
    for (int p = 0; p < 2; p++) {
        int f = tid + p * 256, r = f >> 2, c4 = f & 3;
        pa[1][p] = *(const float4*)&A[(size_t)(m0 + r) * 1024 + 16 + c4 * 4];
    }
    {
        int r = tid >> 2, c4 = tid & 3;
        pbv[1] = *(const float4*)&W[(size_t)r * 1024 + 16 + c4 * 4];
    }
    __syncthreads();

    for (int cc = 0; cc < 64; cc++) {
        const int bi = cc & 1;
        const uint32_t* As = AsW[bi];
        const uint32_t* Bs = BsW[bi];
        uint32_t ah[2][4], al[2][4];
        #pragma unroll
        for (int mt = 0; mt < 2; mt++) {
            int r = wm * 32 + mt * 16 + g;
            ah[mt][0] = As[r*20+tig];      ah[mt][1] = As[(r+8)*20+tig];
            ah[mt][2] = As[r*20+4+tig];    ah[mt][3] = As[(r+8)*20+4+tig];
            al[mt][0] = As[r*20+8+tig];    al[mt][1] = As[(r+8)*20+8+tig];
            al[mt][2] = As[r*20+12+tig];   al[mt][3] = As[(r+8)*20+12+tig];
        }
        // LDG chunk cc+2 into reg set (cc&1)
        if (cc + 2 < 64) {
            #pragma unroll
            for (int p = 0; p < 2; p++) {
                int f = tid + p * 256, r = f >> 2, c4 = f & 3;
                pa[bi][p] = *(const float4*)&A[(size_t)(m0+r)*1024 + (cc+2)*16 + c4*4];
            }
            int r = tid >> 2, c4 = tid & 3;
            pbv[bi] = *(const float4*)&W[(size_t)r * 1024 + (cc+2)*16 + c4*4];
        }
        #pragma unroll
        for (int nt = 0; nt < 4; nt++) {
            int rn = wn * 32 + nt * 8 + g;
            uint32_t bh0 = Bs[rn*20+tig],   bh1 = Bs[rn*20+4+tig];
            uint32_t bl0 = Bs[rn*20+8+tig], bl1 = Bs[rn*20+12+tig];
            #pragma unroll
            for (int mt = 0; mt < 2; mt++)
                MMAX3(c[mt][nt], ah[mt], al[mt], bh0, bh1, bl0, bl1);
        }
        // STS chunk cc+1 from reg set ((cc+1)&1) into smem buf (cc+1)&1
        if (cc + 1 < 64) {
            const int si = (cc + 1) & 1;
            #pragma unroll
            for (int p = 0; p < 2; p++) {
                int f = tid + p * 256, r = f >> 2, c4 = f & 3;
                uint32_t h0, h1, l0, l1;
                split2(pa[si][p].x, pa[si][p].y, h0, l0);
                split2(pa[si][p].z, pa[si][p].w, h1, l1);
                AsW[si][r*20+2*c4] = h0;     AsW[si][r*20+2*c4+1] = h1;
                AsW[si][r*20+8+2*c4] = l0;   AsW[si][r*20+9+2*c4] = l1;
            }
            int r = tid >> 2, c4 = tid & 3;
            uint32_t h0, h1, l0, l1;
            split2(pbv[si].x, pbv[si].y, h0, l0);
            split2(pbv[si].z, pbv[si].w, h1, l1);
            BsW[si][r*20+2*c4] = h0;     BsW[si][r*20+2*c4+1] = h1;
            BsW[si][r*20+8+2*c4] = l0;   BsW[si][r*20+9+2*c4] = l1;
        }
        __syncthreads();
    }

    // rmsnorm: per-row sum of squares via shfl + cross-warp smem
    #pragma unroll
    for (int mt = 0; mt < 2; mt++) {
        int r = wm * 32 + mt * 16 + g;
        float p0 = 0.f, p1 = 0.f;
        #pragma unroll
        for (int nt = 0; nt < 4; nt++) {
            p0 += c[mt][nt][0]*c[mt][nt][0] + c[mt][nt][1]*c[mt][nt][1];
            p1 += c[mt][nt][2]*c[mt][nt][2] + c[mt][nt][3]*c[mt][nt][3];
        }
        p0 += __shfl_xor_sync(0xffffffffu, p0, 1);
        p0 += __shfl_xor_sync(0xffffffffu, p0, 2);
        p1 += __shfl_xor_sync(0xffffffffu, p1, 1);
        p1 += __shfl_xor_sync(0xffffffffu, p1, 2);
        if (tig == 0) { ssm[wn][r] = p0; ssm[wn][r + 8] = p1; }
    }
    __syncthreads();
    #pragma unroll
    for (int mt = 0; mt < 2; mt++) {
        int r = wm * 32 + mt * 16 + g;
        float s0 = rsqrtf((ssm[0][r]     + ssm[1][r])     * (1.0f/64.0f) + 1e-6f);
        float s1 = rsqrtf((ssm[0][r + 8] + ssm[1][r + 8]) * (1.0f/64.0f) + 1e-6f);
        #pragma unroll
        for (int nt = 0; nt < 4; nt++) {
            int col = wn * 32 + nt * 8 + 2 * tig;
            int kc = col >> 5, p = col & 31;
            uint32_t hh, ll;
            size_t b0 = ((size_t)(m0 + r) * 2 + kc) * 64 + p;
            split2(c[mt][nt][0]*s0*nws[col], c[mt][nt][1]*s0*nws[col+1], hh, ll);
            *(uint32_t*)&C[b0] = hh;  *(uint32_t*)&C[b0 + 32] = ll;
            size_t b1 = ((size_t)(m0 + r + 8) * 2 + kc) * 64 + p;
            split2(c[mt][nt][2]*s1*nws[col], c[mt][nt][3]*s1*nws[col+1], hh, ll);
            *(uint32_t*)&C[b1] = hh;  *(uint32_t*)&C[b1 + 32] = ll;
        }
    }
}

// ======================================================================
// attn_tc: flash attention, bf16x3 mma.sync, ldmatrix fragments.
// 64-key sub-chunks double-buffered. Q pre-scaled by 0.125*log2e -> ex2.
// Output written split-interleaved into ys [tok][32][64].
// ======================================================================
#define ATTN_SMEM 98304

__global__ __launch_bounds__(256, 2) void attn_tc(
    const __nv_bfloat16* __restrict__ qh_g, const __nv_bfloat16* __restrict__ ql_g,
    const __nv_bfloat16* __restrict__ kh_g, const __nv_bfloat16* __restrict__ kl_g,
    const __nv_bfloat16* __restrict__ vh_g, const __nv_bfloat16* __restrict__ vl_g,
    __nv_bfloat16* __restrict__ ys)
{
    extern __shared__ char smraw[];
    const uint32_t base = smem_u32(smraw);
    const uint32_t Qh = base, Ql = base + 16384;
    const uint32_t kvb = base + 32768;

    const int tid = threadIdx.x;
    const int w = tid >> 5, lane = tid & 31;
    const int g = lane >> 2, tig = lane & 3;
    const int l8 = lane & 7, sub = lane >> 3;
    const int r0 = w * 16;
    const int bh = blockIdx.y;
    const int q0 = blockIdx.x * 128;
    const size_t hb = (size_t)bh * SEQ;

    #pragma unroll
    for (int p = 0; p < 4; p++) {
        int idx = tid + p * 256, row = idx >> 3, ch = idx & 7;
        size_t go = (hb + q0 + row) * 64 + ch * 8;
        CPA16(lda(Qh, row, ch), qh_g + go);
        CPA16(lda(Ql, row, ch), ql_g + go);
    }
    #pragma unroll
    for (int p = 0; p < 2; p++) {
        int idx = tid + p * 256, row = idx >> 3, ch = idx & 7;
        size_t go = (hb + row) * 64 + ch * 8;
        uint32_t so = (uint32_t)row * 128 + (((uint32_t)ch ^ ((uint32_t)row & 7u)) << 4);
        CPA16(kvb + so,         kh_g + go);  CPA16(kvb + 8192 + so,  kl_g + go);
        CPA16(kvb + 16384 + so, vh_g + go);  CPA16(kvb + 24576 + so, vl_g + go);
    }
    CPCOMMIT();
    #pragma unroll
    for (int p = 0; p < 2; p++) {
        int idx = tid + p * 256, row = idx >> 3, ch = idx & 7;
        size_t go = (hb + 64 + row) * 64 + ch * 8;
        uint32_t so = (uint32_t)row * 128 + (((uint32_t)ch ^ ((uint32_t)row & 7u)) << 4);
        CPA16(kvb + 32768 + so, kh_g + go);  CPA16(kvb + 40960 + so, kl_g + go);
        CPA16(kvb + 49152 + so, vh_g + go);  CPA16(kvb + 57344 + so, vl_g + go);
    }
    CPCOMMIT();

    float o[8][4] = {};
    float lsum0 = 0.f, lsum1 = 0.f;

    for (int sc = 0; sc < 32; sc++) {
        const int bi = sc & 1;
        const uint32_t Kh = kvb + bi * 32768, Kl = Kh + 8192;
        const uint32_t Vh = Kh + 16384,       Vl = Kh + 24576;
        CPWAIT(1);
        __syncthreads();

        float s[8][4] = {};
        #pragma unroll
        for (int ks = 0; ks < 4; ks++) {
            int arow = r0 + l8 + ((sub & 1) << 3);
            int ach  = 2 * ks + (sub >> 1);
            uint32_t ah[4], al[4];
            LDSM4(ah, lda(Qh, arow, ach));
            LDSM4(al, lda(Ql, arow, ach));
            #pragma unroll
            for (int ntp = 0; ntp < 4; ntp++) {
                int krow = ntp * 16 + ((sub >> 1) << 3) + l8;
                int kch  = 2 * ks + (sub & 1);
                uint32_t bhf[4], blf[4];
                LDSM4(bhf, lda(Kh, krow, kch));
                LDSM4(blf, lda(Kl, krow, kch));
                MMAX3(s[2 * ntp],     ah, al, bhf[0], bhf[1], blf[0], blf[1]);
                MMAX3(s[2 * ntp + 1], ah, al, bhf[2], bhf[3], blf[2], blf[3]);
            }
        }

        #pragma unroll
        for (int ks = 0; ks < 4; ks++) {
            float e0 = ex2f(s[2*ks][0]),   e1 = ex2f(s[2*ks][1]);
            float e2 = ex2f(s[2*ks][2]),   e3 = ex2f(s[2*ks][3]);
            float e4 = ex2f(s[2*ks+1][0]), e5 = ex2f(s[2*ks+1][1]);
            float e6 = ex2f(s[2*ks+1][2]), e7 = ex2f(s[2*ks+1][3]);
            lsum0 += e0 + e1 + e4 + e5;
            lsum1 += e2 + e3 + e6 + e7;
            uint32_t ph[4], pl[4];
            split2(e0, e1, ph[0], pl[0]);
            split2(e2, e3, ph[1], pl[1]);
            split2(e4, e5, ph[2], pl[2]);
            split2(e6, e7, ph[3], pl[3]);
            #pragma unroll
            for (int ntp = 0; ntp < 4; ntp++) {
                int vrow = ks * 16 + ((sub & 1) << 3) + l8;
                int vch  = 2 * ntp + (sub >> 1);
                uint32_t vhf[4], vlf[4];
                LDSM4T(vhf, lda(Vh, vrow, vch));
                LDSM4T(vlf, lda(Vl, vrow, vch));
                MMAX3(o[2 * ntp],     ph, pl, vhf[0], vhf[1], vlf[0], vlf[1]);
                MMAX3(o[2 * ntp + 1], ph, pl, vhf[2], vhf[3], vlf[2], vlf[3]);
            }
        }

        __syncthreads();
        if (sc + 2 < 32) {
            #pragma unroll
            for (int p = 0; p < 2; p++) {
                int idx = tid + p * 256, row = idx >> 3, ch = idx & 7;
                size_t go = (hb + (size_t)(sc + 2) * 64 + row) * 64 + ch * 8;
                uint32_t so = (uint32_t)row * 128 + (((uint32_t)ch ^ ((uint32_t)row & 7u)) << 4);
                CPA16(Kh + so, kh_g + go);  CPA16(Kl + so, kl_g + go);
                CPA16(Vh + so, vh_g + go);  CPA16(Vl + so, vl_g + go);
            }
        }
        CPCOMMIT();
    }

    lsum0 += __shfl_xor_sync(0xffffffffu, lsum0, 1);
    lsum0 += __shfl_xor_sync(0xffffffffu, lsum0, 2);
    lsum1 += __shfl_xor_sync(0xffffffffu, lsum1, 1);
    lsum1 += __shfl_xor_sync(0xffffffffu, lsum1, 2);
    float inv0 = 1.0f / lsum0, inv1 = 1.0f / lsum1;

    const int b = bh >> 4, h = bh & 15;
    const size_t tok0 = (size_t)b * SEQ + q0 + r0 + g;
    #pragma unroll
    for (int nt = 0; nt < 8; nt++) {
        int col = nt * 8 + 2 * tig;
        int kc = 2 * h + (col >> 5), p = col & 31;
        uint32_t hh, ll;
        size_t b0 = (tok0 * 32 + kc) * 64 + p;
        split2(o[nt][0] * inv0, o[nt][1] * inv0, hh, ll);
        *(uint32_t*)&ys[b0] = hh;  *(uint32_t*)&ys[b0 + 32] = ll;
        size_t b1 = ((tok0 + 8) * 32 + kc) * 64 + p;
        split2(o[nt][2] * inv1, o[nt][3] * inv1, hh, ll);
        *(uint32_t*)&ys[b1] = hh;  *(uint32_t*)&ys[b1 + 32] = ll;
    }
}

// ---------------------------------------------------------------------------
extern "C" void kernel_launch(void* const* d_in, const int* in_sizes, int n_in,
                              void* d_out, int out_size)
{
    const float* x      = (const float*)d_in[0];
    const float* w_kv_a = (const float*)d_in[1];
    const float* w_kv_b = (const float*)d_in[2];
    const float* w_q_a  = (const float*)d_in[3];
    const float* w_q_b  = (const float*)d_in[4];
    const float* w_proj = (const float*)d_in[5];
    const float* kv_nw  = (const float*)d_in[6];
    const float* q_nw   = (const float*)d_in[7];
    float* out = (float*)d_out;

    __nv_bfloat16 *qlat_s, *kvlat_s, *wq_s, *wkv_s, *wproj_s, *ysv;
    __nv_bfloat16 *qh, *ql, *kh, *kl, *vh, *vl;
    cudaGetSymbolAddress((void**)&qlat_s,  g_qlat_s);
    cudaGetSymbolAddress((void**)&kvlat_s, g_kvlat_s);
    cudaGetSymbolAddress((void**)&wq_s,    g_wq_s);
    cudaGetSymbolAddress((void**)&wkv_s,   g_wkv_s);
    cudaGetSymbolAddress((void**)&wproj_s, g_wproj_s);
    cudaGetSymbolAddress((void**)&ysv,     g_ys);
    cudaGetSymbolAddress((void**)&qh, g_qh);  cudaGetSymbolAddress((void**)&ql, g_ql);
    cudaGetSymbolAddress((void**)&kh, g_kh);  cudaGetSymbolAddress((void**)&kl, g_kl);
    cudaGetSymbolAddress((void**)&vh, g_vh);  cudaGetSymbolAddress((void**)&vl, g_vl);

    cudaFuncSetAttribute(attn_tc,    cudaFuncAttributeMaxDynamicSharedMemorySize, ATTN_SMEM);
    cudaFuncSetAttribute(gemm_bf<0>, cudaFuncAttributeMaxDynamicSharedMemorySize, GEMMBF_SMEM);
    cudaFuncSetAttribute(gemm_bf<1>, cudaFuncAttributeMaxDynamicSharedMemorySize, GEMMBF_SMEM);
    cudaFuncSetAttribute(gemm_bf<2>, cudaFuncAttributeMaxDynamicSharedMemorySize, GEMMBF_SMEM);

    // pre-split weights into interleaved bf16 layout
    wsplit<<<64,   256>>>(w_q_b,  wq_s,    64,   16384);
    wsplit<<<128,  256>>>(w_kv_b, wkv_s,   64,   32768);
    wsplit<<<1024, 256>>>(w_proj, wproj_s, 1024, 262144);

    // latent projections + fused rmsnorm -> split-interleaved latents
    gemm_lat2<<<dim3(64, 2), 256>>>(x, w_q_a, w_kv_a, q_nw, kv_nw, qlat_s, kvlat_s);

    // up-projections -> per-head split tensors
    gemm_bf<0><<<dim3(8, 64),  256, GEMMBF_SMEM>>>(qlat_s,  wq_s,  nullptr, qh, ql, nullptr, nullptr, 64, 1024);
    gemm_bf<1><<<dim3(16, 64), 256, GEMMBF_SMEM>>>(kvlat_s, wkv_s, nullptr, kh, kl, vh, vl, 64, 2048);

    // attention -> split-interleaved y
    attn_tc<<<dim3(16, 64), 256, ATTN_SMEM>>>(qh, ql, kh, kl, vh, vl, ysv);

    // output projection (fp32 out)
    gemm_bf<2><<<dim3(8, 64), 256, GEMMBF_SMEM>>>(ysv, wproj_s, out, nullptr, nullptr, nullptr, nullptr, 1024, 1024);
}

// round 9
// speedup vs baseline: 1.0186x; 1.0186x over previous
#include <cuda_runtime.h>
#include <cuda_bf16.h>
#include <cstdint>

#define SEQ   2048
#define NTOK  8192

// ---------------- scratch (device globals: no runtime allocation) ----------
// interleaved split layout: [row][k/32][32 hi bf16 | 32 lo bf16]  (128B rows)
__device__ __nv_bfloat16 g_qlat_s [(size_t)NTOK * 128];
__device__ __nv_bfloat16 g_kvlat_s[(size_t)NTOK * 128];
__device__ __nv_bfloat16 g_wq_s   [(size_t)1024 * 128];
__device__ __nv_bfloat16 g_wkv_s  [(size_t)2048 * 128];
__device__ __nv_bfloat16 g_wproj_s[(size_t)1024 * 2048];
__device__ __nv_bfloat16 g_ys     [(size_t)NTOK * 2048];
// per-head split tensors for attention [(b*16+h)][seq][64]
__device__ __nv_bfloat16 g_qh[(size_t)NTOK * 1024];
__device__ __nv_bfloat16 g_ql[(size_t)NTOK * 1024];
__device__ __nv_bfloat16 g_kh[(size_t)NTOK * 1024];
__device__ __nv_bfloat16 g_kl[(size_t)NTOK * 1024];
__device__ __nv_bfloat16 g_vh[(size_t)NTOK * 1024];
__device__ __nv_bfloat16 g_vl[(size_t)NTOK * 1024];

#define QSCALE (0.125f * 1.4426950408889634f)   // fold softmax scale * log2e

// ---------------- helpers ---------------------------------------------------
static __device__ __forceinline__ uint32_t smem_u32(const void* p) {
    uint32_t a;
    asm("{ .reg .u64 t; cvta.to.shared.u64 t, %1; cvt.u32.u64 %0, t; }"
        : "=r"(a) : "l"(p));
    return a;
}
static __device__ __forceinline__ uint32_t bfpack(float lo, float hi) {
    uint32_t r;
    asm("cvt.rn.bf16x2.f32 %0, %1, %2;" : "=r"(r) : "f"(hi), "f"(lo));
    return r;
}
static __device__ __forceinline__ void split2(float x, float y,
                                              uint32_t& h, uint32_t& l) {
    h = bfpack(x, y);
    __nv_bfloat162 hb = *reinterpret_cast<__nv_bfloat162*>(&h);
    l = bfpack(x - __bfloat162float(hb.x), y - __bfloat162float(hb.y));
}
static __device__ __forceinline__ float ex2f(float x) {
    float y; asm("ex2.approx.f32 %0, %1;" : "=f"(y) : "f"(x)); return y;
}
// swizzled smem addr: 128B rows of 8 x 16B chunks, chunk ^= row&7
static __device__ __forceinline__ uint32_t lda(uint32_t base, int row, int ch) {
    return base + row * 128 + (((uint32_t)ch ^ ((uint32_t)row & 7u)) << 4);
}

#define MMAB(c, a0, a1, a2, a3, b0, b1)                                        \
    asm volatile("mma.sync.aligned.m16n8k16.row.col.f32.bf16.bf16.f32 "        \
        "{%0,%1,%2,%3},{%4,%5,%6,%7},{%8,%9},{%0,%1,%2,%3};"                   \
        : "+f"((c)[0]), "+f"((c)[1]), "+f"((c)[2]), "+f"((c)[3])               \
        : "r"(a0), "r"(a1), "r"(a2), "r"(a3), "r"(b0), "r"(b1))

#define MMAX3(c, ah, al, bh0, bh1, bl0, bl1) do {                              \
    MMAB(c, (ah)[0], (ah)[1], (ah)[2], (ah)[3], bh0, bh1);                     \
    MMAB(c, (ah)[0], (ah)[1], (ah)[2], (ah)[3], bl0, bl1);                     \
    MMAB(c, (al)[0], (al)[1], (al)[2], (al)[3], bh0, bh1);                     \
} while (0)

#define LDSM4(r, addr)                                                         \
    asm volatile("ldmatrix.sync.aligned.m8n8.x4.shared.b16 {%0,%1,%2,%3}, [%4];" \
        : "=r"((r)[0]), "=r"((r)[1]), "=r"((r)[2]), "=r"((r)[3]) : "r"(addr))
#define LDSM4T(r, addr)                                                        \
    asm volatile("ldmatrix.sync.aligned.m8n8.x4.trans.shared.b16 {%0,%1,%2,%3}, [%4];" \
        : "=r"((r)[0]), "=r"((r)[1]), "=r"((r)[2]), "=r"((r)[3]) : "r"(addr))
#define CPA16(dst, src)                                                        \
    asm volatile("cp.async.cg.shared.global [%0], [%1], 16;" :: "r"(dst), "l"(src))
#define CPCOMMIT() asm volatile("cp.async.commit_group;" ::: "memory")
#define CPWAIT(n)  asm volatile("cp.async.wait_group %0;" :: "n"(n) : "memory")

// ======================================================================
// wsplit: W[n][K] fp32 -> O[n][K/32][32h|32l] bf16
// ======================================================================
__global__ __launch_bounds__(256) void wsplit(
    const float* __restrict__ W, __nv_bfloat16* __restrict__ O,
    int K, int nf4)
{
    int idx = blockIdx.x * 256 + threadIdx.x;
    if (idx >= nf4) return;
    int K4 = K >> 2;
    int n = idx / K4, k4 = idx - n * K4;
    float4 v = *(const float4*)&W[(size_t)n * K + k4 * 4];
    int k = k4 * 4, kc = k >> 5, p = k & 31;
    size_t o = ((size_t)n * (K >> 5) + kc) * 64 + p;
    uint32_t h0, l0, h1, l1;
    split2(v.x, v.y, h0, l0); split2(v.z, v.w, h1, l1);
    *(uint32_t*)&O[o]      = h0;  *(uint32_t*)&O[o + 2]  = h1;
    *(uint32_t*)&O[o + 32] = l0;  *(uint32_t*)&O[o + 34] = l1;
}

// ======================================================================
// gemm_bf<MODE>: C = A[M,K] @ B[N,K]^T, both pre-split interleaved bf16.
// BK=32, cp.async 3-STAGE ring, ldmatrix, x3 MMA. 2 CTAs/SM.
// MODE 0: q-up (scale QSCALE -> qh/ql per-head)
// MODE 1: kv-up (k->H,L / v->H2,L2)      MODE 2: fp32 out (Cf)
// ======================================================================
#define GEMMBF_SMEM 98304

template<int MODE>
__global__ __launch_bounds__(256, 2) void gemm_bf(
    const __nv_bfloat16* __restrict__ A, const __nv_bfloat16* __restrict__ B,
    float* __restrict__ Cf,
    __nv_bfloat16* __restrict__ H,  __nv_bfloat16* __restrict__ L,
    __nv_bfloat16* __restrict__ H2, __nv_bfloat16* __restrict__ L2,
    int K, int N)
{
    extern __shared__ char smraw[];
    const uint32_t base = smem_u32(smraw);
    // stage s: A at base + s*32768, B at +16384

    const int tid = threadIdx.x;
    const int w = tid >> 5, lane = tid & 31;
    const int g = lane >> 2, tig = lane & 3;
    const int l8 = lane & 7, sub = lane >> 3;
    const int wm = w & 1, wn = w >> 1;
    const int m0 = blockIdx.y * 128, n0 = blockIdx.x * 128;
    const int KC = K >> 5, CH = KC;

    float c[4][4][4] = {};

    // stage chunks 0,1,2 (empty commits keep group counting uniform)
    #pragma unroll
    for (int s = 0; s < 3; s++) {
        if (s < CH) {
            #pragma unroll
            for (int p = 0; p < 4; p++) {
                int idx = tid + p * 256, row = idx >> 3, ch = idx & 7;
                CPA16(lda(base + s * 32768, row, ch),
                      A + ((size_t)(m0 + row) * KC + s) * 64 + ch * 8);
                CPA16(lda(base + s * 32768 + 16384, row, ch),
                      B + ((size_t)(n0 + row) * KC + s) * 64 + ch * 8);
            }
        }
        CPCOMMIT();
    }

    int rb = 0;   // ring buffer index = cc % 3
    for (int cc = 0; cc < CH; cc++) {
        const uint32_t Ab = base + rb * 32768;
        const uint32_t Bb = Ab + 16384;
        CPWAIT(2);
        __syncthreads();

        #pragma unroll
        for (int ks = 0; ks < 2; ks++) {
            uint32_t ah[4][4], al[4][4];
            #pragma unroll
            for (int mt = 0; mt < 4; mt++) {
                int arow = wm * 64 + mt * 16 + l8 + ((sub & 1) << 3);
                int hch  = 2 * ks + (sub >> 1);
                LDSM4(ah[mt], lda(Ab, arow, hch));
                LDSM4(al[mt], lda(Ab, arow, hch + 4));
            }
            #pragma unroll
            for (int np = 0; np < 2; np++) {
                int brow = wn * 32 + np * 16 + ((sub >> 1) << 3) + l8;
                int bch  = 2 * ks + (sub & 1);
                uint32_t bhf[4], blf[4];
                LDSM4(bhf, lda(Bb, brow, bch));
                LDSM4(blf, lda(Bb, brow, bch + 4));
                #pragma unroll
                for (int mt = 0; mt < 4; mt++) {
                    MMAX3(c[mt][2*np],   ah[mt], al[mt], bhf[0], bhf[1], blf[0], blf[1]);
                    MMAX3(c[mt][2*np+1], ah[mt], al[mt], bhf[2], bhf[3], blf[2], blf[3]);
                }
            }
        }

        __syncthreads();
        if (cc + 3 < CH) {
            #pragma unroll
            for (int p = 0; p < 4; p++) {
                int idx = tid + p * 256, row = idx >> 3, ch = idx & 7;
                CPA16(lda(Ab, row, ch),
                      A + ((size_t)(m0 + row) * KC + cc + 3) * 64 + ch * 8);
                CPA16(lda(Bb, row, ch),
                      B + ((size_t)(n0 + row) * KC + cc + 3) * 64 + ch * 8);
            }
        }
        CPCOMMIT();
        if (++rb == 3) rb = 0;
    }

    if (MODE == 2) {
        #pragma unroll
        for (int mt = 0; mt < 4; mt++)
            #pragma unroll
            for (int nt = 0; nt < 4; nt++) {
                int r0 = m0 + wm * 64 + mt * 16 + g;
                int col = n0 + wn * 32 + nt * 8 + 2 * tig;
                *(float2*)&Cf[(size_t)r0 * N + col]       = make_float2(c[mt][nt][0], c[mt][nt][1]);
                *(float2*)&Cf[(size_t)(r0 + 8) * N + col] = make_float2(c[mt][nt][2], c[mt][nt][3]);
            }
    } else {
        const float sc = (MODE == 0) ? QSCALE : 1.0f;
        #pragma unroll
        for (int mt = 0; mt < 4; mt++)
            #pragma unroll
            for (int nt = 0; nt < 4; nt++) {
                int tok = m0 + wm * 64 + mt * 16 + g;
                int col = n0 + wn * 32 + nt * 8 + 2 * tig;
                int b = tok >> 11, tn = tok & 2047;
                int h, d;
                __nv_bfloat16 *DH, *DL;
                if (MODE == 0) {
                    h = col >> 6; d = col & 63; DH = H; DL = L;
                } else {
                    h = col >> 7; int rr = col & 127; d = rr & 63;
                    if (rr < 64) { DH = H; DL = L; } else { DH = H2; DL = L2; }
                }
                size_t a0 = (((size_t)b * 16 + h) * SEQ + tn) * 64 + d;
                size_t a1 = a0 + 8 * 64;
                uint32_t hp, lp;
                split2(c[mt][nt][0] * sc, c[mt][nt][1] * sc, hp, lp);
                *(uint32_t*)&DH[a0] = hp;  *(uint32_t*)&DL[a0] = lp;
                split2(c[mt][nt][2] * sc, c[mt][nt][3] * sc, hp, lp);
                *(uint32_t*)&DH[a1] = hp;  *(uint32_t*)&DL[a1] = lp;
            }
    }
}

// ======================================================================
// gemm_latf: FUSED latent projections. One pass over x computes both
// q-latent and kv-latent. M-tile 64 tokens, N-tile 128 = [Wq 64|Wkv 64].
// Warp tile 16(M) x 64(N); wn selects q vs kv half, so rmsnorm is a pure
// intra-warp shfl reduce. Distance-1 LDG/STS pipelining (R7 pattern).
// ======================================================================
__global__ __launch_bounds__(256, 2) void gemm_latf(
    const float* __restrict__ A,
    const float* __restrict__ Wq, const float* __restrict__ Wkv,
    const float* __restrict__ nwq, const float* __restrict__ nwkv,
    __nv_bfloat16* __restrict__ Cq, __nv_bfloat16* __restrict__ Ckv)
{
    __shared__ uint32_t AsW[2][64 * 20];
    __shared__ uint32_t BsW[2][128 * 20];
    __shared__ float nws[128];
    const int tid = threadIdx.x;
    const int w = tid >> 5, lane = tid & 31;
    const int g = lane >> 2, tig = lane & 3;
    const int wm = w >> 1, wn = w & 1;     // wm 0..3 (16-row slice), wn: q/kv
    const int m0 = blockIdx.x * 64;

    if (tid < 64)       nws[tid] = nwq[tid];
    else if (tid < 128) nws[tid] = nwkv[tid - 64];

    float c[8][4] = {};

    // stage chunk 0 into buf 0
    {
        int r = tid >> 2, c4 = tid & 3;    // A: 64 rows x 4 f4
        float4 va = *(const float4*)&A[(size_t)(m0 + r) * 1024 + c4 * 4];
        uint32_t h0, h1, l0, l1;
        split2(va.x, va.y, h0, l0); split2(va.z, va.w, h1, l1);
        AsW[0][r*20+2*c4] = h0;     AsW[0][r*20+2*c4+1] = h1;
        AsW[0][r*20+8+2*c4] = l0;   AsW[0][r*20+9+2*c4] = l1;
    }
    #pragma unroll
    for (int p = 0; p < 2; p++) {          // B: 128 rows (Wq|Wkv)
        int f = tid + p * 256, r = f >> 2, c4 = f & 3;
        const float* src = (r < 64) ? &Wq[(size_t)r * 1024]
                                    : &Wkv[(size_t)(r - 64) * 1024];
        float4 vb = *(const float4*)&src[c4 * 4];
        uint32_t h0, h1, l0, l1;
        split2(vb.x, vb.y, h0, l0); split2(vb.z, vb.w, h1, l1);
        BsW[0][r*20+2*c4] = h0;     BsW[0][r*20+2*c4+1] = h1;
        BsW[0][r*20+8+2*c4] = l0;   BsW[0][r*20+9+2*c4] = l1;
    }
    __syncthreads();

    for (int cc = 0; cc < 64; cc++) {
        const int bi = cc & 1;
        const uint32_t* As = AsW[bi];
        const uint32_t* Bs = BsW[bi];
        uint32_t ah[4], al[4];
        {
            int r = wm * 16 + g;
            ah[0] = As[r*20+tig];      ah[1] = As[(r+8)*20+tig];
            ah[2] = As[r*20+4+tig];    ah[3] = As[(r+8)*20+4+tig];
            al[0] = As[r*20+8+tig];    al[1] = As[(r+8)*20+8+tig];
            al[2] = As[r*20+12+tig];   al[3] = As[(r+8)*20+12+tig];
        }
        // distance-1 global prefetch (consumed after MMAs)
        float4 pav, pb[2];
        const bool pf = (cc + 1 < 64);
        if (pf) {
            int r = tid >> 2, c4 = tid & 3;
            pav = *(const float4*)&A[(size_t)(m0 + r) * 1024 + (cc+1)*16 + c4*4];
            #pragma unroll
            for (int p = 0; p < 2; p++) {
                int f = tid + p * 256, rr = f >> 2, cb = f & 3;
                const float* src = (rr < 64) ? &Wq[(size_t)rr * 1024]
                                             : &Wkv[(size_t)(rr - 64) * 1024];
                pb[p] = *(const float4*)&src[(cc+1)*16 + cb*4];
            }
        }
        #pragma unroll
        for (int nt = 0; nt < 8; nt++) {
            int rn = wn * 64 + nt * 8 + g;
            uint32_t bh0 = Bs[rn*20+tig],   bh1 = Bs[rn*20+4+tig];
            uint32_t bl0 = Bs[rn*20+8+tig], bl1 = Bs[rn*20+12+tig];
            MMAX3(c[nt], ah, al, bh0, bh1, bl0, bl1);
        }
        if (pf) {
            const int si = bi ^ 1;
            int r = tid >> 2, c4 = tid & 3;
            uint32_t h0, h1, l0, l1;
            split2(pav.x, pav.y, h0, l0); split2(pav.z, pav.w, h1, l1);
            AsW[si][r*20+2*c4] = h0;     AsW[si][r*20+2*c4+1] = h1;
            AsW[si][r*20+8+2*c4] = l0;   AsW[si][r*20+9+2*c4] = l1;
            #pragma unroll
            for (int p = 0; p < 2; p++) {
                int f = tid + p * 256, rr = f >> 2, cb = f & 3;
                split2(pb[p].x, pb[p].y, h0, l0); split2(pb[p].z, pb[p].w, h1, l1);
                BsW[si][rr*20+2*cb] = h0;     BsW[si][rr*20+2*cb+1] = h1;
                BsW[si][rr*20+8+2*cb] = l0;   BsW[si][rr*20+9+2*cb] = l1;
            }
        }
        __syncthreads();
    }

    // rmsnorm: whole 64-wide row lives in this warp -> shfl over tig
    float p0 = 0.f, p1 = 0.f;
    #pragma unroll
    for (int nt = 0; nt < 8; nt++) {
        p0 += c[nt][0]*c[nt][0] + c[nt][1]*c[nt][1];
        p1 += c[nt][2]*c[nt][2] + c[nt][3]*c[nt][3];
    }
    p0 += __shfl_xor_sync(0xffffffffu, p0, 1);
    p0 += __shfl_xor_sync(0xffffffffu, p0, 2);
    p1 += __shfl_xor_sync(0xffffffffu, p1, 1);
    p1 += __shfl_xor_sync(0xffffffffu, p1, 2);
    float s0 = rsqrtf(p0 * (1.0f/64.0f) + 1e-6f);
    float s1 = rsqrtf(p1 * (1.0f/64.0f) + 1e-6f);

    __nv_bfloat16* C = wn ? Ckv : Cq;
    const int r = m0 + wm * 16 + g;
    #pragma unroll
    for (int nt = 0; nt < 8; nt++) {
        int col = nt * 8 + 2 * tig;
        float w0 = nws[wn * 64 + col], w1 = nws[wn * 64 + col + 1];
        int kc = col >> 5, p = col & 31;
        uint32_t hh, ll;
        size_t b0 = ((size_t)r * 2 + kc) * 64 + p;
        split2(c[nt][0]*s0*w0, c[nt][1]*s0*w1, hh, ll);
        *(uint32_t*)&C[b0] = hh;  *(uint32_t*)&C[b0 + 32] = ll;
        size_t b1 = ((size_t)(r + 8) * 2 + kc) * 64 + p;
        split2(c[nt][2]*s1*w0, c[nt][3]*s1*w1, hh, ll);
        *(uint32_t*)&C[b1] = hh;  *(uint32_t*)&C[b1 + 32] = ll;
    }
}

// ======================================================================
// attn_tc: flash attention, bf16x3 mma.sync, ldmatrix fragments.
// 64-key sub-chunks double-buffered. Q pre-scaled by 0.125*log2e -> ex2.
// Output written split-interleaved into ys [tok][32][64].
// ======================================================================
#define ATTN_SMEM 98304

__global__ __launch_bounds__(256, 2) void attn_tc(
    const __nv_bfloat16* __restrict__ qh_g, const __nv_bfloat16* __restrict__ ql_g,
    const __nv_bfloat16* __restrict__ kh_g, const __nv_bfloat16* __restrict__ kl_g,
    const __nv_bfloat16* __restrict__ vh_g, const __nv_bfloat16* __restrict__ vl_g,
    __nv_bfloat16* __restrict__ ys)
{
    extern __shared__ char smraw[];
    const uint32_t base = smem_u32(smraw);
    const uint32_t Qh = base, Ql = base + 16384;
    const uint32_t kvb = base + 32768;

    const int tid = threadIdx.x;
    const int w = tid >> 5, lane = tid & 31;
    const int g = lane >> 2, tig = lane & 3;
    const int l8 = lane & 7, sub = lane >> 3;
    const int r0 = w * 16;
    const int bh = blockIdx.y;
    const int q0 = blockIdx.x * 128;
    const size_t hb = (size_t)bh * SEQ;

    #pragma unroll
    for (int p = 0; p < 4; p++) {
        int idx = tid + p * 256, row = idx >> 3, ch = idx & 7;
        size_t go = (hb + q0 + row) * 64 + ch * 8;
        CPA16(lda(Qh, row, ch), qh_g + go);
        CPA16(lda(Ql, row, ch), ql_g + go);
    }
    #pragma unroll
    for (int p = 0; p < 2; p++) {
        int idx = tid + p * 256, row = idx >> 3, ch = idx & 7;
        size_t go = (hb + row) * 64 + ch * 8;
        uint32_t so = (uint32_t)row * 128 + (((uint32_t)ch ^ ((uint32_t)row & 7u)) << 4);
        CPA16(kvb + so,         kh_g + go);  CPA16(kvb + 8192 + so,  kl_g + go);
        CPA16(kvb + 16384 + so, vh_g + go);  CPA16(kvb + 24576 + so, vl_g + go);
    }
    CPCOMMIT();
    #pragma unroll
    for (int p = 0; p < 2; p++) {
        int idx = tid + p * 256, row = idx >> 3, ch = idx & 7;
        size_t go = (hb + 64 + row) * 64 + ch * 8;
        uint32_t so = (uint32_t)row * 128 + (((uint32_t)ch ^ ((uint32_t)row & 7u)) << 4);
        CPA16(kvb + 32768 + so, kh_g + go);  CPA16(kvb + 40960 + so, kl_g + go);
        CPA16(kvb + 49152 + so, vh_g + go);  CPA16(kvb + 57344 + so, vl_g + go);
    }
    CPCOMMIT();

    float o[8][4] = {};
    float lsum0 = 0.f, lsum1 = 0.f;

    for (int sc = 0; sc < 32; sc++) {
        const int bi = sc & 1;
        const uint32_t Kh = kvb + bi * 32768, Kl = Kh + 8192;
        const uint32_t Vh = Kh + 16384,       Vl = Kh + 24576;
        CPWAIT(1);
        __syncthreads();

        float s[8][4] = {};
        #pragma unroll
        for (int ks = 0; ks < 4; ks++) {
            int arow = r0 + l8 + ((sub & 1) << 3);
            int ach  = 2 * ks + (sub >> 1);
            uint32_t ah[4], al[4];
            LDSM4(ah, lda(Qh, arow, ach));
            LDSM4(al, lda(Ql, arow, ach));
            #pragma unroll
            for (int ntp = 0; ntp < 4; ntp++) {
                int krow = ntp * 16 + ((sub >> 1) << 3) + l8;
                int kch  = 2 * ks + (sub & 1);
                uint32_t bhf[4], blf[4];
                LDSM4(bhf, lda(Kh, krow, kch));
                LDSM4(blf, lda(Kl, krow, kch));
                MMAX3(s[2 * ntp],     ah, al, bhf[0], bhf[1], blf[0], blf[1]);
                MMAX3(s[2 * ntp + 1], ah, al, bhf[2], bhf[3], blf[2], blf[3]);
            }
        }

        #pragma unroll
        for (int ks = 0; ks < 4; ks++) {
            float e0 = ex2f(s[2*ks][0]),   e1 = ex2f(s[2*ks][1]);
            float e2 = ex2f(s[2*ks][2]),   e3 = ex2f(s[2*ks][3]);
            float e4 = ex2f(s[2*ks+1][0]), e5 = ex2f(s[2*ks+1][1]);
            float e6 = ex2f(s[2*ks+1][2]), e7 = ex2f(s[2*ks+1][3]);
            lsum0 += e0 + e1 + e4 + e5;
            lsum1 += e2 + e3 + e6 + e7;
            uint32_t ph[4], pl[4];
            split2(e0, e1, ph[0], pl[0]);
            split2(e2, e3, ph[1], pl[1]);
            split2(e4, e5, ph[2], pl[2]);
            split2(e6, e7, ph[3], pl[3]);
            #pragma unroll
            for (int ntp = 0; ntp < 4; ntp++) {
                int vrow = ks * 16 + ((sub & 1) << 3) + l8;
                int vch  = 2 * ntp + (sub >> 1);
                uint32_t vhf[4], vlf[4];
                LDSM4T(vhf, lda(Vh, vrow, vch));
                LDSM4T(vlf, lda(Vl, vrow, vch));
                MMAX3(o[2 * ntp],     ph, pl, vhf[0], vhf[1], vlf[0], vlf[1]);
                MMAX3(o[2 * ntp + 1], ph, pl, vhf[2], vhf[3], vlf[2], vlf[3]);
            }
        }

        __syncthreads();
        if (sc + 2 < 32) {
            #pragma unroll
            for (int p = 0; p < 2; p++) {
                int idx = tid + p * 256, row = idx >> 3, ch = idx & 7;
                size_t go = (hb + (size_t)(sc + 2) * 64 + row) * 64 + ch * 8;
                uint32_t so = (uint32_t)row * 128 + (((uint32_t)ch ^ ((uint32_t)row & 7u)) << 4);
                CPA16(Kh + so, kh_g + go);  CPA16(Kl + so, kl_g + go);
                CPA16(Vh + so, vh_g + go);  CPA16(Vl + so, vl_g + go);
            }
        }
        CPCOMMIT();
    }

    lsum0 += __shfl_xor_sync(0xffffffffu, lsum0, 1);
    lsum0 += __shfl_xor_sync(0xffffffffu, lsum0, 2);
    lsum1 += __shfl_xor_sync(0xffffffffu, lsum1, 1);
    lsum1 += __shfl_xor_sync(0xffffffffu, lsum1, 2);
    float inv0 = 1.0f / lsum0, inv1 = 1.0f / lsum1;

    const int b = bh >> 4, h = bh & 15;
    const size_t tok0 = (size_t)b * SEQ + q0 + r0 + g;
    #pragma unroll
    for (int nt = 0; nt < 8; nt++) {
        int col = nt * 8 + 2 * tig;
        int kc = 2 * h + (col >> 5), p = col & 31;
        uint32_t hh, ll;
        size_t b0 = (tok0 * 32 + kc) * 64 + p;
        split2(o[nt][0] * inv0, o[nt][1] * inv0, hh, ll);
        *(uint32_t*)&ys[b0] = hh;  *(uint32_t*)&ys[b0 + 32] = ll;
        size_t b1 = ((tok0 + 8) * 32 + kc) * 64 + p;
        split2(o[nt][2] * inv1, o[nt][3] * inv1, hh, ll);
        *(uint32_t*)&ys[b1] = hh;  *(uint32_t*)&ys[b1 + 32] = ll;
    }
}

// ---------------------------------------------------------------------------
extern "C" void kernel_launch(void* const* d_in, const int* in_sizes, int n_in,
                              void* d_out, int out_size)
{
    const float* x      = (const float*)d_in[0];
    const float* w_kv_a = (const float*)d_in[1];
    const float* w_kv_b = (const float*)d_in[2];
    const float* w_q_a  = (const float*)d_in[3];
    const float* w_q_b  = (const float*)d_in[4];
    const float* w_proj = (const float*)d_in[5];
    const float* kv_nw  = (const float*)d_in[6];
    const float* q_nw   = (const float*)d_in[7];
    float* out = (float*)d_out;

    __nv_bfloat16 *qlat_s, *kvlat_s, *wq_s, *wkv_s, *wproj_s, *ysv;
    __nv_bfloat16 *qh, *ql, *kh, *kl, *vh, *vl;
    cudaGetSymbolAddress((void**)&qlat_s,  g_qlat_s);
    cudaGetSymbolAddress((void**)&kvlat_s, g_kvlat_s);
    cudaGetSymbolAddress((void**)&wq_s,    g_wq_s);
    cudaGetSymbolAddress((void**)&wkv_s,   g_wkv_s);
    cudaGetSymbolAddress((void**)&wproj_s, g_wproj_s);
    cudaGetSymbolAddress((void**)&ysv,     g_ys);
    cudaGetSymbolAddress((void**)&qh, g_qh);  cudaGetSymbolAddress((void**)&ql, g_ql);
    cudaGetSymbolAddress((void**)&kh, g_kh);  cudaGetSymbolAddress((void**)&kl, g_kl);
    cudaGetSymbolAddress((void**)&vh, g_vh);  cudaGetSymbolAddress((void**)&vl, g_vl);

    cudaFuncSetAttribute(attn_tc,    cudaFuncAttributeMaxDynamicSharedMemorySize, ATTN_SMEM);
    cudaFuncSetAttribute(gemm_bf<0>, cudaFuncAttributeMaxDynamicSharedMemorySize, GEMMBF_SMEM);
    cudaFuncSetAttribute(gemm_bf<1>, cudaFuncAttributeMaxDynamicSharedMemorySize, GEMMBF_SMEM);
    cudaFuncSetAttribute(gemm_bf<2>, cudaFuncAttributeMaxDynamicSharedMemorySize, GEMMBF_SMEM);

    // pre-split weights into interleaved bf16 layout
    wsplit<<<64,   256>>>(w_q_b,  wq_s,    64,   16384);
    wsplit<<<128,  256>>>(w_kv_b, wkv_s,   64,   32768);
    wsplit<<<1024, 256>>>(w_proj, wproj_s, 1024, 262144);

    // fused latent projections + rmsnorm -> split-interleaved latents
    gemm_latf<<<128, 256>>>(x, w_q_a, w_kv_a, q_nw, kv_nw, qlat_s, kvlat_s);

    // up-projections -> per-head split tensors
    gemm_bf<0><<<dim3(8, 64),  256, GEMMBF_SMEM>>>(qlat_s,  wq_s,  nullptr, qh, ql, nullptr, nullptr, 64, 1024);
    gemm_bf<1><<<dim3(16, 64), 256, GEMMBF_SMEM>>>(kvlat_s, wkv_s, nullptr, kh, kl, vh, vl, 64, 2048);

    // attention -> split-interleaved y
    attn_tc<<<dim3(16, 64), 256, ATTN_SMEM>>>(qh, ql, kh, kl, vh, vl, ysv);

    // output projection (fp32 out)
    gemm_bf<2><<<dim3(8, 64), 256, GEMMBF_SMEM>>>(ysv, wproj_s, out, nullptr, nullptr, nullptr, nullptr, 1024, 1024);
}

// round 10
// speedup vs baseline: 1.0378x; 1.0188x over previous
#include <cuda_runtime.h>
#include <cuda_bf16.h>
#include <cstdint>

#define SEQ   2048
#define NTOK  8192

// ---------------- scratch (device globals: no runtime allocation) ----------
// interleaved split layout: [row][k/32][32 hi bf16 | 32 lo bf16]  (128B rows)
__device__ __nv_bfloat16 g_xs     [(size_t)NTOK * 2048];   // x pre-split (K=1024)
__device__ __nv_bfloat16 g_wlat_s [(size_t)128  * 2048];   // [Wq(64)|Wkv(64)] pre-split
__device__ __nv_bfloat16 g_qlat_s [(size_t)NTOK * 128];
__device__ __nv_bfloat16 g_kvlat_s[(size_t)NTOK * 128];
__device__ __nv_bfloat16 g_wq_s   [(size_t)1024 * 128];
__device__ __nv_bfloat16 g_wkv_s  [(size_t)2048 * 128];
__device__ __nv_bfloat16 g_wproj_s[(size_t)1024 * 2048];
__device__ __nv_bfloat16 g_ys     [(size_t)NTOK * 2048];
// per-head split tensors for attention [(b*16+h)][seq][64]
__device__ __nv_bfloat16 g_qh[(size_t)NTOK * 1024];
__device__ __nv_bfloat16 g_ql[(size_t)NTOK * 1024];
__device__ __nv_bfloat16 g_kh[(size_t)NTOK * 1024];
__device__ __nv_bfloat16 g_kl[(size_t)NTOK * 1024];
__device__ __nv_bfloat16 g_vh[(size_t)NTOK * 1024];
__device__ __nv_bfloat16 g_vl[(size_t)NTOK * 1024];

#define QSCALE (0.125f * 1.4426950408889634f)   // fold softmax scale * log2e

// ---------------- helpers ---------------------------------------------------
static __device__ __forceinline__ uint32_t smem_u32(const void* p) {
    uint32_t a;
    asm("{ .reg .u64 t; cvta.to.shared.u64 t, %1; cvt.u32.u64 %0, t; }"
        : "=r"(a) : "l"(p));
    return a;
}
static __device__ __forceinline__ uint32_t bfpack(float lo, float hi) {
    uint32_t r;
    asm("cvt.rn.bf16x2.f32 %0, %1, %2;" : "=r"(r) : "f"(hi), "f"(lo));
    return r;
}
static __device__ __forceinline__ void split2(float x, float y,
                                              uint32_t& h, uint32_t& l) {
    h = bfpack(x, y);
    __nv_bfloat162 hb = *reinterpret_cast<__nv_bfloat162*>(&h);
    l = bfpack(x - __bfloat162float(hb.x), y - __bfloat162float(hb.y));
}
static __device__ __forceinline__ float ex2f(float x) {
    float y; asm("ex2.approx.f32 %0, %1;" : "=f"(y) : "f"(x)); return y;
}
// swizzled smem addr: 128B rows of 8 x 16B chunks, chunk ^= row&7
static __device__ __forceinline__ uint32_t lda(uint32_t base, int row, int ch) {
    return base + row * 128 + (((uint32_t)ch ^ ((uint32_t)row & 7u)) << 4);
}

#define MMAB(c, a0, a1, a2, a3, b0, b1)                                        \
    asm volatile("mma.sync.aligned.m16n8k16.row.col.f32.bf16.bf16.f32 "        \
        "{%0,%1,%2,%3},{%4,%5,%6,%7},{%8,%9},{%0,%1,%2,%3};"                   \
        : "+f"((c)[0]), "+f"((c)[1]), "+f"((c)[2]), "+f"((c)[3])               \
        : "r"(a0), "r"(a1), "r"(a2), "r"(a3), "r"(b0), "r"(b1))

#define MMAX3(c, ah, al, bh0, bh1, bl0, bl1) do {                              \
    MMAB(c, (ah)[0], (ah)[1], (ah)[2], (ah)[3], bh0, bh1);                     \
    MMAB(c, (ah)[0], (ah)[1], (ah)[2], (ah)[3], bl0, bl1);                     \
    MMAB(c, (al)[0], (al)[1], (al)[2], (al)[3], bh0, bh1);                     \
} while (0)

#define LDSM4(r, addr)                                                         \
    asm volatile("ldmatrix.sync.aligned.m8n8.x4.shared.b16 {%0,%1,%2,%3}, [%4];" \
        : "=r"((r)[0]), "=r"((r)[1]), "=r"((r)[2]), "=r"((r)[3]) : "r"(addr))
#define LDSM4T(r, addr)                                                        \
    asm volatile("ldmatrix.sync.aligned.m8n8.x4.trans.shared.b16 {%0,%1,%2,%3}, [%4];" \
        : "=r"((r)[0]), "=r"((r)[1]), "=r"((r)[2]), "=r"((r)[3]) : "r"(addr))
#define CPA16(dst, src)                                                        \
    asm volatile("cp.async.cg.shared.global [%0], [%1], 16;" :: "r"(dst), "l"(src))
#define CPCOMMIT() asm volatile("cp.async.commit_group;" ::: "memory")
#define CPWAIT(n)  asm volatile("cp.async.wait_group %0;" :: "n"(n) : "memory")

// ======================================================================
// wsplit: W[n][K] fp32 -> O[n][K/32][32h|32l] bf16
// ======================================================================
__global__ __launch_bounds__(256) void wsplit(
    const float* __restrict__ W, __nv_bfloat16* __restrict__ O,
    int K, int nf4)
{
    int idx = blockIdx.x * 256 + threadIdx.x;
    if (idx >= nf4) return;
    int K4 = K >> 2;
    int n = idx / K4, k4 = idx - n * K4;
    float4 v = *(const float4*)&W[(size_t)n * K + k4 * 4];
    int k = k4 * 4, kc = k >> 5, p = k & 31;
    size_t o = ((size_t)n * (K >> 5) + kc) * 64 + p;
    uint32_t h0, l0, h1, l1;
    split2(v.x, v.y, h0, l0); split2(v.z, v.w, h1, l1);
    *(uint32_t*)&O[o]      = h0;  *(uint32_t*)&O[o + 2]  = h1;
    *(uint32_t*)&O[o + 32] = l0;  *(uint32_t*)&O[o + 34] = l1;
}

// ======================================================================
// gemm_bf<MODE>: C = A[M,K] @ B[N,K]^T, both pre-split interleaved bf16.
// BK=32, cp.async 3-STAGE ring, ldmatrix, x3 MMA. 2 CTAs/SM.
// MODE 0: q-up (scale QSCALE -> qh/ql per-head)
// MODE 1: kv-up (k->H,L / v->H2,L2)      MODE 2: fp32 out (Cf)
// ======================================================================
#define GEMMBF_SMEM 98304

template<int MODE>
__global__ __launch_bounds__(256, 2) void gemm_bf(
    const __nv_bfloat16* __restrict__ A, const __nv_bfloat16* __restrict__ B,
    float* __restrict__ Cf,
    __nv_bfloat16* __restrict__ H,  __nv_bfloat16* __restrict__ L,
    __nv_bfloat16* __restrict__ H2, __nv_bfloat16* __restrict__ L2,
    int K, int N)
{
    extern __shared__ char smraw[];
    const uint32_t base = smem_u32(smraw);
    // stage s: A at base + s*32768, B at +16384

    const int tid = threadIdx.x;
    const int w = tid >> 5, lane = tid & 31;
    const int g = lane >> 2, tig = lane & 3;
    const int l8 = lane & 7, sub = lane >> 3;
    const int wm = w & 1, wn = w >> 1;
    const int m0 = blockIdx.y * 128, n0 = blockIdx.x * 128;
    const int KC = K >> 5, CH = KC;

    float c[4][4][4] = {};

    // stage chunks 0,1,2 (empty commits keep group counting uniform)
    #pragma unroll
    for (int s = 0; s < 3; s++) {
        if (s < CH) {
            #pragma unroll
            for (int p = 0; p < 4; p++) {
                int idx = tid + p * 256, row = idx >> 3, ch = idx & 7;
                CPA16(lda(base + s * 32768, row, ch),
                      A + ((size_t)(m0 + row) * KC + s) * 64 + ch * 8);
                CPA16(lda(base + s * 32768 + 16384, row, ch),
                      B + ((size_t)(n0 + row) * KC + s) * 64 + ch * 8);
            }
        }
        CPCOMMIT();
    }

    int rb = 0;   // ring buffer index = cc % 3
    for (int cc = 0; cc < CH; cc++) {
        const uint32_t Ab = base + rb * 32768;
        const uint32_t Bb = Ab + 16384;
        // NOTE: for CH<=2 the trailing empty commit groups retire instantly,
        // so wait_group 2 would NOT cover chunk 0 -> wait for everything.
        if (CH > 2) { CPWAIT(2); } else { CPWAIT(0); }
        __syncthreads();

        #pragma unroll
        for (int ks = 0; ks < 2; ks++) {
            uint32_t ah[4][4], al[4][4];
            #pragma unroll
            for (int mt = 0; mt < 4; mt++) {
                int arow = wm * 64 + mt * 16 + l8 + ((sub & 1) << 3);
                int hch  = 2 * ks + (sub >> 1);
                LDSM4(ah[mt], lda(Ab, arow, hch));
                LDSM4(al[mt], lda(Ab, arow, hch + 4));
            }
            #pragma unroll
            for (int np = 0; np < 2; np++) {
                int brow = wn * 32 + np * 16 + ((sub >> 1) << 3) + l8;
                int bch  = 2 * ks + (sub & 1);
                uint32_t bhf[4], blf[4];
                LDSM4(bhf, lda(Bb, brow, bch));
                LDSM4(blf, lda(Bb, brow, bch + 4));
                #pragma unroll
                for (int mt = 0; mt < 4; mt++) {
                    MMAX3(c[mt][2*np],   ah[mt], al[mt], bhf[0], bhf[1], blf[0], blf[1]);
                    MMAX3(c[mt][2*np+1], ah[mt], al[mt], bhf[2], bhf[3], blf[2], blf[3]);
                }
            }
        }

        __syncthreads();
        if (cc + 3 < CH) {
            #pragma unroll
            for (int p = 0; p < 4; p++) {
                int idx = tid + p * 256, row = idx >> 3, ch = idx & 7;
                CPA16(lda(Ab, row, ch),
                      A + ((size_t)(m0 + row) * KC + cc + 3) * 64 + ch * 8);
                CPA16(lda(Bb, row, ch),
                      B + ((size_t)(n0 + row) * KC + cc + 3) * 64 + ch * 8);
            }
        }
        CPCOMMIT();
        if (++rb == 3) rb = 0;
    }

    if (MODE == 2) {
        #pragma unroll
        for (int mt = 0; mt < 4; mt++)
            #pragma unroll
            for (int nt = 0; nt < 4; nt++) {
                int r0 = m0 + wm * 64 + mt * 16 + g;
                int col = n0 + wn * 32 + nt * 8 + 2 * tig;
                *(float2*)&Cf[(size_t)r0 * N + col]       = make_float2(c[mt][nt][0], c[mt][nt][1]);
                *(float2*)&Cf[(size_t)(r0 + 8) * N + col] = make_float2(c[mt][nt][2], c[mt][nt][3]);
            }
    } else {
        const float sc = (MODE == 0) ? QSCALE : 1.0f;
        #pragma unroll
        for (int mt = 0; mt < 4; mt++)
            #pragma unroll
            for (int nt = 0; nt < 4; nt++) {
                int tok = m0 + wm * 64 + mt * 16 + g;
                int col = n0 + wn * 32 + nt * 8 + 2 * tig;
                int b = tok >> 11, tn = tok & 2047;
                int h, d;
                __nv_bfloat16 *DH, *DL;
                if (MODE == 0) {
                    h = col >> 6; d = col & 63; DH = H; DL = L;
                } else {
                    h = col >> 7; int rr = col & 127; d = rr & 63;
                    if (rr < 64) { DH = H; DL = L; } else { DH = H2; DL = L2; }
                }
                size_t a0 = (((size_t)b * 16 + h) * SEQ + tn) * 64 + d;
                size_t a1 = a0 + 8 * 64;
                uint32_t hp, lp;
                split2(c[mt][nt][0] * sc, c[mt][nt][1] * sc, hp, lp);
                *(uint32_t*)&DH[a0] = hp;  *(uint32_t*)&DL[a0] = lp;
                split2(c[mt][nt][2] * sc, c[mt][nt][3] * sc, hp, lp);
                *(uint32_t*)&DH[a1] = hp;  *(uint32_t*)&DL[a1] = lp;
            }
    }
}

// ======================================================================
// gemm_latf2: fused latent projections on PRE-SPLIT x.
// M-tile 64 tokens, N=128 = [Wq 64|Wkv 64], K=1024 -> 32 chunks of 32.
// cp.async 3-stage ring + ldmatrix (gemm_bf pattern). Warp tile 16x64,
// wn selects q/kv half -> rmsnorm is a pure intra-warp shfl reduce.
// ======================================================================
#define LATF_SMEM 73728   // 3 stages x (A 8KB + B 16KB)

__global__ __launch_bounds__(256, 2) void gemm_latf2(
    const __nv_bfloat16* __restrict__ A,   // xs [8192][32][64] split
    const __nv_bfloat16* __restrict__ B,   // wlat_s [128][32][64] split
    const float* __restrict__ nwq, const float* __restrict__ nwkv,
    __nv_bfloat16* __restrict__ Cq, __nv_bfloat16* __restrict__ Ckv)
{
    extern __shared__ char smraw[];
    const uint32_t base = smem_u32(smraw);
    __shared__ float nws[128];
    // stage s: A at base + s*24576 (8KB), B at +8192 (16KB)

    const int tid = threadIdx.x;
    const int w = tid >> 5, lane = tid & 31;
    const int g = lane >> 2, tig = lane & 3;
    const int l8 = lane & 7, sub = lane >> 3;
    const int wm = w >> 1, wn = w & 1;
    const int m0 = blockIdx.x * 64;

    if (tid < 64)       nws[tid] = nwq[tid];
    else if (tid < 128) nws[tid] = nwkv[tid - 64];

    float c[8][4] = {};

    // prologue: stage chunks 0,1,2
    #pragma unroll
    for (int s = 0; s < 3; s++) {
        const uint32_t Ab = base + s * 24576, Bb = Ab + 8192;
        #pragma unroll
        for (int p = 0; p < 2; p++) {           // A: 512 16B chunks
            int idx = tid + p * 256, row = idx >> 3, ch = idx & 7;
            CPA16(lda(Ab, row, ch), A + ((size_t)(m0 + row) * 32 + s) * 64 + ch * 8);
        }
        #pragma unroll
        for (int p = 0; p < 4; p++) {           // B: 1024 16B chunks
            int idx = tid + p * 256, row = idx >> 3, ch = idx & 7;
            CPA16(lda(Bb, row, ch), B + ((size_t)row * 32 + s) * 64 + ch * 8);
        }
        CPCOMMIT();
    }

    int rb = 0;
    for (int cc = 0; cc < 32; cc++) {
        const uint32_t Ab = base + rb * 24576, Bb = Ab + 8192;
        CPWAIT(2);
        __syncthreads();

        #pragma unroll
        for (int ks = 0; ks < 2; ks++) {
            uint32_t ah[4], al[4];
            {
                int arow = wm * 16 + l8 + ((sub & 1) << 3);
                int hch  = 2 * ks + (sub >> 1);
                LDSM4(ah, lda(Ab, arow, hch));
                LDSM4(al, lda(Ab, arow, hch + 4));
            }
            #pragma unroll
            for (int np = 0; np < 4; np++) {
                int brow = wn * 64 + np * 16 + ((sub >> 1) << 3) + l8;
                int bch  = 2 * ks + (sub & 1);
                uint32_t bhf[4], blf[4];
                LDSM4(bhf, lda(Bb, brow, bch));
                LDSM4(blf, lda(Bb, brow, bch + 4));
                MMAX3(c[2*np],   ah, al, bhf[0], bhf[1], blf[0], blf[1]);
                MMAX3(c[2*np+1], ah, al, bhf[2], bhf[3], blf[2], blf[3]);
            }
        }

        __syncthreads();
        if (cc + 3 < 32) {
            #pragma unroll
            for (int p = 0; p < 2; p++) {
                int idx = tid + p * 256, row = idx >> 3, ch = idx & 7;
                CPA16(lda(Ab, row, ch), A + ((size_t)(m0 + row) * 32 + cc + 3) * 64 + ch * 8);
            }
            #pragma unroll
            for (int p = 0; p < 4; p++) {
                int idx = tid + p * 256, row = idx >> 3, ch = idx & 7;
                CPA16(lda(Bb, row, ch), B + ((size_t)row * 32 + cc + 3) * 64 + ch * 8);
            }
        }
        CPCOMMIT();
        if (++rb == 3) rb = 0;
    }

    // rmsnorm: whole 64-wide row lives in this warp -> shfl over tig
    float p0 = 0.f, p1 = 0.f;
    #pragma unroll
    for (int nt = 0; nt < 8; nt++) {
        p0 += c[nt][0]*c[nt][0] + c[nt][1]*c[nt][1];
        p1 += c[nt][2]*c[nt][2] + c[nt][3]*c[nt][3];
    }
    p0 += __shfl_xor_sync(0xffffffffu, p0, 1);
    p0 += __shfl_xor_sync(0xffffffffu, p0, 2);
    p1 += __shfl_xor_sync(0xffffffffu, p1, 1);
    p1 += __shfl_xor_sync(0xffffffffu, p1, 2);
    float s0 = rsqrtf(p0 * (1.0f/64.0f) + 1e-6f);
    float s1 = rsqrtf(p1 * (1.0f/64.0f) + 1e-6f);

    __nv_bfloat16* C = wn ? Ckv : Cq;
    const int r = m0 + wm * 16 + g;
    #pragma unroll
    for (int nt = 0; nt < 8; nt++) {
        int col = nt * 8 + 2 * tig;
        float w0 = nws[wn * 64 + col], w1 = nws[wn * 64 + col + 1];
        int kc = col >> 5, p = col & 31;
        uint32_t hh, ll;
        size_t b0 = ((size_t)r * 2 + kc) * 64 + p;
        split2(c[nt][0]*s0*w0, c[nt][1]*s0*w1, hh, ll);
        *(uint32_t*)&C[b0] = hh;  *(uint32_t*)&C[b0 + 32] = ll;
        size_t b1 = ((size_t)(r + 8) * 2 + kc) * 64 + p;
        split2(c[nt][2]*s1*w0, c[nt][3]*s1*w1, hh, ll);
        *(uint32_t*)&C[b1] = hh;  *(uint32_t*)&C[b1 + 32] = ll;
    }
}

// ======================================================================
// attn_tc: flash attention, bf16x3 mma.sync, ldmatrix fragments.
// 64-key sub-chunks double-buffered. Q pre-scaled by 0.125*log2e -> ex2.
// Output written split-interleaved into ys [tok][32][64].
// ======================================================================
#define ATTN_SMEM 98304

__global__ __launch_bounds__(256, 2) void attn_tc(
    const __nv_bfloat16* __restrict__ qh_g, const __nv_bfloat16* __restrict__ ql_g,
    const __nv_bfloat16* __restrict__ kh_g, const __nv_bfloat16* __restrict__ kl_g,
    const __nv_bfloat16* __restrict__ vh_g, const __nv_bfloat16* __restrict__ vl_g,
    __nv_bfloat16* __restrict__ ys)
{
    extern __shared__ char smraw[];
    const uint32_t base = smem_u32(smraw);
    const uint32_t Qh = base, Ql = base + 16384;
    const uint32_t kvb = base + 32768;

    const int tid = threadIdx.x;
    const int w = tid >> 5, lane = tid & 31;
    const int g = lane >> 2, tig = lane & 3;
    const int l8 = lane & 7, sub = lane >> 3;
    const int r0 = w * 16;
    const int bh = blockIdx.y;
    const int q0 = blockIdx.x * 128;
    const size_t hb = (size_t)bh * SEQ;

    #pragma unroll
    for (int p = 0; p < 4; p++) {
        int idx = tid + p * 256, row = idx >> 3, ch = idx & 7;
        size_t go = (hb + q0 + row) * 64 + ch * 8;
        CPA16(lda(Qh, row, ch), qh_g + go);
        CPA16(lda(Ql, row, ch), ql_g + go);
    }
    #pragma unroll
    for (int p = 0; p < 2; p++) {
        int idx = tid + p * 256, row = idx >> 3, ch = idx & 7;
        size_t go = (hb + row) * 64 + ch * 8;
        uint32_t so = (uint32_t)row * 128 + (((uint32_t)ch ^ ((uint32_t)row & 7u)) << 4);
        CPA16(kvb + so,         kh_g + go);  CPA16(kvb + 8192 + so,  kl_g + go);
        CPA16(kvb + 16384 + so, vh_g + go);  CPA16(kvb + 24576 + so, vl_g + go);
    }
    CPCOMMIT();
    #pragma unroll
    for (int p = 0; p < 2; p++) {
        int idx = tid + p * 256, row = idx >> 3, ch = idx & 7;
        size_t go = (hb + 64 + row) * 64 + ch * 8;
        uint32_t so = (uint32_t)row * 128 + (((uint32_t)ch ^ ((uint32_t)row & 7u)) << 4);
        CPA16(kvb + 32768 + so, kh_g + go);  CPA16(kvb + 40960 + so, kl_g + go);
        CPA16(kvb + 49152 + so, vh_g + go);  CPA16(kvb + 57344 + so, vl_g + go);
    }
    CPCOMMIT();

    float o[8][4] = {};
    float lsum0 = 0.f, lsum1 = 0.f;

    for (int sc = 0; sc < 32; sc++) {
        const int bi = sc & 1;
        const uint32_t Kh = kvb + bi * 32768, Kl = Kh + 8192;
        const uint32_t Vh = Kh + 16384,       Vl = Kh + 24576;
        CPWAIT(1);
        __syncthreads();

        float s[8][4] = {};
        #pragma unroll
        for (int ks = 0; ks < 4; ks++) {
            int arow = r0 + l8 + ((sub & 1) << 3);
            int ach  = 2 * ks + (sub >> 1);
            uint32_t ah[4], al[4];
            LDSM4(ah, lda(Qh, arow, ach));
            LDSM4(al, lda(Ql, arow, ach));
            #pragma unroll
            for (int ntp = 0; ntp < 4; ntp++) {
                int krow = ntp * 16 + ((sub >> 1) << 3) + l8;
                int kch  = 2 * ks + (sub & 1);
                uint32_t bhf[4], blf[4];
                LDSM4(bhf, lda(Kh, krow, kch));
                LDSM4(blf, lda(Kl, krow, kch));
                MMAX3(s[2 * ntp],     ah, al, bhf[0], bhf[1], blf[0], blf[1]);
                MMAX3(s[2 * ntp + 1], ah, al, bhf[2], bhf[3], blf[2], blf[3]);
            }
        }

        #pragma unroll
        for (int ks = 0; ks < 4; ks++) {
            float e0 = ex2f(s[2*ks][0]),   e1 = ex2f(s[2*ks][1]);
            float e2 = ex2f(s[2*ks][2]),   e3 = ex2f(s[2*ks][3]);
            float e4 = ex2f(s[2*ks+1][0]), e5 = ex2f(s[2*ks+1][1]);
            float e6 = ex2f(s[2*ks+1][2]), e7 = ex2f(s[2*ks+1][3]);
            lsum0 += e0 + e1 + e4 + e5;
            lsum1 += e2 + e3 + e6 + e7;
            uint32_t ph[4], pl[4];
            split2(e0, e1, ph[0], pl[0]);
            split2(e2, e3, ph[1], pl[1]);
            split2(e4, e5, ph[2], pl[2]);
            split2(e6, e7, ph[3], pl[3]);
            #pragma unroll
            for (int ntp = 0; ntp < 4; ntp++) {
                int vrow = ks * 16 + ((sub & 1) << 3) + l8;
                int vch  = 2 * ntp + (sub >> 1);
                uint32_t vhf[4], vlf[4];
                LDSM4T(vhf, lda(Vh, vrow, vch));
                LDSM4T(vlf, lda(Vl, vrow, vch));
                MMAX3(o[2 * ntp],     ph, pl, vhf[0], vhf[1], vlf[0], vlf[1]);
                MMAX3(o[2 * ntp + 1], ph, pl, vhf[2], vhf[3], vlf[2], vlf[3]);
            }
        }

        __syncthreads();
        if (sc + 2 < 32) {
            #pragma unroll
            for (int p = 0; p < 2; p++) {
                int idx = tid + p * 256, row = idx >> 3, ch = idx & 7;
                size_t go = (hb + (size_t)(sc + 2) * 64 + row) * 64 + ch * 8;
                uint32_t so = (uint32_t)row * 128 + (((uint32_t)ch ^ ((uint32_t)row & 7u)) << 4);
                CPA16(Kh + so, kh_g + go);  CPA16(Kl + so, kl_g + go);
                CPA16(Vh + so, vh_g + go);  CPA16(Vl + so, vl_g + go);
            }
        }
        CPCOMMIT();
    }

    lsum0 += __shfl_xor_sync(0xffffffffu, lsum0, 1);
    lsum0 += __shfl_xor_sync(0xffffffffu, lsum0, 2);
    lsum1 += __shfl_xor_sync(0xffffffffu, lsum1, 1);
    lsum1 += __shfl_xor_sync(0xffffffffu, lsum1, 2);
    float inv0 = 1.0f / lsum0, inv1 = 1.0f / lsum1;

    const int b = bh >> 4, h = bh & 15;
    const size_t tok0 = (size_t)b * SEQ + q0 + r0 + g;
    #pragma unroll
    for (int nt = 0; nt < 8; nt++) {
        int col = nt * 8 + 2 * tig;
        int kc = 2 * h + (col >> 5), p = col & 31;
        uint32_t hh, ll;
        size_t b0 = (tok0 * 32 + kc) * 64 + p;
        split2(o[nt][0] * inv0, o[nt][1] * inv0, hh, ll);
        *(uint32_t*)&ys[b0] = hh;  *(uint32_t*)&ys[b0 + 32] = ll;
        size_t b1 = ((tok0 + 8) * 32 + kc) * 64 + p;
        split2(o[nt][2] * inv1, o[nt][3] * inv1, hh, ll);
        *(uint32_t*)&ys[b1] = hh;  *(uint32_t*)&ys[b1 + 32] = ll;
    }
}

// ---------------------------------------------------------------------------
extern "C" void kernel_launch(void* const* d_in, const int* in_sizes, int n_in,
                              void* d_out, int out_size)
{
    const float* x      = (const float*)d_in[0];
    const float* w_kv_a = (const float*)d_in[1];
    const float* w_kv_b = (const float*)d_in[2];
    const float* w_q_a  = (const float*)d_in[3];
    const float* w_q_b  = (const float*)d_in[4];
    const float* w_proj = (const float*)d_in[5];
    const float* kv_nw  = (const float*)d_in[6];
    const float* q_nw   = (const float*)d_in[7];
    float* out = (float*)d_out;

    __nv_bfloat16 *xs, *wlat_s, *qlat_s, *kvlat_s, *wq_s, *wkv_s, *wproj_s, *ysv;
    __nv_bfloat16 *qh, *ql, *kh, *kl, *vh, *vl;
    cudaGetSymbolAddress((void**)&xs,      g_xs);
    cudaGetSymbolAddress((void**)&wlat_s,  g_wlat_s);
    cudaGetSymbolAddress((void**)&qlat_s,  g_qlat_s);
    cudaGetSymbolAddress((void**)&kvlat_s, g_kvlat_s);
    cudaGetSymbolAddress((void**)&wq_s,    g_wq_s);
    cudaGetSymbolAddress((void**)&wkv_s,   g_wkv_s);
    cudaGetSymbolAddress((void**)&wproj_s, g_wproj_s);
    cudaGetSymbolAddress((void**)&ysv,     g_ys);
    cudaGetSymbolAddress((void**)&qh, g_qh);  cudaGetSymbolAddress((void**)&ql, g_ql);
    cudaGetSymbolAddress((void**)&kh, g_kh);  cudaGetSymbolAddress((void**)&kl, g_kl);
    cudaGetSymbolAddress((void**)&vh, g_vh);  cudaGetSymbolAddress((void**)&vl, g_vl);

    cudaFuncSetAttribute(attn_tc,    cudaFuncAttributeMaxDynamicSharedMemorySize, ATTN_SMEM);
    cudaFuncSetAttribute(gemm_bf<0>, cudaFuncAttributeMaxDynamicSharedMemorySize, GEMMBF_SMEM);
    cudaFuncSetAttribute(gemm_bf<1>, cudaFuncAttributeMaxDynamicSharedMemorySize, GEMMBF_SMEM);
    cudaFuncSetAttribute(gemm_bf<2>, cudaFuncAttributeMaxDynamicSharedMemorySize, GEMMBF_SMEM);
    cudaFuncSetAttribute(gemm_latf2, cudaFuncAttributeMaxDynamicSharedMemorySize, LATF_SMEM);

    // pre-split weights and x into interleaved bf16 layout
    wsplit<<<64,   256>>>(w_q_b,  wq_s,    64,   16384);
    wsplit<<<128,  256>>>(w_kv_b, wkv_s,   64,   32768);
    wsplit<<<1024, 256>>>(w_proj, wproj_s, 1024, 262144);
    wsplit<<<64,   256>>>(w_q_a,  wlat_s,              1024, 16384);
    wsplit<<<64,   256>>>(w_kv_a, wlat_s + 64 * 2048,  1024, 16384);
    wsplit<<<8192, 256>>>(x,      xs,      1024, 2097152);

    // fused latent projections + rmsnorm -> split-interleaved latents
    gemm_latf2<<<128, 256, LATF_SMEM>>>(xs, wlat_s, q_nw, kv_nw, qlat_s, kvlat_s);

    // up-projections -> per-head split tensors
    gemm_bf<0><<<dim3(8, 64),  256, GEMMBF_SMEM>>>(qlat_s,  wq_s,  nullptr, qh, ql, nullptr, nullptr, 64, 1024);
    gemm_bf<1><<<dim3(16, 64), 256, GEMMBF_SMEM>>>(kvlat_s, wkv_s, nullptr, kh, kl, vh, vl, 64, 2048);

    // attention -> split-interleaved y
    attn_tc<<<dim3(16, 64), 256, ATTN_SMEM>>>(qh, ql, kh, kl, vh, vl, ysv);

    // output projection (fp32 out)
    gemm_bf<2><<<dim3(8, 64), 256, GEMMBF_SMEM>>>(ysv, wproj_s, out, nullptr, nullptr, nullptr, nullptr, 1024, 1024);
}

// round 11
// speedup vs baseline: 1.0474x; 1.0093x over previous
#include <cuda_runtime.h>
#include <cuda_bf16.h>
#include <cstdint>

#define SEQ   2048
#define NTOK  8192

// ---------------- scratch (device globals: no runtime allocation) ----------
// interleaved split layout: [row][k/32][32 hi bf16 | 32 lo bf16]  (128B rows)
__device__ __nv_bfloat16 g_xs     [(size_t)NTOK * 2048];   // x pre-split (K=1024)
__device__ __nv_bfloat16 g_wlat_s [(size_t)128  * 2048];   // [Wq(64)|Wkv(64)] pre-split
__device__ __nv_bfloat16 g_qlat_s [(size_t)NTOK * 128];
__device__ __nv_bfloat16 g_kvlat_s[(size_t)NTOK * 128];
__device__ __nv_bfloat16 g_wq_s   [(size_t)1024 * 128];
__device__ __nv_bfloat16 g_wkv_s  [(size_t)2048 * 128];
__device__ __nv_bfloat16 g_wproj_s[(size_t)1024 * 2048];
__device__ __nv_bfloat16 g_ys     [(size_t)NTOK * 2048];
// per-head split tensors for attention [(b*16+h)][seq][64]
__device__ __nv_bfloat16 g_qh[(size_t)NTOK * 1024];
__device__ __nv_bfloat16 g_ql[(size_t)NTOK * 1024];
__device__ __nv_bfloat16 g_kh[(size_t)NTOK * 1024];
__device__ __nv_bfloat16 g_kl[(size_t)NTOK * 1024];
__device__ __nv_bfloat16 g_vh[(size_t)NTOK * 1024];
__device__ __nv_bfloat16 g_vl[(size_t)NTOK * 1024];

#define QSCALE (0.125f * 1.4426950408889634f)   // fold softmax scale * log2e

// ---------------- helpers ---------------------------------------------------
static __device__ __forceinline__ uint32_t smem_u32(const void* p) {
    uint32_t a;
    asm("{ .reg .u64 t; cvta.to.shared.u64 t, %1; cvt.u32.u64 %0, t; }"
        : "=r"(a) : "l"(p));
    return a;
}
static __device__ __forceinline__ uint32_t bfpack(float lo, float hi) {
    uint32_t r;
    asm("cvt.rn.bf16x2.f32 %0, %1, %2;" : "=r"(r) : "f"(hi), "f"(lo));
    return r;
}
static __device__ __forceinline__ void split2(float x, float y,
                                              uint32_t& h, uint32_t& l) {
    h = bfpack(x, y);
    __nv_bfloat162 hb = *reinterpret_cast<__nv_bfloat162*>(&h);
    l = bfpack(x - __bfloat162float(hb.x), y - __bfloat162float(hb.y));
}
static __device__ __forceinline__ float ex2f(float x) {
    float y; asm("ex2.approx.f32 %0, %1;" : "=f"(y) : "f"(x)); return y;
}
// swizzled smem addr: 128B rows of 8 x 16B chunks, chunk ^= row&7
static __device__ __forceinline__ uint32_t lda(uint32_t base, int row, int ch) {
    return base + row * 128 + (((uint32_t)ch ^ ((uint32_t)row & 7u)) << 4);
}

#define MMAB(c, a0, a1, a2, a3, b0, b1)                                        \
    asm volatile("mma.sync.aligned.m16n8k16.row.col.f32.bf16.bf16.f32 "        \
        "{%0,%1,%2,%3},{%4,%5,%6,%7},{%8,%9},{%0,%1,%2,%3};"                   \
        : "+f"((c)[0]), "+f"((c)[1]), "+f"((c)[2]), "+f"((c)[3])               \
        : "r"(a0), "r"(a1), "r"(a2), "r"(a3), "r"(b0), "r"(b1))

#define MMAX3(c, ah, al, bh0, bh1, bl0, bl1) do {                              \
    MMAB(c, (ah)[0], (ah)[1], (ah)[2], (ah)[3], bh0, bh1);                     \
    MMAB(c, (ah)[0], (ah)[1], (ah)[2], (ah)[3], bl0, bl1);                     \
    MMAB(c, (al)[0], (al)[1], (al)[2], (al)[3], bh0, bh1);                     \
} while (0)

#define LDSM4(r, addr)                                                         \
    asm volatile("ldmatrix.sync.aligned.m8n8.x4.shared.b16 {%0,%1,%2,%3}, [%4];" \
        : "=r"((r)[0]), "=r"((r)[1]), "=r"((r)[2]), "=r"((r)[3]) : "r"(addr))
#define LDSM4T(r, addr)                                                        \
    asm volatile("ldmatrix.sync.aligned.m8n8.x4.trans.shared.b16 {%0,%1,%2,%3}, [%4];" \
        : "=r"((r)[0]), "=r"((r)[1]), "=r"((r)[2]), "=r"((r)[3]) : "r"(addr))
#define CPA16(dst, src)                                                        \
    asm volatile("cp.async.cg.shared.global [%0], [%1], 16;" :: "r"(dst), "l"(src))
#define CPCOMMIT() asm volatile("cp.async.commit_group;" ::: "memory")
#define CPWAIT(n)  asm volatile("cp.async.wait_group %0;" :: "n"(n) : "memory")

// ======================================================================
// wsplit: W[n][K] fp32 -> O[n][K/32][32h|32l] bf16
// ======================================================================
__global__ __launch_bounds__(256) void wsplit(
    const float* __restrict__ W, __nv_bfloat16* __restrict__ O,
    int K, int nf4)
{
    int idx = blockIdx.x * 256 + threadIdx.x;
    if (idx >= nf4) return;
    int K4 = K >> 2;
    int n = idx / K4, k4 = idx - n * K4;
    float4 v = *(const float4*)&W[(size_t)n * K + k4 * 4];
    int k = k4 * 4, kc = k >> 5, p = k & 31;
    size_t o = ((size_t)n * (K >> 5) + kc) * 64 + p;
    uint32_t h0, l0, h1, l1;
    split2(v.x, v.y, h0, l0); split2(v.z, v.w, h1, l1);
    *(uint32_t*)&O[o]      = h0;  *(uint32_t*)&O[o + 2]  = h1;
    *(uint32_t*)&O[o + 32] = l0;  *(uint32_t*)&O[o + 34] = l1;
}

// ======================================================================
// gemm_bf<MODE,KC,NN>: C = A[M,K] @ B[N,K]^T, pre-split interleaved bf16.
// KC = K/32 (compile-time), NN = N (compile-time). 3-stage cp.async ring,
// ldmatrix, x3 MMA, 2 CTAs/SM. Unroll-3 folds the ring index.
// MODE 0: q-up (QSCALE -> qh/ql)  MODE 1: kv-up  MODE 2: fp32 out
// ======================================================================
#define GEMMBF_SMEM 98304

template<int MODE, int KC, int NN>
__global__ __launch_bounds__(256, 2) void gemm_bf(
    const __nv_bfloat16* __restrict__ A, const __nv_bfloat16* __restrict__ B,
    float* __restrict__ Cf,
    __nv_bfloat16* __restrict__ H,  __nv_bfloat16* __restrict__ L,
    __nv_bfloat16* __restrict__ H2, __nv_bfloat16* __restrict__ L2)
{
    extern __shared__ char smraw[];
    const uint32_t base = smem_u32(smraw);
    // stage s: A at base + s*32768, B at +16384

    const int tid = threadIdx.x;
    const int w = tid >> 5, lane = tid & 31;
    const int g = lane >> 2, tig = lane & 3;
    const int l8 = lane & 7, sub = lane >> 3;
    const int wm = w & 1, wn = w >> 1;
    const int m0 = blockIdx.y * 128, n0 = blockIdx.x * 128;

    // per-thread staging constants (4 pieces of 256 threads each)
    int rowp[4], chp[4];
    uint32_t sop[4];
    const __nv_bfloat16 *pa[4], *pb[4];
    #pragma unroll
    for (int p = 0; p < 4; p++) {
        int idx = tid + p * 256;
        rowp[p] = idx >> 3; chp[p] = idx & 7;
        sop[p] = (uint32_t)rowp[p] * 128 +
                 (((uint32_t)chp[p] ^ ((uint32_t)rowp[p] & 7u)) << 4);
        pa[p] = A + (size_t)(m0 + rowp[p]) * KC * 64 + chp[p] * 8;
        pb[p] = B + (size_t)(n0 + rowp[p]) * KC * 64 + chp[p] * 8;
    }

    float c[4][4][4] = {};

    // stage chunks 0,1,2 (empty commits keep group counting uniform)
    #pragma unroll
    for (int s = 0; s < 3; s++) {
        if (s < KC) {
            #pragma unroll
            for (int p = 0; p < 4; p++) {
                CPA16(base + s * 32768 + sop[p],         pa[p] + s * 64);
                CPA16(base + s * 32768 + 16384 + sop[p], pb[p] + s * 64);
            }
        }
        CPCOMMIT();
    }

    #pragma unroll 3
    for (int cc = 0; cc < KC; cc++) {
        const int rb = cc % 3;
        const uint32_t Ab = base + rb * 32768;
        const uint32_t Bb = Ab + 16384;
        // for KC<=2 trailing empty groups retire instantly -> wait all
        if (KC > 2) { CPWAIT(2); } else { CPWAIT(0); }
        __syncthreads();

        #pragma unroll
        for (int ks = 0; ks < 2; ks++) {
            uint32_t ah[4][4], al[4][4];
            #pragma unroll
            for (int mt = 0; mt < 4; mt++) {
                int arow = wm * 64 + mt * 16 + l8 + ((sub & 1) << 3);
                int hch  = 2 * ks + (sub >> 1);
                LDSM4(ah[mt], lda(Ab, arow, hch));
                LDSM4(al[mt], lda(Ab, arow, hch + 4));
            }
            #pragma unroll
            for (int np = 0; np < 2; np++) {
                int brow = wn * 32 + np * 16 + ((sub >> 1) << 3) + l8;
                int bch  = 2 * ks + (sub & 1);
                uint32_t bhf[4], blf[4];
                LDSM4(bhf, lda(Bb, brow, bch));
                LDSM4(blf, lda(Bb, brow, bch + 4));
                #pragma unroll
                for (int mt = 0; mt < 4; mt++) {
                    MMAX3(c[mt][2*np],   ah[mt], al[mt], bhf[0], bhf[1], blf[0], blf[1]);
                    MMAX3(c[mt][2*np+1], ah[mt], al[mt], bhf[2], bhf[3], blf[2], blf[3]);
                }
            }
        }

        __syncthreads();
        if (cc + 3 < KC) {
            #pragma unroll
            for (int p = 0; p < 4; p++) {
                CPA16(Ab + sop[p],         pa[p] + (cc + 3) * 64);
                CPA16(Bb + sop[p],         pb[p] + (cc + 3) * 64);
            }
        }
        CPCOMMIT();
    }

    if (MODE == 2) {
        #pragma unroll
        for (int mt = 0; mt < 4; mt++)
            #pragma unroll
            for (int nt = 0; nt < 4; nt++) {
                int r0 = m0 + wm * 64 + mt * 16 + g;
                int col = n0 + wn * 32 + nt * 8 + 2 * tig;
                *(float2*)&Cf[(size_t)r0 * NN + col]       = make_float2(c[mt][nt][0], c[mt][nt][1]);
                *(float2*)&Cf[(size_t)(r0 + 8) * NN + col] = make_float2(c[mt][nt][2], c[mt][nt][3]);
            }
    } else {
        const float sc = (MODE == 0) ? QSCALE : 1.0f;
        #pragma unroll
        for (int mt = 0; mt < 4; mt++)
            #pragma unroll
            for (int nt = 0; nt < 4; nt++) {
                int tok = m0 + wm * 64 + mt * 16 + g;
                int col = n0 + wn * 32 + nt * 8 + 2 * tig;
                int b = tok >> 11, tn = tok & 2047;
                int h, d;
                __nv_bfloat16 *DH, *DL;
                if (MODE == 0) {
                    h = col >> 6; d = col & 63; DH = H; DL = L;
                } else {
                    h = col >> 7; int rr = col & 127; d = rr & 63;
                    if (rr < 64) { DH = H; DL = L; } else { DH = H2; DL = L2; }
                }
                size_t a0 = (((size_t)b * 16 + h) * SEQ + tn) * 64 + d;
                size_t a1 = a0 + 8 * 64;
                uint32_t hp, lp;
                split2(c[mt][nt][0] * sc, c[mt][nt][1] * sc, hp, lp);
                *(uint32_t*)&DH[a0] = hp;  *(uint32_t*)&DL[a0] = lp;
                split2(c[mt][nt][2] * sc, c[mt][nt][3] * sc, hp, lp);
                *(uint32_t*)&DH[a1] = hp;  *(uint32_t*)&DL[a1] = lp;
            }
    }
}

// ======================================================================
// gemm_latf2: fused latent projections on PRE-SPLIT x.
// M-tile 64 tokens, N=128 = [Wq 64|Wkv 64], K=1024 -> 32 chunks of 32.
// cp.async 3-stage ring + ldmatrix. Warp tile 16x64, wn selects q/kv
// half -> rmsnorm is a pure intra-warp shfl reduce. Unroll-3 ring.
// ======================================================================
#define LATF_SMEM 73728   // 3 stages x (A 8KB + B 16KB)

__global__ __launch_bounds__(256, 2) void gemm_latf2(
    const __nv_bfloat16* __restrict__ A,   // xs [8192][32][64] split
    const __nv_bfloat16* __restrict__ B,   // wlat_s [128][32][64] split
    const float* __restrict__ nwq, const float* __restrict__ nwkv,
    __nv_bfloat16* __restrict__ Cq, __nv_bfloat16* __restrict__ Ckv)
{
    extern __shared__ char smraw[];
    const uint32_t base = smem_u32(smraw);
    __shared__ float nws[128];
    // stage s: A at base + s*24576 (8KB), B at +8192 (16KB)

    const int tid = threadIdx.x;
    const int w = tid >> 5, lane = tid & 31;
    const int g = lane >> 2, tig = lane & 3;
    const int l8 = lane & 7, sub = lane >> 3;
    const int wm = w >> 1, wn = w & 1;
    const int m0 = blockIdx.x * 64;

    if (tid < 64)       nws[tid] = nwq[tid];
    else if (tid < 128) nws[tid] = nwkv[tid - 64];

    // staging constants
    int rowA[2], chA[2], rowB[4], chB[4];
    uint32_t soA[2], soB[4];
    const __nv_bfloat16 *pA[2], *pB[4];
    #pragma unroll
    for (int p = 0; p < 2; p++) {
        int idx = tid + p * 256;
        rowA[p] = idx >> 3; chA[p] = idx & 7;
        soA[p] = (uint32_t)rowA[p] * 128 +
                 (((uint32_t)chA[p] ^ ((uint32_t)rowA[p] & 7u)) << 4);
        pA[p] = A + (size_t)(m0 + rowA[p]) * 2048 + chA[p] * 8;
    }
    #pragma unroll
    for (int p = 0; p < 4; p++) {
        int idx = tid + p * 256;
        rowB[p] = idx >> 3; chB[p] = idx & 7;
        soB[p] = (uint32_t)rowB[p] * 128 +
                 (((uint32_t)chB[p] ^ ((uint32_t)rowB[p] & 7u)) << 4);
        pB[p] = B + (size_t)rowB[p] * 2048 + chB[p] * 8;
    }

    float c[8][4] = {};

    // prologue: stage chunks 0,1,2
    #pragma unroll
    for (int s = 0; s < 3; s++) {
        const uint32_t Ab = base + s * 24576, Bb = Ab + 8192;
        #pragma unroll
        for (int p = 0; p < 2; p++)
            CPA16(Ab + soA[p], pA[p] + s * 64);
        #pragma unroll
        for (int p = 0; p < 4; p++)
            CPA16(Bb + soB[p], pB[p] + s * 64);
        CPCOMMIT();
    }

    #pragma unroll 3
    for (int cc = 0; cc < 32; cc++) {
        const int rb = cc % 3;
        const uint32_t Ab = base + rb * 24576, Bb = Ab + 8192;
        CPWAIT(2);
        __syncthreads();

        #pragma unroll
        for (int ks = 0; ks < 2; ks++) {
            uint32_t ah[4], al[4];
            {
                int arow = wm * 16 + l8 + ((sub & 1) << 3);
                int hch  = 2 * ks + (sub >> 1);
                LDSM4(ah, lda(Ab, arow, hch));
                LDSM4(al, lda(Ab, arow, hch + 4));
            }
            #pragma unroll
            for (int np = 0; np < 4; np++) {
                int brow = wn * 64 + np * 16 + ((sub >> 1) << 3) + l8;
                int bch  = 2 * ks + (sub & 1);
                uint32_t bhf[4], blf[4];
                LDSM4(bhf, lda(Bb, brow, bch));
                LDSM4(blf, lda(Bb, brow, bch + 4));
                MMAX3(c[2*np],   ah, al, bhf[0], bhf[1], blf[0], blf[1]);
                MMAX3(c[2*np+1], ah, al, bhf[2], bhf[3], blf[2], blf[3]);
            }
        }

        __syncthreads();
        if (cc + 3 < 32) {
            #pragma unroll
            for (int p = 0; p < 2; p++)
                CPA16(Ab + soA[p], pA[p] + (cc + 3) * 64);
            #pragma unroll
            for (int p = 0; p < 4; p++)
                CPA16(Bb + soB[p], pB[p] + (cc + 3) * 64);
        }
        CPCOMMIT();
    }

    // rmsnorm: whole 64-wide row lives in this warp -> shfl over tig
    float p0 = 0.f, p1 = 0.f;
    #pragma unroll
    for (int nt = 0; nt < 8; nt++) {
        p0 += c[nt][0]*c[nt][0] + c[nt][1]*c[nt][1];
        p1 += c[nt][2]*c[nt][2] + c[nt][3]*c[nt][3];
    }
    p0 += __shfl_xor_sync(0xffffffffu, p0, 1);
    p0 += __shfl_xor_sync(0xffffffffu, p0, 2);
    p1 += __shfl_xor_sync(0xffffffffu, p1, 1);
    p1 += __shfl_xor_sync(0xffffffffu, p1, 2);
    float s0 = rsqrtf(p0 * (1.0f/64.0f) + 1e-6f);
    float s1 = rsqrtf(p1 * (1.0f/64.0f) + 1e-6f);

    __nv_bfloat16* C = wn ? Ckv : Cq;
    const int r = m0 + wm * 16 + g;
    #pragma unroll
    for (int nt = 0; nt < 8; nt++) {
        int col = nt * 8 + 2 * tig;
        float w0 = nws[wn * 64 + col], w1 = nws[wn * 64 + col + 1];
        int kc = col >> 5, p = col & 31;
        uint32_t hh, ll;
        size_t b0 = ((size_t)r * 2 + kc) * 64 + p;
        split2(c[nt][0]*s0*w0, c[nt][1]*s0*w1, hh, ll);
        *(uint32_t*)&C[b0] = hh;  *(uint32_t*)&C[b0 + 32] = ll;
        size_t b1 = ((size_t)(r + 8) * 2 + kc) * 64 + p;
        split2(c[nt][2]*s1*w0, c[nt][3]*s1*w1, hh, ll);
        *(uint32_t*)&C[b1] = hh;  *(uint32_t*)&C[b1 + 32] = ll;
    }
}

// ======================================================================
// attn_tc: flash attention, bf16x3 mma.sync, ldmatrix fragments.
// 64-key sub-chunks double-buffered, sc-loop UNROLLED x2 (buffer bases
// fold to constants), running global offsets. ex2-based softmax.
// Output written split-interleaved into ys [tok][32][64].
// ======================================================================
#define ATTN_SMEM 98304

__global__ __launch_bounds__(256, 2) void attn_tc(
    const __nv_bfloat16* __restrict__ qh_g, const __nv_bfloat16* __restrict__ ql_g,
    const __nv_bfloat16* __restrict__ kh_g, const __nv_bfloat16* __restrict__ kl_g,
    const __nv_bfloat16* __restrict__ vh_g, const __nv_bfloat16* __restrict__ vl_g,
    __nv_bfloat16* __restrict__ ys)
{
    extern __shared__ char smraw[];
    const uint32_t base = smem_u32(smraw);
    const uint32_t Qh = base, Ql = base + 16384;
    const uint32_t kvb = base + 32768;

    const int tid = threadIdx.x;
    const int w = tid >> 5, lane = tid & 31;
    const int g = lane >> 2, tig = lane & 3;
    const int l8 = lane & 7, sub = lane >> 3;
    const int r0 = w * 16;
    const int bh = blockIdx.y;
    const int q0 = blockIdx.x * 128;
    const size_t hb = (size_t)bh * SEQ;

    // staging constants: 2 pieces of 256 threads for each KV tensor
    int rowp[2], chp[2];
    uint32_t sop[2];
    size_t offp[2];
    #pragma unroll
    for (int p = 0; p < 2; p++) {
        int idx = tid + p * 256;
        rowp[p] = idx >> 3; chp[p] = idx & 7;
        sop[p] = (uint32_t)rowp[p] * 128 +
                 (((uint32_t)chp[p] ^ ((uint32_t)rowp[p] & 7u)) << 4);
        offp[p] = (size_t)rowp[p] * 64 + chp[p] * 8;
    }
    const __nv_bfloat16* pkh = kh_g + hb * 64;
    const __nv_bfloat16* pkl = kl_g + hb * 64;
    const __nv_bfloat16* pvh = vh_g + hb * 64;
    const __nv_bfloat16* pvl = vl_g + hb * 64;

    // stage Q
    #pragma unroll
    for (int p = 0; p < 4; p++) {
        int idx = tid + p * 256, row = idx >> 3, ch = idx & 7;
        size_t go = (hb + q0 + row) * 64 + ch * 8;
        CPA16(lda(Qh, row, ch), qh_g + go);
        CPA16(lda(Ql, row, ch), ql_g + go);
    }
    // stage sub-chunks 0,1
    #pragma unroll
    for (int s = 0; s < 2; s++) {
        const uint32_t Kb = kvb + s * 32768;
        #pragma unroll
        for (int p = 0; p < 2; p++) {
            size_t go = (size_t)s * 4096 + offp[p];
            CPA16(Kb + sop[p],         pkh + go);
            CPA16(Kb + 8192 + sop[p],  pkl + go);
            CPA16(Kb + 16384 + sop[p], pvh + go);
            CPA16(Kb + 24576 + sop[p], pvl + go);
        }
        CPCOMMIT();
    }

    float o[8][4] = {};
    float lsum0 = 0.f, lsum1 = 0.f;
    size_t goff = 2 * 4096;

    #pragma unroll 2
    for (int sc = 0; sc < 32; sc++) {
        const int bi = sc & 1;   // folds to literal under unroll 2
        const uint32_t Kh = kvb + bi * 32768, Kl = Kh + 8192;
        const uint32_t Vh = Kh + 16384,       Vl = Kh + 24576;
        CPWAIT(1);
        __syncthreads();

        float s[8][4] = {};
        #pragma unroll
        for (int ks = 0; ks < 4; ks++) {
            int arow = r0 + l8 + ((sub & 1) << 3);
            int ach  = 2 * ks + (sub >> 1);
            uint32_t ah[4], al[4];
            LDSM4(ah, lda(Qh, arow, ach));
            LDSM4(al, lda(Ql, arow, ach));
            #pragma unroll
            for (int ntp = 0; ntp < 4; ntp++) {
                int krow = ntp * 16 + ((sub >> 1) << 3) + l8;
                int kch  = 2 * ks + (sub & 1);
                uint32_t bhf[4], blf[4];
                LDSM4(bhf, lda(Kh, krow, kch));
                LDSM4(blf, lda(Kl, krow, kch));
                MMAX3(s[2 * ntp],     ah, al, bhf[0], bhf[1], blf[0], blf[1]);
                MMAX3(s[2 * ntp + 1], ah, al, bhf[2], bhf[3], blf[2], blf[3]);
            }
        }

        #pragma unroll
        for (int ks = 0; ks < 4; ks++) {
            float e0 = ex2f(s[2*ks][0]),   e1 = ex2f(s[2*ks][1]);
            float e2 = ex2f(s[2*ks][2]),   e3 = ex2f(s[2*ks][3]);
            float e4 = ex2f(s[2*ks+1][0]), e5 = ex2f(s[2*ks+1][1]);
            float e6 = ex2f(s[2*ks+1][2]), e7 = ex2f(s[2*ks+1][3]);
            lsum0 += e0 + e1 + e4 + e5;
            lsum1 += e2 + e3 + e6 + e7;
            uint32_t ph[4], pl[4];
            split2(e0, e1, ph[0], pl[0]);
            split2(e2, e3, ph[1], pl[1]);
            split2(e4, e5, ph[2], pl[2]);
            split2(e6, e7, ph[3], pl[3]);
            #pragma unroll
            for (int ntp = 0; ntp < 4; ntp++) {
                int vrow = ks * 16 + ((sub & 1) << 3) + l8;
                int vch  = 2 * ntp + (sub >> 1);
                uint32_t vhf[4], vlf[4];
                LDSM4T(vhf, lda(Vh, vrow, vch));
                LDSM4T(vlf, lda(Vl, vrow, vch));
                MMAX3(o[2 * ntp],     ph, pl, vhf[0], vhf[1], vlf[0], vlf[1]);
                MMAX3(o[2 * ntp + 1], ph, pl, vhf[2], vhf[3], vlf[2], vlf[3]);
            }
        }

        __syncthreads();
        if (sc + 2 < 32) {
            #pragma unroll
            for (int p = 0; p < 2; p++) {
                size_t go = goff + offp[p];
                CPA16(Kh + sop[p], pkh + go);  CPA16(Kl + sop[p], pkl + go);
                CPA16(Vh + sop[p], pvh + go);  CPA16(Vl + sop[p], pvl + go);
            }
        }
        CPCOMMIT();
        goff += 4096;
    }

    lsum0 += __shfl_xor_sync(0xffffffffu, lsum0, 1);
    lsum0 += __shfl_xor_sync(0xffffffffu, lsum0, 2);
    lsum1 += __shfl_xor_sync(0xffffffffu, lsum1, 1);
    lsum1 += __shfl_xor_sync(0xffffffffu, lsum1, 2);
    float inv0 = 1.0f / lsum0, inv1 = 1.0f / lsum1;

    const int b = bh >> 4, h = bh & 15;
    const size_t tok0 = (size_t)b * SEQ + q0 + r0 + g;
    #pragma unroll
    for (int nt = 0; nt < 8; nt++) {
        int col = nt * 8 + 2 * tig;
        int kc = 2 * h + (col >> 5), p = col & 31;
        uint32_t hh, ll;
        size_t b0 = (tok0 * 32 + kc) * 64 + p;
        split2(o[nt][0] * inv0, o[nt][1] * inv0, hh, ll);
        *(uint32_t*)&ys[b0] = hh;  *(uint32_t*)&ys[b0 + 32] = ll;
        size_t b1 = ((tok0 + 8) * 32 + kc) * 64 + p;
        split2(o[nt][2] * inv1, o[nt][3] * inv1, hh, ll);
        *(uint32_t*)&ys[b1] = hh;  *(uint32_t*)&ys[b1 + 32] = ll;
    }
}

// ---------------------------------------------------------------------------
extern "C" void kernel_launch(void* const* d_in, const int* in_sizes, int n_in,
                              void* d_out, int out_size)
{
    const float* x      = (const float*)d_in[0];
    const float* w_kv_a = (const float*)d_in[1];
    const float* w_kv_b = (const float*)d_in[2];
    const float* w_q_a  = (const float*)d_in[3];
    const float* w_q_b  = (const float*)d_in[4];
    const float* w_proj = (const float*)d_in[5];
    const float* kv_nw  = (const float*)d_in[6];
    const float* q_nw   = (const float*)d_in[7];
    float* out = (float*)d_out;

    __nv_bfloat16 *xs, *wlat_s, *qlat_s, *kvlat_s, *wq_s, *wkv_s, *wproj_s, *ysv;
    __nv_bfloat16 *qh, *ql, *kh, *kl, *vh, *vl;
    cudaGetSymbolAddress((void**)&xs,      g_xs);
    cudaGetSymbolAddress((void**)&wlat_s,  g_wlat_s);
    cudaGetSymbolAddress((void**)&qlat_s,  g_qlat_s);
    cudaGetSymbolAddress((void**)&kvlat_s, g_kvlat_s);
    cudaGetSymbolAddress((void**)&wq_s,    g_wq_s);
    cudaGetSymbolAddress((void**)&wkv_s,   g_wkv_s);
    cudaGetSymbolAddress((void**)&wproj_s, g_wproj_s);
    cudaGetSymbolAddress((void**)&ysv,     g_ys);
    cudaGetSymbolAddress((void**)&qh, g_qh);  cudaGetSymbolAddress((void**)&ql, g_ql);
    cudaGetSymbolAddress((void**)&kh, g_kh);  cudaGetSymbolAddress((void**)&kl, g_kl);
    cudaGetSymbolAddress((void**)&vh, g_vh);  cudaGetSymbolAddress((void**)&vl, g_vl);

    cudaFuncSetAttribute(attn_tc, cudaFuncAttributeMaxDynamicSharedMemorySize, ATTN_SMEM);
    cudaFuncSetAttribute((gemm_bf<0, 2, 1024>),  cudaFuncAttributeMaxDynamicSharedMemorySize, GEMMBF_SMEM);
    cudaFuncSetAttribute((gemm_bf<1, 2, 2048>),  cudaFuncAttributeMaxDynamicSharedMemorySize, GEMMBF_SMEM);
    cudaFuncSetAttribute((gemm_bf<2, 32, 1024>), cudaFuncAttributeMaxDynamicSharedMemorySize, GEMMBF_SMEM);
    cudaFuncSetAttribute(gemm_latf2, cudaFuncAttributeMaxDynamicSharedMemorySize, LATF_SMEM);

    // pre-split weights and x into interleaved bf16 layout
    wsplit<<<64,   256>>>(w_q_b,  wq_s,    64,   16384);
    wsplit<<<128,  256>>>(w_kv_b, wkv_s,   64,   32768);
    wsplit<<<1024, 256>>>(w_proj, wproj_s, 1024, 262144);
    wsplit<<<64,   256>>>(w_q_a,  wlat_s,              1024, 16384);
    wsplit<<<64,   256>>>(w_kv_a, wlat_s + 64 * 2048,  1024, 16384);
    wsplit<<<8192, 256>>>(x,      xs,      1024, 2097152);

    // fused latent projections + rmsnorm -> split-interleaved latents
    gemm_latf2<<<128, 256, LATF_SMEM>>>(xs, wlat_s, q_nw, kv_nw, qlat_s, kvlat_s);

    // up-projections -> per-head split tensors
    gemm_bf<0, 2, 1024><<<dim3(8, 64),  256, GEMMBF_SMEM>>>(qlat_s,  wq_s,  nullptr, qh, ql, nullptr, nullptr);
    gemm_bf<1, 2, 2048><<<dim3(16, 64), 256, GEMMBF_SMEM>>>(kvlat_s, wkv_s, nullptr, kh, kl, vh, vl);

    // attention -> split-interleaved y
    attn_tc<<<dim3(16, 64), 256, ATTN_SMEM>>>(qh, ql, kh, kl, vh, vl, ysv);

    // output projection (fp32 out)
    gemm_bf<2, 32, 1024><<<dim3(8, 64), 256, GEMMBF_SMEM>>>(ysv, wproj_s, out, nullptr, nullptr, nullptr, nullptr);
}

// round 12
// speedup vs baseline: 1.0678x; 1.0194x over previous
#include <cuda_runtime.h>
#include <cuda_bf16.h>
#include <cstdint>

#define SEQ   2048
#define NTOK  8192

// ---------------- scratch (device globals: no runtime allocation) ----------
// interleaved split layout: [row][k/32][32 hi bf16 | 32 lo bf16]  (128B rows)
__device__ __nv_bfloat16 g_xs     [(size_t)NTOK * 2048];   // x pre-split (K=1024)
__device__ __nv_bfloat16 g_wlat_s [(size_t)128  * 2048];   // [Wq(64)|Wkv(64)] pre-split
__device__ __nv_bfloat16 g_qlat_s [(size_t)NTOK * 128];
__device__ __nv_bfloat16 g_kvlat_s[(size_t)NTOK * 128];
__device__ __nv_bfloat16 g_wq_s   [(size_t)1024 * 128];
__device__ __nv_bfloat16 g_wkv_s  [(size_t)2048 * 128];
__device__ __nv_bfloat16 g_wproj_s[(size_t)1024 * 2048];
__device__ __nv_bfloat16 g_ys     [(size_t)NTOK * 2048];
// per-head split tensors for attention [(b*16+h)][seq][64]
__device__ __nv_bfloat16 g_qh[(size_t)NTOK * 1024];
__device__ __nv_bfloat16 g_ql[(size_t)NTOK * 1024];
__device__ __nv_bfloat16 g_kh[(size_t)NTOK * 1024];
__device__ __nv_bfloat16 g_kl[(size_t)NTOK * 1024];
__device__ __nv_bfloat16 g_vh[(size_t)NTOK * 1024];
__device__ __nv_bfloat16 g_vl[(size_t)NTOK * 1024];

#define QSCALE (0.125f * 1.4426950408889634f)   // fold softmax scale * log2e

// ---------------- helpers ---------------------------------------------------
static __device__ __forceinline__ uint32_t smem_u32(const void* p) {
    uint32_t a;
    asm("{ .reg .u64 t; cvta.to.shared.u64 t, %1; cvt.u32.u64 %0, t; }"
        : "=r"(a) : "l"(p));
    return a;
}
static __device__ __forceinline__ uint32_t bfpack(float lo, float hi) {
    uint32_t r;
    asm("cvt.rn.bf16x2.f32 %0, %1, %2;" : "=r"(r) : "f"(hi), "f"(lo));
    return r;
}
static __device__ __forceinline__ void split2(float x, float y,
                                              uint32_t& h, uint32_t& l) {
    h = bfpack(x, y);
    __nv_bfloat162 hb = *reinterpret_cast<__nv_bfloat162*>(&h);
    l = bfpack(x - __bfloat162float(hb.x), y - __bfloat162float(hb.y));
}
static __device__ __forceinline__ float ex2f(float x) {
    float y; asm("ex2.approx.f32 %0, %1;" : "=f"(y) : "f"(x)); return y;
}
// swizzled smem addr: 128B rows of 8 x 16B chunks, chunk ^= row&7
static __device__ __forceinline__ uint32_t lda(uint32_t base, int row, int ch) {
    return base + row * 128 + (((uint32_t)ch ^ ((uint32_t)row & 7u)) << 4);
}

#define MMAB(c, a0, a1, a2, a3, b0, b1)                                        \
    asm volatile("mma.sync.aligned.m16n8k16.row.col.f32.bf16.bf16.f32 "        \
        "{%0,%1,%2,%3},{%4,%5,%6,%7},{%8,%9},{%0,%1,%2,%3};"                   \
        : "+f"((c)[0]), "+f"((c)[1]), "+f"((c)[2]), "+f"((c)[3])               \
        : "r"(a0), "r"(a1), "r"(a2), "r"(a3), "r"(b0), "r"(b1))

#define MMAX3(c, ah, al, bh0, bh1, bl0, bl1) do {                              \
    MMAB(c, (ah)[0], (ah)[1], (ah)[2], (ah)[3], bh0, bh1);                     \
    MMAB(c, (ah)[0], (ah)[1], (ah)[2], (ah)[3], bl0, bl1);                     \
    MMAB(c, (al)[0], (al)[1], (al)[2], (al)[3], bh0, bh1);                     \
} while (0)

#define LDSM4(r, addr)                                                         \
    asm volatile("ldmatrix.sync.aligned.m8n8.x4.shared.b16 {%0,%1,%2,%3}, [%4];" \
        : "=r"((r)[0]), "=r"((r)[1]), "=r"((r)[2]), "=r"((r)[3]) : "r"(addr))
#define LDSM4T(r, addr)                                                        \
    asm volatile("ldmatrix.sync.aligned.m8n8.x4.trans.shared.b16 {%0,%1,%2,%3}, [%4];" \
        : "=r"((r)[0]), "=r"((r)[1]), "=r"((r)[2]), "=r"((r)[3]) : "r"(addr))
#define CPA16(dst, src)                                                        \
    asm volatile("cp.async.cg.shared.global [%0], [%1], 16;" :: "r"(dst), "l"(src))
#define CPCOMMIT() asm volatile("cp.async.commit_group;" ::: "memory")
#define CPWAIT(n)  asm volatile("cp.async.wait_group %0;" :: "n"(n) : "memory")

// ======================================================================
// split core: one float4 of W[n][K] -> interleaved split layout
// ======================================================================
static __device__ __forceinline__ void split_f4(
    const float* __restrict__ W, __nv_bfloat16* __restrict__ O,
    int K, int rel)
{
    int K4 = K >> 2;
    int n = rel / K4, k4 = rel - n * K4;
    float4 v = *(const float4*)&W[(size_t)n * K + k4 * 4];
    int k = k4 * 4, kc = k >> 5, p = k & 31;
    size_t o = ((size_t)n * (K >> 5) + kc) * 64 + p;
    uint32_t h0, l0, h1, l1;
    split2(v.x, v.y, h0, l0); split2(v.z, v.w, h1, l1);
    *(uint32_t*)&O[o]      = h0;  *(uint32_t*)&O[o + 2]  = h1;
    *(uint32_t*)&O[o + 32] = l0;  *(uint32_t*)&O[o + 34] = l1;
}

// wsplit: single tensor (used for x)
__global__ __launch_bounds__(256) void wsplit(
    const float* __restrict__ W, __nv_bfloat16* __restrict__ O,
    int K, int nf4)
{
    int idx = blockIdx.x * 256 + threadIdx.x;
    if (idx < nf4) split_f4(W, O, K, idx);
}

// wsplit5: all five weight tensors in ONE launch (segment dispatch)
__global__ __launch_bounds__(256) void wsplit5(
    const float* __restrict__ wq_b,  const float* __restrict__ wkv_b,
    const float* __restrict__ w_q_a, const float* __restrict__ w_kv_a,
    const float* __restrict__ w_proj,
    __nv_bfloat16* __restrict__ owq,   __nv_bfloat16* __restrict__ owkv,
    __nv_bfloat16* __restrict__ owlat, __nv_bfloat16* __restrict__ owproj)
{
    int idx = blockIdx.x * 256 + threadIdx.x;
    if (idx < 16384)        split_f4(wq_b,   owq,              64,   idx);
    else if (idx < 49152)   split_f4(wkv_b,  owkv,             64,   idx - 16384);
    else if (idx < 65536)   split_f4(w_q_a,  owlat,            1024, idx - 49152);
    else if (idx < 81920)   split_f4(w_kv_a, owlat + 64*2048,  1024, idx - 65536);
    else if (idx < 344064)  split_f4(w_proj, owproj,           1024, idx - 81920);
}

// ======================================================================
// gemm_bf_body<MODE,KC,NN>: C = A[M,K] @ B[N,K]^T, pre-split bf16.
// 3-stage cp.async ring, ldmatrix, x3 MMA.
// MODE 0: q-up (QSCALE -> qh/ql)  MODE 1: kv-up  MODE 2: fp32 out
// ======================================================================
#define GEMMBF_SMEM 98304

template<int MODE, int KC, int NN>
static __device__ __forceinline__ void gemm_bf_body(
    const __nv_bfloat16* __restrict__ A, const __nv_bfloat16* __restrict__ B,
    float* __restrict__ Cf,
    __nv_bfloat16* __restrict__ H,  __nv_bfloat16* __restrict__ L,
    __nv_bfloat16* __restrict__ H2, __nv_bfloat16* __restrict__ L2,
    int m0, int n0, uint32_t base)
{
    const int tid = threadIdx.x;
    const int w = tid >> 5, lane = tid & 31;
    const int g = lane >> 2, tig = lane & 3;
    const int l8 = lane & 7, sub = lane >> 3;
    const int wm = w & 1, wn = w >> 1;

    int rowp[4], chp[4];
    uint32_t sop[4];
    const __nv_bfloat16 *pa[4], *pb[4];
    #pragma unroll
    for (int p = 0; p < 4; p++) {
        int idx = tid + p * 256;
        rowp[p] = idx >> 3; chp[p] = idx & 7;
        sop[p] = (uint32_t)rowp[p] * 128 +
                 (((uint32_t)chp[p] ^ ((uint32_t)rowp[p] & 7u)) << 4);
        pa[p] = A + (size_t)(m0 + rowp[p]) * KC * 64 + chp[p] * 8;
        pb[p] = B + (size_t)(n0 + rowp[p]) * KC * 64 + chp[p] * 8;
    }

    float c[4][4][4] = {};

    #pragma unroll
    for (int s = 0; s < 3; s++) {
        if (s < KC) {
            #pragma unroll
            for (int p = 0; p < 4; p++) {
                CPA16(base + s * 32768 + sop[p],         pa[p] + s * 64);
                CPA16(base + s * 32768 + 16384 + sop[p], pb[p] + s * 64);
            }
        }
        CPCOMMIT();
    }

    #pragma unroll 3
    for (int cc = 0; cc < KC; cc++) {
        const int rb = cc % 3;
        const uint32_t Ab = base + rb * 32768;
        const uint32_t Bb = Ab + 16384;
        // order-based semantics: all but the 2 newest commit groups complete
        CPWAIT(2);
        __syncthreads();

        #pragma unroll
        for (int ks = 0; ks < 2; ks++) {
            uint32_t ah[4][4], al[4][4];
            #pragma unroll
            for (int mt = 0; mt < 4; mt++) {
                int arow = wm * 64 + mt * 16 + l8 + ((sub & 1) << 3);
                int hch  = 2 * ks + (sub >> 1);
                LDSM4(ah[mt], lda(Ab, arow, hch));
                LDSM4(al[mt], lda(Ab, arow, hch + 4));
            }
            #pragma unroll
            for (int np = 0; np < 2; np++) {
                int brow = wn * 32 + np * 16 + ((sub >> 1) << 3) + l8;
                int bch  = 2 * ks + (sub & 1);
                uint32_t bhf[4], blf[4];
                LDSM4(bhf, lda(Bb, brow, bch));
                LDSM4(blf, lda(Bb, brow, bch + 4));
                #pragma unroll
                for (int mt = 0; mt < 4; mt++) {
                    MMAX3(c[mt][2*np],   ah[mt], al[mt], bhf[0], bhf[1], blf[0], blf[1]);
                    MMAX3(c[mt][2*np+1], ah[mt], al[mt], bhf[2], bhf[3], blf[2], blf[3]);
                }
            }
        }

        __syncthreads();
        if (cc + 3 < KC) {
            #pragma unroll
            for (int p = 0; p < 4; p++) {
                CPA16(Ab + sop[p], pa[p] + (cc + 3) * 64);
                CPA16(Bb + sop[p], pb[p] + (cc + 3) * 64);
            }
        }
        CPCOMMIT();
    }

    if (MODE == 2) {
        #pragma unroll
        for (int mt = 0; mt < 4; mt++)
            #pragma unroll
            for (int nt = 0; nt < 4; nt++) {
                int r0 = m0 + wm * 64 + mt * 16 + g;
                int col = n0 + wn * 32 + nt * 8 + 2 * tig;
                *(float2*)&Cf[(size_t)r0 * NN + col]       = make_float2(c[mt][nt][0], c[mt][nt][1]);
                *(float2*)&Cf[(size_t)(r0 + 8) * NN + col] = make_float2(c[mt][nt][2], c[mt][nt][3]);
            }
    } else {
        const float sc = (MODE == 0) ? QSCALE : 1.0f;
        #pragma unroll
        for (int mt = 0; mt < 4; mt++)
            #pragma unroll
            for (int nt = 0; nt < 4; nt++) {
                int tok = m0 + wm * 64 + mt * 16 + g;
                int col = n0 + wn * 32 + nt * 8 + 2 * tig;
                int b = tok >> 11, tn = tok & 2047;
                int h, d;
                __nv_bfloat16 *DH, *DL;
                if (MODE == 0) {
                    h = col >> 6; d = col & 63; DH = H; DL = L;
                } else {
                    h = col >> 7; int rr = col & 127; d = rr & 63;
                    if (rr < 64) { DH = H; DL = L; } else { DH = H2; DL = L2; }
                }
                size_t a0 = (((size_t)b * 16 + h) * SEQ + tn) * 64 + d;
                size_t a1 = a0 + 8 * 64;
                uint32_t hp, lp;
                split2(c[mt][nt][0] * sc, c[mt][nt][1] * sc, hp, lp);
                *(uint32_t*)&DH[a0] = hp;  *(uint32_t*)&DL[a0] = lp;
                split2(c[mt][nt][2] * sc, c[mt][nt][3] * sc, hp, lp);
                *(uint32_t*)&DH[a1] = hp;  *(uint32_t*)&DL[a1] = lp;
            }
    }
}

// merged q-up + kv-up: one launch, grid (24, 64)
__global__ __launch_bounds__(256, 2) void gemm_up_all(
    const __nv_bfloat16* __restrict__ qlat,  const __nv_bfloat16* __restrict__ wq,
    const __nv_bfloat16* __restrict__ kvlat, const __nv_bfloat16* __restrict__ wkv,
    __nv_bfloat16* __restrict__ qh, __nv_bfloat16* __restrict__ ql,
    __nv_bfloat16* __restrict__ kh, __nv_bfloat16* __restrict__ kl,
    __nv_bfloat16* __restrict__ vh, __nv_bfloat16* __restrict__ vl)
{
    extern __shared__ char smraw[];
    const uint32_t base = smem_u32(smraw);
    const int m0 = blockIdx.y * 128;
    if (blockIdx.x < 8)
        gemm_bf_body<0, 2, 1024>(qlat, wq, nullptr, qh, ql, nullptr, nullptr,
                                 m0, blockIdx.x * 128, base);
    else
        gemm_bf_body<1, 2, 2048>(kvlat, wkv, nullptr, kh, kl, vh, vl,
                                 m0, (blockIdx.x - 8) * 128, base);
}

// out-projection kernel
__global__ __launch_bounds__(256, 2) void gemm_out(
    const __nv_bfloat16* __restrict__ A, const __nv_bfloat16* __restrict__ B,
    float* __restrict__ Cf)
{
    extern __shared__ char smraw[];
    const uint32_t base = smem_u32(smraw);
    gemm_bf_body<2, 32, 1024>(A, B, Cf, nullptr, nullptr, nullptr, nullptr,
                              blockIdx.y * 128, blockIdx.x * 128, base);
}

// ======================================================================
// gemm_latf2: fused latent projections on PRE-SPLIT x.
// M-tile 64 tokens, N=128 = [Wq 64|Wkv 64], K=1024 -> 32 chunks of 32.
// cp.async 3-stage ring + ldmatrix, shfl rmsnorm epilogue.
// ======================================================================
#define LATF_SMEM 73728   // 3 stages x (A 8KB + B 16KB)

__global__ __launch_bounds__(256, 2) void gemm_latf2(
    const __nv_bfloat16* __restrict__ A,   // xs [8192][32][64] split
    const __nv_bfloat16* __restrict__ B,   // wlat_s [128][32][64] split
    const float* __restrict__ nwq, const float* __restrict__ nwkv,
    __nv_bfloat16* __restrict__ Cq, __nv_bfloat16* __restrict__ Ckv)
{
    extern __shared__ char smraw[];
    const uint32_t base = smem_u32(smraw);
    __shared__ float nws[128];

    const int tid = threadIdx.x;
    const int w = tid >> 5, lane = tid & 31;
    const int g = lane >> 2, tig = lane & 3;
    const int l8 = lane & 7, sub = lane >> 3;
    const int wm = w >> 1, wn = w & 1;
    const int m0 = blockIdx.x * 64;

    if (tid < 64)       nws[tid] = nwq[tid];
    else if (tid < 128) nws[tid] = nwkv[tid - 64];

    int rowA[2], chA[2], rowB[4], chB[4];
    uint32_t soA[2], soB[4];
    const __nv_bfloat16 *pA[2], *pB[4];
    #pragma unroll
    for (int p = 0; p < 2; p++) {
        int idx = tid + p * 256;
        rowA[p] = idx >> 3; chA[p] = idx & 7;
        soA[p] = (uint32_t)rowA[p] * 128 +
                 (((uint32_t)chA[p] ^ ((uint32_t)rowA[p] & 7u)) << 4);
        pA[p] = A + (size_t)(m0 + rowA[p]) * 2048 + chA[p] * 8;
    }
    #pragma unroll
    for (int p = 0; p < 4; p++) {
        int idx = tid + p * 256;
        rowB[p] = idx >> 3; chB[p] = idx & 7;
        soB[p] = (uint32_t)rowB[p] * 128 +
                 (((uint32_t)chB[p] ^ ((uint32_t)rowB[p] & 7u)) << 4);
        pB[p] = B + (size_t)rowB[p] * 2048 + chB[p] * 8;
    }

    float c[8][4] = {};

    #pragma unroll
    for (int s = 0; s < 3; s++) {
        const uint32_t Ab = base + s * 24576, Bb = Ab + 8192;
        #pragma unroll
        for (int p = 0; p < 2; p++)
            CPA16(Ab + soA[p], pA[p] + s * 64);
        #pragma unroll
        for (int p = 0; p < 4; p++)
            CPA16(Bb + soB[p], pB[p] + s * 64);
        CPCOMMIT();
    }

    #pragma unroll 3
    for (int cc = 0; cc < 32; cc++) {
        const int rb = cc % 3;
        const uint32_t Ab = base + rb * 24576, Bb = Ab + 8192;
        CPWAIT(2);
        __syncthreads();

        #pragma unroll
        for (int ks = 0; ks < 2; ks++) {
            uint32_t ah[4], al[4];
            {
                int arow = wm * 16 + l8 + ((sub & 1) << 3);
                int hch  = 2 * ks + (sub >> 1);
                LDSM4(ah, lda(Ab, arow, hch));
                LDSM4(al, lda(Ab, arow, hch + 4));
            }
            #pragma unroll
            for (int np = 0; np < 4; np++) {
                int brow = wn * 64 + np * 16 + ((sub >> 1) << 3) + l8;
                int bch  = 2 * ks + (sub & 1);
                uint32_t bhf[4], blf[4];
                LDSM4(bhf, lda(Bb, brow, bch));
                LDSM4(blf, lda(Bb, brow, bch + 4));
                MMAX3(c[2*np],   ah, al, bhf[0], bhf[1], blf[0], blf[1]);
                MMAX3(c[2*np+1], ah, al, bhf[2], bhf[3], blf[2], blf[3]);
            }
        }

        __syncthreads();
        if (cc + 3 < 32) {
            #pragma unroll
            for (int p = 0; p < 2; p++)
                CPA16(Ab + soA[p], pA[p] + (cc + 3) * 64);
            #pragma unroll
            for (int p = 0; p < 4; p++)
                CPA16(Bb + soB[p], pB[p] + (cc + 3) * 64);
        }
        CPCOMMIT();
    }

    float p0 = 0.f, p1 = 0.f;
    #pragma unroll
    for (int nt = 0; nt < 8; nt++) {
        p0 += c[nt][0]*c[nt][0] + c[nt][1]*c[nt][1];
        p1 += c[nt][2]*c[nt][2] + c[nt][3]*c[nt][3];
    }
    p0 += __shfl_xor_sync(0xffffffffu, p0, 1);
    p0 += __shfl_xor_sync(0xffffffffu, p0, 2);
    p1 += __shfl_xor_sync(0xffffffffu, p1, 1);
    p1 += __shfl_xor_sync(0xffffffffu, p1, 2);
    float s0 = rsqrtf(p0 * (1.0f/64.0f) + 1e-6f);
    float s1 = rsqrtf(p1 * (1.0f/64.0f) + 1e-6f);

    __nv_bfloat16* C = wn ? Ckv : Cq;
    const int r = m0 + wm * 16 + g;
    #pragma unroll
    for (int nt = 0; nt < 8; nt++) {
        int col = nt * 8 + 2 * tig;
        float w0 = nws[wn * 64 + col], w1 = nws[wn * 64 + col + 1];
        int kc = col >> 5, p = col & 31;
        uint32_t hh, ll;
        size_t b0 = ((size_t)r * 2 + kc) * 64 + p;
        split2(c[nt][0]*s0*w0, c[nt][1]*s0*w1, hh, ll);
        *(uint32_t*)&C[b0] = hh;  *(uint32_t*)&C[b0 + 32] = ll;
        size_t b1 = ((size_t)(r + 8) * 2 + kc) * 64 + p;
        split2(c[nt][2]*s1*w0, c[nt][3]*s1*w1, hh, ll);
        *(uint32_t*)&C[b1] = hh;  *(uint32_t*)&C[b1 + 32] = ll;
    }
}

// ======================================================================
// attn_tc: flash attention, bf16x3 mma.sync, ldmatrix fragments.
// 64-key sub-chunks double-buffered, sc-loop unrolled x2.
// ======================================================================
#define ATTN_SMEM 98304

__global__ __launch_bounds__(256, 2) void attn_tc(
    const __nv_bfloat16* __restrict__ qh_g, const __nv_bfloat16* __restrict__ ql_g,
    const __nv_bfloat16* __restrict__ kh_g, const __nv_bfloat16* __restrict__ kl_g,
    const __nv_bfloat16* __restrict__ vh_g, const __nv_bfloat16* __restrict__ vl_g,
    __nv_bfloat16* __restrict__ ys)
{
    extern __shared__ char smraw[];
    const uint32_t base = smem_u32(smraw);
    const uint32_t Qh = base, Ql = base + 16384;
    const uint32_t kvb = base + 32768;

    const int tid = threadIdx.x;
    const int w = tid >> 5, lane = tid & 31;
    const int g = lane >> 2, tig = lane & 3;
    const int l8 = lane & 7, sub = lane >> 3;
    const int r0 = w * 16;
    const int bh = blockIdx.y;
    const int q0 = blockIdx.x * 128;
    const size_t hb = (size_t)bh * SEQ;

    int rowp[2], chp[2];
    uint32_t sop[2];
    size_t offp[2];
    #pragma unroll
    for (int p = 0; p < 2; p++) {
        int idx = tid + p * 256;
        rowp[p] = idx >> 3; chp[p] = idx & 7;
        sop[p] = (uint32_t)rowp[p] * 128 +
                 (((uint32_t)chp[p] ^ ((uint32_t)rowp[p] & 7u)) << 4);
        offp[p] = (size_t)rowp[p] * 64 + chp[p] * 8;
    }
    const __nv_bfloat16* pkh = kh_g + hb * 64;
    const __nv_bfloat16* pkl = kl_g + hb * 64;
    const __nv_bfloat16* pvh = vh_g + hb * 64;
    const __nv_bfloat16* pvl = vl_g + hb * 64;

    #pragma unroll
    for (int p = 0; p < 4; p++) {
        int idx = tid + p * 256, row = idx >> 3, ch = idx & 7;
        size_t go = (hb + q0 + row) * 64 + ch * 8;
        CPA16(lda(Qh, row, ch), qh_g + go);
        CPA16(lda(Ql, row, ch), ql_g + go);
    }
    #pragma unroll
    for (int s = 0; s < 2; s++) {
        const uint32_t Kb = kvb + s * 32768;
        #pragma unroll
        for (int p = 0; p < 2; p++) {
            size_t go = (size_t)s * 4096 + offp[p];
            CPA16(Kb + sop[p],         pkh + go);
            CPA16(Kb + 8192 + sop[p],  pkl + go);
            CPA16(Kb + 16384 + sop[p], pvh + go);
            CPA16(Kb + 24576 + sop[p], pvl + go);
        }
        CPCOMMIT();
    }

    float o[8][4] = {};
    float lsum0 = 0.f, lsum1 = 0.f;
    size_t goff = 2 * 4096;

    #pragma unroll 2
    for (int sc = 0; sc < 32; sc++) {
        const int bi = sc & 1;
        const uint32_t Kh = kvb + bi * 32768, Kl = Kh + 8192;
        const uint32_t Vh = Kh + 16384,       Vl = Kh + 24576;
        CPWAIT(1);
        __syncthreads();

        float s[8][4] = {};
        #pragma unroll
        for (int ks = 0; ks < 4; ks++) {
            int arow = r0 + l8 + ((sub & 1) << 3);
            int ach  = 2 * ks + (sub >> 1);
            uint32_t ah[4], al[4];
            LDSM4(ah, lda(Qh, arow, ach));
            LDSM4(al, lda(Ql, arow, ach));
            #pragma unroll
            for (int ntp = 0; ntp < 4; ntp++) {
                int krow = ntp * 16 + ((sub >> 1) << 3) + l8;
                int kch  = 2 * ks + (sub & 1);
                uint32_t bhf[4], blf[4];
                LDSM4(bhf, lda(Kh, krow, kch));
                LDSM4(blf, lda(Kl, krow, kch));
                MMAX3(s[2 * ntp],     ah, al, bhf[0], bhf[1], blf[0], blf[1]);
                MMAX3(s[2 * ntp + 1], ah, al, bhf[2], bhf[3], blf[2], blf[3]);
            }
        }

        #pragma unroll
        for (int ks = 0; ks < 4; ks++) {
            float e0 = ex2f(s[2*ks][0]),   e1 = ex2f(s[2*ks][1]);
            float e2 = ex2f(s[2*ks][2]),   e3 = ex2f(s[2*ks][3]);
            float e4 = ex2f(s[2*ks+1][0]), e5 = ex2f(s[2*ks+1][1]);
            float e6 = ex2f(s[2*ks+1][2]), e7 = ex2f(s[2*ks+1][3]);
            lsum0 += e0 + e1 + e4 + e5;
            lsum1 += e2 + e3 + e6 + e7;
            uint32_t ph[4], pl[4];
            split2(e0, e1, ph[0], pl[0]);
            split2(e2, e3, ph[1], pl[1]);
            split2(e4, e5, ph[2], pl[2]);
            split2(e6, e7, ph[3], pl[3]);
            #pragma unroll
            for (int ntp = 0; ntp < 4; ntp++) {
                int vrow = ks * 16 + ((sub & 1) << 3) + l8;
                int vch  = 2 * ntp + (sub >> 1);
                uint32_t vhf[4], vlf[4];
                LDSM4T(vhf, lda(Vh, vrow, vch));
                LDSM4T(vlf, lda(Vl, vrow, vch));
                MMAX3(o[2 * ntp],     ph, pl, vhf[0], vhf[1], vlf[0], vlf[1]);
                MMAX3(o[2 * ntp + 1], ph, pl, vhf[2], vhf[3], vlf[2], vlf[3]);
            }
        }

        __syncthreads();
        if (sc + 2 < 32) {
            #pragma unroll
            for (int p = 0; p < 2; p++) {
                size_t go = goff + offp[p];
                CPA16(Kh + sop[p], pkh + go);  CPA16(Kl + sop[p], pkl + go);
                CPA16(Vh + sop[p], pvh + go);  CPA16(Vl + sop[p], pvl + go);
            }
        }
        CPCOMMIT();
        goff += 4096;
    }

    lsum0 += __shfl_xor_sync(0xffffffffu, lsum0, 1);
    lsum0 += __shfl_xor_sync(0xffffffffu, lsum0, 2);
    lsum1 += __shfl_xor_sync(0xffffffffu, lsum1, 1);
    lsum1 += __shfl_xor_sync(0xffffffffu, lsum1, 2);
    float inv0 = 1.0f / lsum0, inv1 = 1.0f / lsum1;

    const int b = bh >> 4, h = bh & 15;
    const size_t tok0 = (size_t)b * SEQ + q0 + r0 + g;
    #pragma unroll
    for (int nt = 0; nt < 8; nt++) {
        int col = nt * 8 + 2 * tig;
        int kc = 2 * h + (col >> 5), p = col & 31;
        uint32_t hh, ll;
        size_t b0 = (tok0 * 32 + kc) * 64 + p;
        split2(o[nt][0] * inv0, o[nt][1] * inv0, hh, ll);
        *(uint32_t*)&ys[b0] = hh;  *(uint32_t*)&ys[b0 + 32] = ll;
        size_t b1 = ((tok0 + 8) * 32 + kc) * 64 + p;
        split2(o[nt][2] * inv1, o[nt][3] * inv1, hh, ll);
        *(uint32_t*)&ys[b1] = hh;  *(uint32_t*)&ys[b1 + 32] = ll;
    }
}

// ---------------------------------------------------------------------------
extern "C" void kernel_launch(void* const* d_in, const int* in_sizes, int n_in,
                              void* d_out, int out_size)
{
    const float* x      = (const float*)d_in[0];
    const float* w_kv_a = (const float*)d_in[1];
    const float* w_kv_b = (const float*)d_in[2];
    const float* w_q_a  = (const float*)d_in[3];
    const float* w_q_b  = (const float*)d_in[4];
    const float* w_proj = (const float*)d_in[5];
    const float* kv_nw  = (const float*)d_in[6];
    const float* q_nw   = (const float*)d_in[7];
    float* out = (float*)d_out;

    __nv_bfloat16 *xs, *wlat_s, *qlat_s, *kvlat_s, *wq_s, *wkv_s, *wproj_s, *ysv;
    __nv_bfloat16 *qh, *ql, *kh, *kl, *vh, *vl;
    cudaGetSymbolAddress((void**)&xs,      g_xs);
    cudaGetSymbolAddress((void**)&wlat_s,  g_wlat_s);
    cudaGetSymbolAddress((void**)&qlat_s,  g_qlat_s);
    cudaGetSymbolAddress((void**)&kvlat_s, g_kvlat_s);
    cudaGetSymbolAddress((void**)&wq_s,    g_wq_s);
    cudaGetSymbolAddress((void**)&wkv_s,   g_wkv_s);
    cudaGetSymbolAddress((void**)&wproj_s, g_wproj_s);
    cudaGetSymbolAddress((void**)&ysv,     g_ys);
    cudaGetSymbolAddress((void**)&qh, g_qh);  cudaGetSymbolAddress((void**)&ql, g_ql);
    cudaGetSymbolAddress((void**)&kh, g_kh);  cudaGetSymbolAddress((void**)&kl, g_kl);
    cudaGetSymbolAddress((void**)&vh, g_vh);  cudaGetSymbolAddress((void**)&vl, g_vl);

    cudaFuncSetAttribute(attn_tc,     cudaFuncAttributeMaxDynamicSharedMemorySize, ATTN_SMEM);
    cudaFuncSetAttribute(gemm_up_all, cudaFuncAttributeMaxDynamicSharedMemorySize, GEMMBF_SMEM);
    cudaFuncSetAttribute(gemm_out,    cudaFuncAttributeMaxDynamicSharedMemorySize, GEMMBF_SMEM);
    cudaFuncSetAttribute(gemm_latf2,  cudaFuncAttributeMaxDynamicSharedMemorySize, LATF_SMEM);

    // pre-split: x (big, own launch) + all five weights (one launch)
    wsplit<<<8192, 256>>>(x, xs, 1024, 2097152);
    wsplit5<<<1344, 256>>>(w_q_b, w_kv_b, w_q_a, w_kv_a, w_proj,
                           wq_s, wkv_s, wlat_s, wproj_s);

    // fused latent projections + rmsnorm -> split-interleaved latents
    gemm_latf2<<<128, 256, LATF_SMEM>>>(xs, wlat_s, q_nw, kv_nw, qlat_s, kvlat_s);

    // merged up-projections -> per-head split tensors
    gemm_up_all<<<dim3(24, 64), 256, GEMMBF_SMEM>>>(qlat_s, wq_s, kvlat_s, wkv_s,
                                                    qh, ql, kh, kl, vh, vl);

    // attention -> split-interleaved y
    attn_tc<<<dim3(16, 64), 256, ATTN_SMEM>>>(qh, ql, kh, kl, vh, vl, ysv);

    // output projection (fp32 out)
    gemm_out<<<dim3(8, 64), 256, GEMMBF_SMEM>>>(ysv, wproj_s, out);
}

// round 13
// speedup vs baseline: 1.3800x; 1.2924x over previous
#include <cuda_runtime.h>
#include <cuda_bf16.h>
#include <cuda_fp16.h>
#include <cstdint>

#define SEQ   2048
#define NTOK  8192

// ---------------- scratch (device globals: no runtime allocation) ----------
// interleaved split layout: [row][k/32][32 hi bf16 | 32 lo bf16]  (128B rows)
__device__ __nv_bfloat16 g_xs     [(size_t)NTOK * 2048];   // x pre-split (K=1024)
__device__ __nv_bfloat16 g_wlat_s [(size_t)128  * 2048];   // [Wq(64)|Wkv(64)] pre-split
__device__ __nv_bfloat16 g_qlat_s [(size_t)NTOK * 128];
__device__ __nv_bfloat16 g_kvlat_s[(size_t)NTOK * 128];
__device__ __nv_bfloat16 g_wq_s   [(size_t)1024 * 128];
__device__ __nv_bfloat16 g_wkv_s  [(size_t)2048 * 128];
__device__ __nv_bfloat16 g_wproj_s[(size_t)1024 * 2048];
__device__ __nv_bfloat16 g_ys     [(size_t)NTOK * 2048];
// attention tensors, per-head layout [(b*16+h)][seq][64]
// Q: fp16 hi+lo (exact), K/V: plain fp16 (x2 split scheme)
__device__ __half g_qh[(size_t)NTOK * 1024];
__device__ __half g_ql[(size_t)NTOK * 1024];
__device__ __half g_kh[(size_t)NTOK * 1024];
__device__ __half g_vh[(size_t)NTOK * 1024];

#define QSCALE (0.125f * 1.4426950408889634f)   // fold softmax scale * log2e

// ---------------- helpers ---------------------------------------------------
static __device__ __forceinline__ uint32_t smem_u32(const void* p) {
    uint32_t a;
    asm("{ .reg .u64 t; cvta.to.shared.u64 t, %1; cvt.u32.u64 %0, t; }"
        : "=r"(a) : "l"(p));
    return a;
}
static __device__ __forceinline__ uint32_t bfpack(float lo, float hi) {
    uint32_t r;
    asm("cvt.rn.bf16x2.f32 %0, %1, %2;" : "=r"(r) : "f"(hi), "f"(lo));
    return r;
}
static __device__ __forceinline__ void split2(float x, float y,
                                              uint32_t& h, uint32_t& l) {
    h = bfpack(x, y);
    __nv_bfloat162 hb = *reinterpret_cast<__nv_bfloat162*>(&h);
    l = bfpack(x - __bfloat162float(hb.x), y - __bfloat162float(hb.y));
}
static __device__ __forceinline__ uint32_t hpack(float lo, float hi) {
    uint32_t r;
    asm("cvt.rn.f16x2.f32 %0, %1, %2;" : "=r"(r) : "f"(hi), "f"(lo));
    return r;
}
static __device__ __forceinline__ void split2h(float x, float y,
                                               uint32_t& h, uint32_t& l) {
    h = hpack(x, y);
    __half2 hb = *reinterpret_cast<__half2*>(&h);
    l = hpack(x - __half2float(hb.x), y - __half2float(hb.y));
}
static __device__ __forceinline__ float ex2f(float x) {
    float y; asm("ex2.approx.f32 %0, %1;" : "=f"(y) : "f"(x)); return y;
}
// swizzled smem addr: 128B rows of 8 x 16B chunks, chunk ^= row&7
static __device__ __forceinline__ uint32_t lda(uint32_t base, int row, int ch) {
    return base + row * 128 + (((uint32_t)ch ^ ((uint32_t)row & 7u)) << 4);
}

#define MMAB(c, a0, a1, a2, a3, b0, b1)                                        \
    asm volatile("mma.sync.aligned.m16n8k16.row.col.f32.bf16.bf16.f32 "        \
        "{%0,%1,%2,%3},{%4,%5,%6,%7},{%8,%9},{%0,%1,%2,%3};"                   \
        : "+f"((c)[0]), "+f"((c)[1]), "+f"((c)[2]), "+f"((c)[3])               \
        : "r"(a0), "r"(a1), "r"(a2), "r"(a3), "r"(b0), "r"(b1))

#define MMAF(c, a0, a1, a2, a3, b0, b1)                                        \
    asm volatile("mma.sync.aligned.m16n8k16.row.col.f32.f16.f16.f32 "          \
        "{%0,%1,%2,%3},{%4,%5,%6,%7},{%8,%9},{%0,%1,%2,%3};"                   \
        : "+f"((c)[0]), "+f"((c)[1]), "+f"((c)[2]), "+f"((c)[3])               \
        : "r"(a0), "r"(a1), "r"(a2), "r"(a3), "r"(b0), "r"(b1))

#define MMAX3(c, ah, al, bh0, bh1, bl0, bl1) do {                              \
    MMAB(c, (ah)[0], (ah)[1], (ah)[2], (ah)[3], bh0, bh1);                     \
    MMAB(c, (ah)[0], (ah)[1], (ah)[2], (ah)[3], bl0, bl1);                     \
    MMAB(c, (al)[0], (al)[1], (al)[2], (al)[3], bh0, bh1);                     \
} while (0)

// fp16 x2: A = hi+lo (exact), B = plain fp16
#define MMAX2(c, ah, al, b0, b1) do {                                          \
    MMAF(c, (ah)[0], (ah)[1], (ah)[2], (ah)[3], b0, b1);                       \
    MMAF(c, (al)[0], (al)[1], (al)[2], (al)[3], b0, b1);                       \
} while (0)

#define LDSM4(r, addr)                                                         \
    asm volatile("ldmatrix.sync.aligned.m8n8.x4.shared.b16 {%0,%1,%2,%3}, [%4];" \
        : "=r"((r)[0]), "=r"((r)[1]), "=r"((r)[2]), "=r"((r)[3]) : "r"(addr))
#define LDSM4T(r, addr)                                                        \
    asm volatile("ldmatrix.sync.aligned.m8n8.x4.trans.shared.b16 {%0,%1,%2,%3}, [%4];" \
        : "=r"((r)[0]), "=r"((r)[1]), "=r"((r)[2]), "=r"((r)[3]) : "r"(addr))
#define CPA16(dst, src)                                                        \
    asm volatile("cp.async.cg.shared.global [%0], [%1], 16;" :: "r"(dst), "l"(src))
#define CPCOMMIT() asm volatile("cp.async.commit_group;" ::: "memory")
#define CPWAIT(n)  asm volatile("cp.async.wait_group %0;" :: "n"(n) : "memory")

// ======================================================================
// split core: one float4 of W[n][K] -> interleaved split layout
// ======================================================================
static __device__ __forceinline__ void split_f4(
    const float* __restrict__ W, __nv_bfloat16* __restrict__ O,
    int K, int rel)
{
    int K4 = K >> 2;
    int n = rel / K4, k4 = rel - n * K4;
    float4 v = *(const float4*)&W[(size_t)n * K + k4 * 4];
    int k = k4 * 4, kc = k >> 5, p = k & 31;
    size_t o = ((size_t)n * (K >> 5) + kc) * 64 + p;
    uint32_t h0, l0, h1, l1;
    split2(v.x, v.y, h0, l0); split2(v.z, v.w, h1, l1);
    *(uint32_t*)&O[o]      = h0;  *(uint32_t*)&O[o + 2]  = h1;
    *(uint32_t*)&O[o + 32] = l0;  *(uint32_t*)&O[o + 34] = l1;
}

__global__ __launch_bounds__(256) void wsplit(
    const float* __restrict__ W, __nv_bfloat16* __restrict__ O,
    int K, int nf4)
{
    int idx = blockIdx.x * 256 + threadIdx.x;
    if (idx < nf4) split_f4(W, O, K, idx);
}

__global__ __launch_bounds__(256) void wsplit5(
    const float* __restrict__ wq_b,  const float* __restrict__ wkv_b,
    const float* __restrict__ w_q_a, const float* __restrict__ w_kv_a,
    const float* __restrict__ w_proj,
    __nv_bfloat16* __restrict__ owq,   __nv_bfloat16* __restrict__ owkv,
    __nv_bfloat16* __restrict__ owlat, __nv_bfloat16* __restrict__ owproj)
{
    int idx = blockIdx.x * 256 + threadIdx.x;
    if (idx < 16384)        split_f4(wq_b,   owq,              64,   idx);
    else if (idx < 49152)   split_f4(wkv_b,  owkv,             64,   idx - 16384);
    else if (idx < 65536)   split_f4(w_q_a,  owlat,            1024, idx - 49152);
    else if (idx < 81920)   split_f4(w_kv_a, owlat + 64*2048,  1024, idx - 65536);
    else if (idx < 344064)  split_f4(w_proj, owproj,           1024, idx - 81920);
}

// ======================================================================
// gemm_bf_body<MODE,KC,NN>: C = A[M,K] @ B[N,K]^T, pre-split bf16 in.
// 3-stage cp.async ring, ldmatrix, x3 MMA.
// MODE 0: q-up -> fp16 hi/lo (QSCALE)  MODE 1: kv-up -> fp16 k/v (plain)
// MODE 2: fp32 out
// ======================================================================
#define GEMMBF_SMEM 98304

template<int MODE, int KC, int NN>
static __device__ __forceinline__ void gemm_bf_body(
    const __nv_bfloat16* __restrict__ A, const __nv_bfloat16* __restrict__ B,
    float* __restrict__ Cf,
    __half* __restrict__ H, __half* __restrict__ L, __half* __restrict__ H2,
    int m0, int n0, uint32_t base)
{
    const int tid = threadIdx.x;
    const int w = tid >> 5, lane = tid & 31;
    const int g = lane >> 2, tig = lane & 3;
    const int l8 = lane & 7, sub = lane >> 3;
    const int wm = w & 1, wn = w >> 1;

    int rowp[4], chp[4];
    uint32_t sop[4];
    const __nv_bfloat16 *pa[4], *pb[4];
    #pragma unroll
    for (int p = 0; p < 4; p++) {
        int idx = tid + p * 256;
        rowp[p] = idx >> 3; chp[p] = idx & 7;
        sop[p] = (uint32_t)rowp[p] * 128 +
                 (((uint32_t)chp[p] ^ ((uint32_t)rowp[p] & 7u)) << 4);
        pa[p] = A + (size_t)(m0 + rowp[p]) * KC * 64 + chp[p] * 8;
        pb[p] = B + (size_t)(n0 + rowp[p]) * KC * 64 + chp[p] * 8;
    }

    float c[4][4][4] = {};

    #pragma unroll
    for (int s = 0; s < 3; s++) {
        if (s < KC) {
            #pragma unroll
            for (int p = 0; p < 4; p++) {
                CPA16(base + s * 32768 + sop[p],         pa[p] + s * 64);
                CPA16(base + s * 32768 + 16384 + sop[p], pb[p] + s * 64);
            }
        }
        CPCOMMIT();
    }

    #pragma unroll 3
    for (int cc = 0; cc < KC; cc++) {
        const int rb = cc % 3;
        const uint32_t Ab = base + rb * 32768;
        const uint32_t Bb = Ab + 16384;
        CPWAIT(2);
        __syncthreads();

        #pragma unroll
        for (int ks = 0; ks < 2; ks++) {
            uint32_t ah[4][4], al[4][4];
            #pragma unroll
            for (int mt = 0; mt < 4; mt++) {
                int arow = wm * 64 + mt * 16 + l8 + ((sub & 1) << 3);
                int hch  = 2 * ks + (sub >> 1);
                LDSM4(ah[mt], lda(Ab, arow, hch));
                LDSM4(al[mt], lda(Ab, arow, hch + 4));
            }
            #pragma unroll
            for (int np = 0; np < 2; np++) {
                int brow = wn * 32 + np * 16 + ((sub >> 1) << 3) + l8;
                int bch  = 2 * ks + (sub & 1);
                uint32_t bhf[4], blf[4];
                LDSM4(bhf, lda(Bb, brow, bch));
                LDSM4(blf, lda(Bb, brow, bch + 4));
                #pragma unroll
                for (int mt = 0; mt < 4; mt++) {
                    MMAX3(c[mt][2*np],   ah[mt], al[mt], bhf[0], bhf[1], blf[0], blf[1]);
                    MMAX3(c[mt][2*np+1], ah[mt], al[mt], bhf[2], bhf[3], blf[2], blf[3]);
                }
            }
        }

        __syncthreads();
        if (cc + 3 < KC) {
            #pragma unroll
            for (int p = 0; p < 4; p++) {
                CPA16(Ab + sop[p], pa[p] + (cc + 3) * 64);
                CPA16(Bb + sop[p], pb[p] + (cc + 3) * 64);
            }
        }
        CPCOMMIT();
    }

    if (MODE == 2) {
        #pragma unroll
        for (int mt = 0; mt < 4; mt++)
            #pragma unroll
            for (int nt = 0; nt < 4; nt++) {
                int r0 = m0 + wm * 64 + mt * 16 + g;
                int col = n0 + wn * 32 + nt * 8 + 2 * tig;
                *(float2*)&Cf[(size_t)r0 * NN + col]       = make_float2(c[mt][nt][0], c[mt][nt][1]);
                *(float2*)&Cf[(size_t)(r0 + 8) * NN + col] = make_float2(c[mt][nt][2], c[mt][nt][3]);
            }
    } else if (MODE == 0) {
        #pragma unroll
        for (int mt = 0; mt < 4; mt++)
            #pragma unroll
            for (int nt = 0; nt < 4; nt++) {
                int tok = m0 + wm * 64 + mt * 16 + g;
                int col = n0 + wn * 32 + nt * 8 + 2 * tig;
                int b = tok >> 11, tn = tok & 2047;
                int h = col >> 6, d = col & 63;
                size_t a0 = (((size_t)b * 16 + h) * SEQ + tn) * 64 + d;
                size_t a1 = a0 + 8 * 64;
                uint32_t hp, lp;
                split2h(c[mt][nt][0] * QSCALE, c[mt][nt][1] * QSCALE, hp, lp);
                *(uint32_t*)&H[a0] = hp;  *(uint32_t*)&L[a0] = lp;
                split2h(c[mt][nt][2] * QSCALE, c[mt][nt][3] * QSCALE, hp, lp);
                *(uint32_t*)&H[a1] = hp;  *(uint32_t*)&L[a1] = lp;
            }
    } else {
        #pragma unroll
        for (int mt = 0; mt < 4; mt++)
            #pragma unroll
            for (int nt = 0; nt < 4; nt++) {
                int tok = m0 + wm * 64 + mt * 16 + g;
                int col = n0 + wn * 32 + nt * 8 + 2 * tig;
                int b = tok >> 11, tn = tok & 2047;
                int h = col >> 7, rr = col & 127, d = rr & 63;
                __half* D = (rr < 64) ? H : H2;   // k or v
                size_t a0 = (((size_t)b * 16 + h) * SEQ + tn) * 64 + d;
                size_t a1 = a0 + 8 * 64;
                *(uint32_t*)&D[a0] = hpack(c[mt][nt][0], c[mt][nt][1]);
                *(uint32_t*)&D[a1] = hpack(c[mt][nt][2], c[mt][nt][3]);
            }
    }
}

// merged q-up + kv-up: one launch, grid (24, 64)
__global__ __launch_bounds__(256, 2) void gemm_up_all(
    const __nv_bfloat16* __restrict__ qlat,  const __nv_bfloat16* __restrict__ wq,
    const __nv_bfloat16* __restrict__ kvlat, const __nv_bfloat16* __restrict__ wkv,
    __half* __restrict__ qh, __half* __restrict__ ql,
    __half* __restrict__ kh, __half* __restrict__ vh)
{
    extern __shared__ char smraw[];
    const uint32_t base = smem_u32(smraw);
    const int m0 = blockIdx.y * 128;
    if (blockIdx.x < 8)
        gemm_bf_body<0, 2, 1024>(qlat, wq, nullptr, qh, ql, nullptr,
                                 m0, blockIdx.x * 128, base);
    else
        gemm_bf_body<1, 2, 2048>(kvlat, wkv, nullptr, kh, nullptr, vh,
                                 m0, (blockIdx.x - 8) * 128, base);
}

__global__ __launch_bounds__(256, 2) void gemm_out(
    const __nv_bfloat16* __restrict__ A, const __nv_bfloat16* __restrict__ B,
    float* __restrict__ Cf)
{
    extern __shared__ char smraw[];
    const uint32_t base = smem_u32(smraw);
    gemm_bf_body<2, 32, 1024>(A, B, Cf, nullptr, nullptr, nullptr,
                              blockIdx.y * 128, blockIdx.x * 128, base);
}

// ======================================================================
// gemm_latf2: fused latent projections on PRE-SPLIT x. (unchanged)
// ======================================================================
#define LATF_SMEM 73728

__global__ __launch_bounds__(256, 2) void gemm_latf2(
    const __nv_bfloat16* __restrict__ A,
    const __nv_bfloat16* __restrict__ B,
    const float* __restrict__ nwq, const float* __restrict__ nwkv,
    __nv_bfloat16* __restrict__ Cq, __nv_bfloat16* __restrict__ Ckv)
{
    extern __shared__ char smraw[];
    const uint32_t base = smem_u32(smraw);
    __shared__ float nws[128];

    const int tid = threadIdx.x;
    const int w = tid >> 5, lane = tid & 31;
    const int g = lane >> 2, tig = lane & 3;
    const int l8 = lane & 7, sub = lane >> 3;
    const int wm = w >> 1, wn = w & 1;
    const int m0 = blockIdx.x * 64;

    if (tid < 64)       nws[tid] = nwq[tid];
    else if (tid < 128) nws[tid] = nwkv[tid - 64];

    int rowA[2], chA[2], rowB[4], chB[4];
    uint32_t soA[2], soB[4];
    const __nv_bfloat16 *pA[2], *pB[4];
    #pragma unroll
    for (int p = 0; p < 2; p++) {
        int idx = tid + p * 256;
        rowA[p] = idx >> 3; chA[p] = idx & 7;
        soA[p] = (uint32_t)rowA[p] * 128 +
                 (((uint32_t)chA[p] ^ ((uint32_t)rowA[p] & 7u)) << 4);
        pA[p] = A + (size_t)(m0 + rowA[p]) * 2048 + chA[p] * 8;
    }
    #pragma unroll
    for (int p = 0; p < 4; p++) {
        int idx = tid + p * 256;
        rowB[p] = idx >> 3; chB[p] = idx & 7;
        soB[p] = (uint32_t)rowB[p] * 128 +
                 (((uint32_t)chB[p] ^ ((uint32_t)rowB[p] & 7u)) << 4);
        pB[p] = B + (size_t)rowB[p] * 2048 + chB[p] * 8;
    }

    float c[8][4] = {};

    #pragma unroll
    for (int s = 0; s < 3; s++) {
        const uint32_t Ab = base + s * 24576, Bb = Ab + 8192;
        #pragma unroll
        for (int p = 0; p < 2; p++)
            CPA16(Ab + soA[p], pA[p] + s * 64);
        #pragma unroll
        for (int p = 0; p < 4; p++)
            CPA16(Bb + soB[p], pB[p] + s * 64);
        CPCOMMIT();
    }

    #pragma unroll 3
    for (int cc = 0; cc < 32; cc++) {
        const int rb = cc % 3;
        const uint32_t Ab = base + rb * 24576, Bb = Ab + 8192;
        CPWAIT(2);
        __syncthreads();

        #pragma unroll
        for (int ks = 0; ks < 2; ks++) {
            uint32_t ah[4], al[4];
            {
                int arow = wm * 16 + l8 + ((sub & 1) << 3);
                int hch  = 2 * ks + (sub >> 1);
                LDSM4(ah, lda(Ab, arow, hch));
                LDSM4(al, lda(Ab, arow, hch + 4));
            }
            #pragma unroll
            for (int np = 0; np < 4; np++) {
                int brow = wn * 64 + np * 16 + ((sub >> 1) << 3) + l8;
                int bch  = 2 * ks + (sub & 1);
                uint32_t bhf[4], blf[4];
                LDSM4(bhf, lda(Bb, brow, bch));
                LDSM4(blf, lda(Bb, brow, bch + 4));
                MMAX3(c[2*np],   ah, al, bhf[0], bhf[1], blf[0], blf[1]);
                MMAX3(c[2*np+1], ah, al, bhf[2], bhf[3], blf[2], blf[3]);
            }
        }

        __syncthreads();
        if (cc + 3 < 32) {
            #pragma unroll
            for (int p = 0; p < 2; p++)
                CPA16(Ab + soA[p], pA[p] + (cc + 3) * 64);
            #pragma unroll
            for (int p = 0; p < 4; p++)
                CPA16(Bb + soB[p], pB[p] + (cc + 3) * 64);
        }
        CPCOMMIT();
    }

    float p0 = 0.f, p1 = 0.f;
    #pragma unroll
    for (int nt = 0; nt < 8; nt++) {
        p0 += c[nt][0]*c[nt][0] + c[nt][1]*c[nt][1];
        p1 += c[nt][2]*c[nt][2] + c[nt][3]*c[nt][3];
    }
    p0 += __shfl_xor_sync(0xffffffffu, p0, 1);
    p0 += __shfl_xor_sync(0xffffffffu, p0, 2);
    p1 += __shfl_xor_sync(0xffffffffu, p1, 1);
    p1 += __shfl_xor_sync(0xffffffffu, p1, 2);
    float s0 = rsqrtf(p0 * (1.0f/64.0f) + 1e-6f);
    float s1 = rsqrtf(p1 * (1.0f/64.0f) + 1e-6f);

    __nv_bfloat16* C = wn ? Ckv : Cq;
    const int r = m0 + wm * 16 + g;
    #pragma unroll
    for (int nt = 0; nt < 8; nt++) {
        int col = nt * 8 + 2 * tig;
        float w0 = nws[wn * 64 + col], w1 = nws[wn * 64 + col + 1];
        int kc = col >> 5, p = col & 31;
        uint32_t hh, ll;
        size_t b0 = ((size_t)r * 2 + kc) * 64 + p;
        split2(c[nt][0]*s0*w0, c[nt][1]*s0*w1, hh, ll);
        *(uint32_t*)&C[b0] = hh;  *(uint32_t*)&C[b0 + 32] = ll;
        size_t b1 = ((size_t)(r + 8) * 2 + kc) * 64 + p;
        split2(c[nt][2]*s1*w0, c[nt][3]*s1*w1, hh, ll);
        *(uint32_t*)&C[b1] = hh;  *(uint32_t*)&C[b1 + 32] = ll;
    }
}

// ======================================================================
// attn_tc: flash attention, fp16 x2 mma.sync.
// Q = fp16 hi+lo (exact), K/V = plain fp16. 64-key sub-chunks double-
// buffered (Kh 8KB + Vh 8KB per buffer). 64KB smem, 2 CTAs/SM.
// Output ys stays bf16 hi/lo split for the x3 out-projection.
// ======================================================================
#define ATTN_SMEM 65536

__global__ __launch_bounds__(256, 2) void attn_tc(
    const __half* __restrict__ qh_g, const __half* __restrict__ ql_g,
    const __half* __restrict__ kh_g, const __half* __restrict__ vh_g,
    __nv_bfloat16* __restrict__ ys)
{
    extern __shared__ char smraw[];
    const uint32_t base = smem_u32(smraw);
    const uint32_t Qh = base, Ql = base + 16384;
    const uint32_t kvb = base + 32768;   // buf bi: Kh at +bi*16384, Vh at +8192

    const int tid = threadIdx.x;
    const int w = tid >> 5, lane = tid & 31;
    const int g = lane >> 2, tig = lane & 3;
    const int l8 = lane & 7, sub = lane >> 3;
    const int r0 = w * 16;
    const int bh = blockIdx.y;
    const int q0 = blockIdx.x * 128;
    const size_t hb = (size_t)bh * SEQ;

    int rowp[2], chp[2];
    uint32_t sop[2];
    size_t offp[2];
    #pragma unroll
    for (int p = 0; p < 2; p++) {
        int idx = tid + p * 256;
        rowp[p] = idx >> 3; chp[p] = idx & 7;
        sop[p] = (uint32_t)rowp[p] * 128 +
                 (((uint32_t)chp[p] ^ ((uint32_t)rowp[p] & 7u)) << 4);
        offp[p] = (size_t)rowp[p] * 64 + chp[p] * 8;
    }
    const __half* pkh = kh_g + hb * 64;
    const __half* pvh = vh_g + hb * 64;

    // stage Q (hi + lo)
    #pragma unroll
    for (int p = 0; p < 4; p++) {
        int idx = tid + p * 256, row = idx >> 3, ch = idx & 7;
        size_t go = (hb + q0 + row) * 64 + ch * 8;
        CPA16(lda(Qh, row, ch), qh_g + go);
        CPA16(lda(Ql, row, ch), ql_g + go);
    }
    // stage sub-chunks 0,1
    #pragma unroll
    for (int s = 0; s < 2; s++) {
        const uint32_t Kb = kvb + s * 16384;
        #pragma unroll
        for (int p = 0; p < 2; p++) {
            size_t go = (size_t)s * 4096 + offp[p];
            CPA16(Kb + sop[p],        pkh + go);
            CPA16(Kb + 8192 + sop[p], pvh + go);
        }
        CPCOMMIT();
    }

    float o[8][4] = {};
    float lsum0 = 0.f, lsum1 = 0.f;
    size_t goff = 2 * 4096;

    #pragma unroll 2
    for (int sc = 0; sc < 32; sc++) {
        const int bi = sc & 1;
        const uint32_t Kh = kvb + bi * 16384, Vh = Kh + 8192;
        CPWAIT(1);
        __syncthreads();

        // S = (Qh + Ql) @ Kh^T
        float s[8][4] = {};
        #pragma unroll
        for (int ks = 0; ks < 4; ks++) {
            int arow = r0 + l8 + ((sub & 1) << 3);
            int ach  = 2 * ks + (sub >> 1);
            uint32_t ah[4], al[4];
            LDSM4(ah, lda(Qh, arow, ach));
            LDSM4(al, lda(Ql, arow, ach));
            #pragma unroll
            for (int ntp = 0; ntp < 4; ntp++) {
                int krow = ntp * 16 + ((sub >> 1) << 3) + l8;
                int kch  = 2 * ks + (sub & 1);
                uint32_t bhf[4];
                LDSM4(bhf, lda(Kh, krow, kch));
                MMAX2(s[2 * ntp],     ah, al, bhf[0], bhf[1]);
                MMAX2(s[2 * ntp + 1], ah, al, bhf[2], bhf[3]);
            }
        }

        // p = ex2(s) (fp16 hi+lo); O += (Ph + Pl) @ Vh
        #pragma unroll
        for (int ks = 0; ks < 4; ks++) {
            float e0 = ex2f(s[2*ks][0]),   e1 = ex2f(s[2*ks][1]);
            float e2 = ex2f(s[2*ks][2]),   e3 = ex2f(s[2*ks][3]);
            float e4 = ex2f(s[2*ks+1][0]), e5 = ex2f(s[2*ks+1][1]);
            float e6 = ex2f(s[2*ks+1][2]), e7 = ex2f(s[2*ks+1][3]);
            lsum0 += e0 + e1 + e4 + e5;
            lsum1 += e2 + e3 + e6 + e7;
            uint32_t ph[4], pl[4];
            split2h(e0, e1, ph[0], pl[0]);
            split2h(e2, e3, ph[1], pl[1]);
            split2h(e4, e5, ph[2], pl[2]);
            split2h(e6, e7, ph[3], pl[3]);
            #pragma unroll
            for (int ntp = 0; ntp < 4; ntp++) {
                int vrow = ks * 16 + ((sub & 1) << 3) + l8;
                int vch  = 2 * ntp + (sub >> 1);
                uint32_t vhf[4];
                LDSM4T(vhf, lda(Vh, vrow, vch));
                MMAX2(o[2 * ntp],     ph, pl, vhf[0], vhf[1]);
                MMAX2(o[2 * ntp + 1], ph, pl, vhf[2], vhf[3]);
            }
        }

        __syncthreads();
        if (sc + 2 < 32) {
            #pragma unroll
            for (int p = 0; p < 2; p++) {
                size_t go = goff + offp[p];
                CPA16(Kh + sop[p],        pkh + go);
                CPA16(Kh + 8192 + sop[p], pvh + go);
            }
        }
        CPCOMMIT();
        goff += 4096;
    }

    lsum0 += __shfl_xor_sync(0xffffffffu, lsum0, 1);
    lsum0 += __shfl_xor_sync(0xffffffffu, lsum0, 2);
    lsum1 += __shfl_xor_sync(0xffffffffu, lsum1, 1);
    lsum1 += __shfl_xor_sync(0xffffffffu, lsum1, 2);
    float inv0 = 1.0f / lsum0, inv1 = 1.0f / lsum1;

    const int b = bh >> 4, h = bh & 15;
    const size_t tok0 = (size_t)b * SEQ + q0 + r0 + g;
    #pragma unroll
    for (int nt = 0; nt < 8; nt++) {
        int col = nt * 8 + 2 * tig;
        int kc = 2 * h + (col >> 5), p = col & 31;
        uint32_t hh, ll;
        size_t b0 = (tok0 * 32 + kc) * 64 + p;
        split2(o[nt][0] * inv0, o[nt][1] * inv0, hh, ll);
        *(uint32_t*)&ys[b0] = hh;  *(uint32_t*)&ys[b0 + 32] = ll;
        size_t b1 = ((tok0 + 8) * 32 + kc) * 64 + p;
        split2(o[nt][2] * inv1, o[nt][3] * inv1, hh, ll);
        *(uint32_t*)&ys[b1] = hh;  *(uint32_t*)&ys[b1 + 32] = ll;
    }
}

// ---------------------------------------------------------------------------
extern "C" void kernel_launch(void* const* d_in, const int* in_sizes, int n_in,
                              void* d_out, int out_size)
{
    const float* x      = (const float*)d_in[0];
    const float* w_kv_a = (const float*)d_in[1];
    const float* w_kv_b = (const float*)d_in[2];
    const float* w_q_a  = (const float*)d_in[3];
    const float* w_q_b  = (const float*)d_in[4];
    const float* w_proj = (const float*)d_in[5];
    const float* kv_nw  = (const float*)d_in[6];
    const float* q_nw   = (const float*)d_in[7];
    float* out = (float*)d_out;

    __nv_bfloat16 *xs, *wlat_s, *qlat_s, *kvlat_s, *wq_s, *wkv_s, *wproj_s, *ysv;
    __half *qh, *ql, *kh, *vh;
    cudaGetSymbolAddress((void**)&xs,      g_xs);
    cudaGetSymbolAddress((void**)&wlat_s,  g_wlat_s);
    cudaGetSymbolAddress((void**)&qlat_s,  g_qlat_s);
    cudaGetSymbolAddress((void**)&kvlat_s, g_kvlat_s);
    cudaGetSymbolAddress((void**)&wq_s,    g_wq_s);
    cudaGetSymbolAddress((void**)&wkv_s,   g_wkv_s);
    cudaGetSymbolAddress((void**)&wproj_s, g_wproj_s);
    cudaGetSymbolAddress((void**)&ysv,     g_ys);
    cudaGetSymbolAddress((void**)&qh, g_qh);  cudaGetSymbolAddress((void**)&ql, g_ql);
    cudaGetSymbolAddress((void**)&kh, g_kh);  cudaGetSymbolAddress((void**)&vh, g_vh);

    cudaFuncSetAttribute(attn_tc,     cudaFuncAttributeMaxDynamicSharedMemorySize, ATTN_SMEM);
    cudaFuncSetAttribute(gemm_up_all, cudaFuncAttributeMaxDynamicSharedMemorySize, GEMMBF_SMEM);
    cudaFuncSetAttribute(gemm_out,    cudaFuncAttributeMaxDynamicSharedMemorySize, GEMMBF_SMEM);
    cudaFuncSetAttribute(gemm_latf2,  cudaFuncAttributeMaxDynamicSharedMemorySize, LATF_SMEM);

    // pre-split: x (big, own launch) + all five weights (one launch)
    wsplit<<<8192, 256>>>(x, xs, 1024, 2097152);
    wsplit5<<<1344, 256>>>(w_q_b, w_kv_b, w_q_a, w_kv_a, w_proj,
                           wq_s, wkv_s, wlat_s, wproj_s);

    // fused latent projections + rmsnorm -> split-interleaved latents
    gemm_latf2<<<128, 256, LATF_SMEM>>>(xs, wlat_s, q_nw, kv_nw, qlat_s, kvlat_s);

    // merged up-projections -> fp16 attention tensors
    gemm_up_all<<<dim3(24, 64), 256, GEMMBF_SMEM>>>(qlat_s, wq_s, kvlat_s, wkv_s,
                                                    qh, ql, kh, vh);

    // attention (fp16 x2) -> split-interleaved y (bf16)
    attn_tc<<<dim3(16, 64), 256, ATTN_SMEM>>>(qh, ql, kh, vh, ysv);

    // output projection (bf16 x3, fp32 out)
    gemm_out<<<dim3(8, 64), 256, GEMMBF_SMEM>>>(ysv, wproj_s, out);
}

// round 14
// speedup vs baseline: 1.4701x; 1.0653x over previous
#include <cuda_runtime.h>
#include <cuda_bf16.h>
#include <cuda_fp16.h>
#include <cstdint>

#define SEQ   2048
#define NTOK  8192

// ---------------- scratch (device globals: no runtime allocation) ----------
// interleaved split layout: [row][k/32][32 hi | 32 lo]  (128B rows)
__device__ __nv_bfloat16 g_xs     [(size_t)NTOK * 2048];   // x pre-split bf16 (K=1024)
__device__ __nv_bfloat16 g_wlat_s [(size_t)128  * 2048];   // [Wq(64)|Wkv(64)] pre-split
__device__ __nv_bfloat16 g_qlat_s [(size_t)NTOK * 128];
__device__ __nv_bfloat16 g_kvlat_s[(size_t)NTOK * 128];
__device__ __nv_bfloat16 g_wq_s   [(size_t)1024 * 128];
__device__ __nv_bfloat16 g_wkv_s  [(size_t)2048 * 128];
__device__ __half        g_wproj_h[(size_t)1024 * 1024];   // plain fp16 [n][k]
__device__ __half        g_ysh    [(size_t)NTOK * 2048];   // y fp16 hi/lo split
// attention tensors, per-head layout [(b*16+h)][seq][64]
__device__ __half g_qh[(size_t)NTOK * 1024];
__device__ __half g_ql[(size_t)NTOK * 1024];
__device__ __half g_kh[(size_t)NTOK * 1024];
__device__ __half g_vh[(size_t)NTOK * 1024];

#define QSCALE (0.125f * 1.4426950408889634f)   // fold softmax scale * log2e

// ---------------- helpers ---------------------------------------------------
static __device__ __forceinline__ uint32_t smem_u32(const void* p) {
    uint32_t a;
    asm("{ .reg .u64 t; cvta.to.shared.u64 t, %1; cvt.u32.u64 %0, t; }"
        : "=r"(a) : "l"(p));
    return a;
}
static __device__ __forceinline__ uint32_t bfpack(float lo, float hi) {
    uint32_t r;
    asm("cvt.rn.bf16x2.f32 %0, %1, %2;" : "=r"(r) : "f"(hi), "f"(lo));
    return r;
}
static __device__ __forceinline__ void split2(float x, float y,
                                              uint32_t& h, uint32_t& l) {
    h = bfpack(x, y);
    __nv_bfloat162 hb = *reinterpret_cast<__nv_bfloat162*>(&h);
    l = bfpack(x - __bfloat162float(hb.x), y - __bfloat162float(hb.y));
}
static __device__ __forceinline__ uint32_t hpack(float lo, float hi) {
    uint32_t r;
    asm("cvt.rn.f16x2.f32 %0, %1, %2;" : "=r"(r) : "f"(hi), "f"(lo));
    return r;
}
static __device__ __forceinline__ void split2h(float x, float y,
                                               uint32_t& h, uint32_t& l) {
    h = hpack(x, y);
    __half2 hb = *reinterpret_cast<__half2*>(&h);
    l = hpack(x - __half2float(hb.x), y - __half2float(hb.y));
}
static __device__ __forceinline__ float ex2f(float x) {
    float y; asm("ex2.approx.f32 %0, %1;" : "=f"(y) : "f"(x)); return y;
}
// swizzled smem addr: 128B rows of 8 x 16B chunks, chunk ^= row&7
static __device__ __forceinline__ uint32_t lda(uint32_t base, int row, int ch) {
    return base + row * 128 + (((uint32_t)ch ^ ((uint32_t)row & 7u)) << 4);
}
// paired-row layout for 64B rows: 2 rows per 128B line, conflict-free swizzle
static __device__ __forceinline__ uint32_t ldb(uint32_t base, int row, int ch) {
    return base + (uint32_t)(row >> 1) * 128 +
           (((((uint32_t)row & 1u) << 2 | (uint32_t)ch) ^ (((uint32_t)row >> 1) & 7u)) << 4);
}

#define MMAB(c, a0, a1, a2, a3, b0, b1)                                        \
    asm volatile("mma.sync.aligned.m16n8k16.row.col.f32.bf16.bf16.f32 "        \
        "{%0,%1,%2,%3},{%4,%5,%6,%7},{%8,%9},{%0,%1,%2,%3};"                   \
        : "+f"((c)[0]), "+f"((c)[1]), "+f"((c)[2]), "+f"((c)[3])               \
        : "r"(a0), "r"(a1), "r"(a2), "r"(a3), "r"(b0), "r"(b1))

#define MMAF(c, a0, a1, a2, a3, b0, b1)                                        \
    asm volatile("mma.sync.aligned.m16n8k16.row.col.f32.f16.f16.f32 "          \
        "{%0,%1,%2,%3},{%4,%5,%6,%7},{%8,%9},{%0,%1,%2,%3};"                   \
        : "+f"((c)[0]), "+f"((c)[1]), "+f"((c)[2]), "+f"((c)[3])               \
        : "r"(a0), "r"(a1), "r"(a2), "r"(a3), "r"(b0), "r"(b1))

#define MMAX3(c, ah, al, bh0, bh1, bl0, bl1) do {                              \
    MMAB(c, (ah)[0], (ah)[1], (ah)[2], (ah)[3], bh0, bh1);                     \
    MMAB(c, (ah)[0], (ah)[1], (ah)[2], (ah)[3], bl0, bl1);                     \
    MMAB(c, (al)[0], (al)[1], (al)[2], (al)[3], bh0, bh1);                     \
} while (0)

// fp16 x2: A = hi+lo (exact), B = plain fp16
#define MMAX2(c, ah, al, b0, b1) do {                                          \
    MMAF(c, (ah)[0], (ah)[1], (ah)[2], (ah)[3], b0, b1);                       \
    MMAF(c, (al)[0], (al)[1], (al)[2], (al)[3], b0, b1);                       \
} while (0)

#define LDSM4(r, addr)                                                         \
    asm volatile("ldmatrix.sync.aligned.m8n8.x4.shared.b16 {%0,%1,%2,%3}, [%4];" \
        : "=r"((r)[0]), "=r"((r)[1]), "=r"((r)[2]), "=r"((r)[3]) : "r"(addr))
#define LDSM4T(r, addr)                                                        \
    asm volatile("ldmatrix.sync.aligned.m8n8.x4.trans.shared.b16 {%0,%1,%2,%3}, [%4];" \
        : "=r"((r)[0]), "=r"((r)[1]), "=r"((r)[2]), "=r"((r)[3]) : "r"(addr))
#define CPA16(dst, src)                                                        \
    asm volatile("cp.async.cg.shared.global [%0], [%1], 16;" :: "r"(dst), "l"(src))
#define CPCOMMIT() asm volatile("cp.async.commit_group;" ::: "memory")
#define CPWAIT(n)  asm volatile("cp.async.wait_group %0;" :: "n"(n) : "memory")

// ======================================================================
// split cores
// ======================================================================
static __device__ __forceinline__ void split_f4(
    const float* __restrict__ W, __nv_bfloat16* __restrict__ O,
    int K, int rel)
{
    int K4 = K >> 2;
    int n = rel / K4, k4 = rel - n * K4;
    float4 v = *(const float4*)&W[(size_t)n * K + k4 * 4];
    int k = k4 * 4, kc = k >> 5, p = k & 31;
    size_t o = ((size_t)n * (K >> 5) + kc) * 64 + p;
    uint32_t h0, l0, h1, l1;
    split2(v.x, v.y, h0, l0); split2(v.z, v.w, h1, l1);
    *(uint32_t*)&O[o]      = h0;  *(uint32_t*)&O[o + 2]  = h1;
    *(uint32_t*)&O[o + 32] = l0;  *(uint32_t*)&O[o + 34] = l1;
}

__global__ __launch_bounds__(256) void wsplit(
    const float* __restrict__ W, __nv_bfloat16* __restrict__ O,
    int K, int nf4)
{
    int idx = blockIdx.x * 256 + threadIdx.x;
    if (idx < nf4) split_f4(W, O, K, idx);
}

// wsplit5: four bf16-split weights + w_proj plain fp16, one launch
__global__ __launch_bounds__(256) void wsplit5(
    const float* __restrict__ wq_b,  const float* __restrict__ wkv_b,
    const float* __restrict__ w_q_a, const float* __restrict__ w_kv_a,
    const float* __restrict__ w_proj,
    __nv_bfloat16* __restrict__ owq,   __nv_bfloat16* __restrict__ owkv,
    __nv_bfloat16* __restrict__ owlat, __half* __restrict__ owproj)
{
    int idx = blockIdx.x * 256 + threadIdx.x;
    if (idx < 16384)        split_f4(wq_b,   owq,              64,   idx);
    else if (idx < 49152)   split_f4(wkv_b,  owkv,             64,   idx - 16384);
    else if (idx < 65536)   split_f4(w_q_a,  owlat,            1024, idx - 49152);
    else if (idx < 81920)   split_f4(w_kv_a, owlat + 64*2048,  1024, idx - 65536);
    else if (idx < 344064) {
        int rel = idx - 81920;
        float4 v = *(const float4*)&w_proj[(size_t)rel * 4];
        *(uint32_t*)&owproj[(size_t)rel * 4]     = hpack(v.x, v.y);
        *(uint32_t*)&owproj[(size_t)rel * 4 + 2] = hpack(v.z, v.w);
    }
}

// ======================================================================
// gemm_bf_body<MODE,KC,NN>: bf16-x3 body (latent-fed GEMMs).
// MODE 0: q-up -> fp16 hi/lo (QSCALE)  MODE 1: kv-up -> fp16 k/v (plain)
// ======================================================================
#define GEMMBF_SMEM 98304

template<int MODE, int KC, int NN>
static __device__ __forceinline__ void gemm_bf_body(
    const __nv_bfloat16* __restrict__ A, const __nv_bfloat16* __restrict__ B,
    __half* __restrict__ H, __half* __restrict__ L, __half* __restrict__ H2,
    int m0, int n0, uint32_t base)
{
    const int tid = threadIdx.x;
    const int w = tid >> 5, lane = tid & 31;
    const int g = lane >> 2, tig = lane & 3;
    const int l8 = lane & 7, sub = lane >> 3;
    const int wm = w & 1, wn = w >> 1;

    int rowp[4], chp[4];
    uint32_t sop[4];
    const __nv_bfloat16 *pa[4], *pb[4];
    #pragma unroll
    for (int p = 0; p < 4; p++) {
        int idx = tid + p * 256;
        rowp[p] = idx >> 3; chp[p] = idx & 7;
        sop[p] = (uint32_t)rowp[p] * 128 +
                 (((uint32_t)chp[p] ^ ((uint32_t)rowp[p] & 7u)) << 4);
        pa[p] = A + (size_t)(m0 + rowp[p]) * KC * 64 + chp[p] * 8;
        pb[p] = B + (size_t)(n0 + rowp[p]) * KC * 64 + chp[p] * 8;
    }

    float c[4][4][4] = {};

    #pragma unroll
    for (int s = 0; s < 3; s++) {
        if (s < KC) {
            #pragma unroll
            for (int p = 0; p < 4; p++) {
                CPA16(base + s * 32768 + sop[p],         pa[p] + s * 64);
                CPA16(base + s * 32768 + 16384 + sop[p], pb[p] + s * 64);
            }
        }
        CPCOMMIT();
    }

    #pragma unroll 3
    for (int cc = 0; cc < KC; cc++) {
        const int rb = cc % 3;
        const uint32_t Ab = base + rb * 32768;
        const uint32_t Bb = Ab + 16384;
        CPWAIT(2);
        __syncthreads();

        #pragma unroll
        for (int ks = 0; ks < 2; ks++) {
            uint32_t ah[4][4], al[4][4];
            #pragma unroll
            for (int mt = 0; mt < 4; mt++) {
                int arow = wm * 64 + mt * 16 + l8 + ((sub & 1) << 3);
                int hch  = 2 * ks + (sub >> 1);
                LDSM4(ah[mt], lda(Ab, arow, hch));
                LDSM4(al[mt], lda(Ab, arow, hch + 4));
            }
            #pragma unroll
            for (int np = 0; np < 2; np++) {
                int brow = wn * 32 + np * 16 + ((sub >> 1) << 3) + l8;
                int bch  = 2 * ks + (sub & 1);
                uint32_t bhf[4], blf[4];
                LDSM4(bhf, lda(Bb, brow, bch));
                LDSM4(blf, lda(Bb, brow, bch + 4));
                #pragma unroll
                for (int mt = 0; mt < 4; mt++) {
                    MMAX3(c[mt][2*np],   ah[mt], al[mt], bhf[0], bhf[1], blf[0], blf[1]);
                    MMAX3(c[mt][2*np+1], ah[mt], al[mt], bhf[2], bhf[3], blf[2], blf[3]);
                }
            }
        }

        __syncthreads();
        if (cc + 3 < KC) {
            #pragma unroll
            for (int p = 0; p < 4; p++) {
                CPA16(Ab + sop[p], pa[p] + (cc + 3) * 64);
                CPA16(Bb + sop[p], pb[p] + (cc + 3) * 64);
            }
        }
        CPCOMMIT();
    }

    if (MODE == 0) {
        #pragma unroll
        for (int mt = 0; mt < 4; mt++)
            #pragma unroll
            for (int nt = 0; nt < 4; nt++) {
                int tok = m0 + wm * 64 + mt * 16 + g;
                int col = n0 + wn * 32 + nt * 8 + 2 * tig;
                int b = tok >> 11, tn = tok & 2047;
                int h = col >> 6, d = col & 63;
                size_t a0 = (((size_t)b * 16 + h) * SEQ + tn) * 64 + d;
                size_t a1 = a0 + 8 * 64;
                uint32_t hp, lp;
                split2h(c[mt][nt][0] * QSCALE, c[mt][nt][1] * QSCALE, hp, lp);
                *(uint32_t*)&H[a0] = hp;  *(uint32_t*)&L[a0] = lp;
                split2h(c[mt][nt][2] * QSCALE, c[mt][nt][3] * QSCALE, hp, lp);
                *(uint32_t*)&H[a1] = hp;  *(uint32_t*)&L[a1] = lp;
            }
    } else {
        #pragma unroll
        for (int mt = 0; mt < 4; mt++)
            #pragma unroll
            for (int nt = 0; nt < 4; nt++) {
                int tok = m0 + wm * 64 + mt * 16 + g;
                int col = n0 + wn * 32 + nt * 8 + 2 * tig;
                int b = tok >> 11, tn = tok & 2047;
                int h = col >> 7, rr = col & 127, d = rr & 63;
                __half* D = (rr < 64) ? H : H2;   // k or v
                size_t a0 = (((size_t)b * 16 + h) * SEQ + tn) * 64 + d;
                size_t a1 = a0 + 8 * 64;
                *(uint32_t*)&D[a0] = hpack(c[mt][nt][0], c[mt][nt][1]);
                *(uint32_t*)&D[a1] = hpack(c[mt][nt][2], c[mt][nt][3]);
            }
    }
}

// merged q-up + kv-up: one launch, grid (24, 64)
__global__ __launch_bounds__(256, 2) void gemm_up_all(
    const __nv_bfloat16* __restrict__ qlat,  const __nv_bfloat16* __restrict__ wq,
    const __nv_bfloat16* __restrict__ kvlat, const __nv_bfloat16* __restrict__ wkv,
    __half* __restrict__ qh, __half* __restrict__ ql,
    __half* __restrict__ kh, __half* __restrict__ vh)
{
    extern __shared__ char smraw[];
    const uint32_t base = smem_u32(smraw);
    const int m0 = blockIdx.y * 128;
    if (blockIdx.x < 8)
        gemm_bf_body<0, 2, 1024>(qlat, wq, qh, ql, nullptr,
                                 m0, blockIdx.x * 128, base);
    else
        gemm_bf_body<1, 2, 2048>(kvlat, wkv, kh, nullptr, vh,
                                 m0, (blockIdx.x - 8) * 128, base);
}

// ======================================================================
// gemm_out_h: out-projection, fp16 x2.
// A = ys [tok][32][32h|32l] fp16 (128B rows), B = wproj plain fp16 [n][k].
// Stage = A 16KB + B 8KB = 24KB; 3-stage ring = 72KB; 2 CTAs/SM.
// ======================================================================
#define GEMMOUT_SMEM 73728

__global__ __launch_bounds__(256, 2) void gemm_out_h(
    const __half* __restrict__ A, const __half* __restrict__ B,
    float* __restrict__ Cf)
{
    extern __shared__ char smraw[];
    const uint32_t base = smem_u32(smraw);
    // stage s: A at base + s*24576 (16KB), B at +16384 (8KB)

    const int tid = threadIdx.x;
    const int w = tid >> 5, lane = tid & 31;
    const int g = lane >> 2, tig = lane & 3;
    const int l8 = lane & 7, sub = lane >> 3;
    const int wm = w & 1, wn = w >> 1;
    const int m0 = blockIdx.y * 128, n0 = blockIdx.x * 128;

    // A staging: 1024 16B pieces -> 4/thread
    int rowa[4], cha[4];
    uint32_t soa[4];
    const __half* pa[4];
    #pragma unroll
    for (int p = 0; p < 4; p++) {
        int idx = tid + p * 256;
        rowa[p] = idx >> 3; cha[p] = idx & 7;
        soa[p] = (uint32_t)rowa[p] * 128 +
                 (((uint32_t)cha[p] ^ ((uint32_t)rowa[p] & 7u)) << 4);
        pa[p] = A + ((size_t)(m0 + rowa[p]) * 32) * 64 + cha[p] * 8;
    }
    // B staging: 512 16B pieces -> 2/thread
    int rowb[2], chb[2];
    uint32_t sob[2];
    const __half* pb[2];
    #pragma unroll
    for (int p = 0; p < 2; p++) {
        int idx = tid + p * 256;
        rowb[p] = idx >> 2; chb[p] = idx & 3;
        sob[p] = ldb(0, rowb[p], chb[p]);
        pb[p] = B + (size_t)(n0 + rowb[p]) * 1024 + chb[p] * 8;
    }

    float c[4][4][4] = {};

    #pragma unroll
    for (int s = 0; s < 3; s++) {
        #pragma unroll
        for (int p = 0; p < 4; p++)
            CPA16(base + s * 24576 + soa[p], pa[p] + s * 64);
        #pragma unroll
        for (int p = 0; p < 2; p++)
            CPA16(base + s * 24576 + 16384 + sob[p], pb[p] + s * 32);
        CPCOMMIT();
    }

    #pragma unroll 3
    for (int cc = 0; cc < 32; cc++) {
        const int rb = cc % 3;
        const uint32_t Ab = base + rb * 24576;
        const uint32_t Bb = Ab + 16384;
        CPWAIT(2);
        __syncthreads();

        #pragma unroll
        for (int ks = 0; ks < 2; ks++) {
            uint32_t ah[4][4], al[4][4];
            #pragma unroll
            for (int mt = 0; mt < 4; mt++) {
                int arow = wm * 64 + mt * 16 + l8 + ((sub & 1) << 3);
                int hch  = 2 * ks + (sub >> 1);
                LDSM4(ah[mt], lda(Ab, arow, hch));
                LDSM4(al[mt], lda(Ab, arow, hch + 4));
            }
            #pragma unroll
            for (int np = 0; np < 2; np++) {
                int brow = wn * 32 + np * 16 + ((sub >> 1) << 3) + l8;
                int bch  = 2 * ks + (sub & 1);
                uint32_t bhf[4];
                LDSM4(bhf, ldb(Bb, brow, bch));
                #pragma unroll
                for (int mt = 0; mt < 4; mt++) {
                    MMAX2(c[mt][2*np],   ah[mt], al[mt], bhf[0], bhf[1]);
                    MMAX2(c[mt][2*np+1], ah[mt], al[mt], bhf[2], bhf[3]);
                }
            }
        }

        __syncthreads();
        if (cc + 3 < 32) {
            #pragma unroll
            for (int p = 0; p < 4; p++)
                CPA16(Ab + soa[p], pa[p] + (cc + 3) * 64);
            #pragma unroll
            for (int p = 0; p < 2; p++)
                CPA16(Bb + sob[p], pb[p] + (cc + 3) * 32);
        }
        CPCOMMIT();
    }

    #pragma unroll
    for (int mt = 0; mt < 4; mt++)
        #pragma unroll
        for (int nt = 0; nt < 4; nt++) {
            int r0 = m0 + wm * 64 + mt * 16 + g;
            int col = n0 + wn * 32 + nt * 8 + 2 * tig;
            *(float2*)&Cf[(size_t)r0 * 1024 + col]       = make_float2(c[mt][nt][0], c[mt][nt][1]);
            *(float2*)&Cf[(size_t)(r0 + 8) * 1024 + col] = make_float2(c[mt][nt][2], c[mt][nt][3]);
        }
}

// ======================================================================
// gemm_latf2: fused latent projections on PRE-SPLIT x. (unchanged)
// ======================================================================
#define LATF_SMEM 73728

__global__ __launch_bounds__(256, 2) void gemm_latf2(
    const __nv_bfloat16* __restrict__ A,
    const __nv_bfloat16* __restrict__ B,
    const float* __restrict__ nwq, const float* __restrict__ nwkv,
    __nv_bfloat16* __restrict__ Cq, __nv_bfloat16* __restrict__ Ckv)
{
    extern __shared__ char smraw[];
    const uint32_t base = smem_u32(smraw);
    __shared__ float nws[128];

    const int tid = threadIdx.x;
    const int w = tid >> 5, lane = tid & 31;
    const int g = lane >> 2, tig = lane & 3;
    const int l8 = lane & 7, sub = lane >> 3;
    const int wm = w >> 1, wn = w & 1;
    const int m0 = blockIdx.x * 64;

    if (tid < 64)       nws[tid] = nwq[tid];
    else if (tid < 128) nws[tid] = nwkv[tid - 64];

    int rowA[2], chA[2], rowB[4], chB[4];
    uint32_t soA[2], soB[4];
    const __nv_bfloat16 *pA[2], *pB[4];
    #pragma unroll
    for (int p = 0; p < 2; p++) {
        int idx = tid + p * 256;
        rowA[p] = idx >> 3; chA[p] = idx & 7;
        soA[p] = (uint32_t)rowA[p] * 128 +
                 (((uint32_t)chA[p] ^ ((uint32_t)rowA[p] & 7u)) << 4);
        pA[p] = A + (size_t)(m0 + rowA[p]) * 2048 + chA[p] * 8;
    }
    #pragma unroll
    for (int p = 0; p < 4; p++) {
        int idx = tid + p * 256;
        rowB[p] = idx >> 3; chB[p] = idx & 7;
        soB[p] = (uint32_t)rowB[p] * 128 +
                 (((uint32_t)chB[p] ^ ((uint32_t)rowB[p] & 7u)) << 4);
        pB[p] = B + (size_t)rowB[p] * 2048 + chB[p] * 8;
    }

    float c[8][4] = {};

    #pragma unroll
    for (int s = 0; s < 3; s++) {
        const uint32_t Ab = base + s * 24576, Bb = Ab + 8192;
        #pragma unroll
        for (int p = 0; p < 2; p++)
            CPA16(Ab + soA[p], pA[p] + s * 64);
        #pragma unroll
        for (int p = 0; p < 4; p++)
            CPA16(Bb + soB[p], pB[p] + s * 64);
        CPCOMMIT();
    }

    #pragma unroll 3
    for (int cc = 0; cc < 32; cc++) {
        const int rb = cc % 3;
        const uint32_t Ab = base + rb * 24576, Bb = Ab + 8192;
        CPWAIT(2);
        __syncthreads();

        #pragma unroll
        for (int ks = 0; ks < 2; ks++) {
            uint32_t ah[4], al[4];
            {
                int arow = wm * 16 + l8 + ((sub & 1) << 3);
                int hch  = 2 * ks + (sub >> 1);
                LDSM4(ah, lda(Ab, arow, hch));
                LDSM4(al, lda(Ab, arow, hch + 4));
            }
            #pragma unroll
            for (int np = 0; np < 4; np++) {
                int brow = wn * 64 + np * 16 + ((sub >> 1) << 3) + l8;
                int bch  = 2 * ks + (sub & 1);
                uint32_t bhf[4], blf[4];
                LDSM4(bhf, lda(Bb, brow, bch));
                LDSM4(blf, lda(Bb, brow, bch + 4));
                MMAX3(c[2*np],   ah, al, bhf[0], bhf[1], blf[0], blf[1]);
                MMAX3(c[2*np+1], ah, al, bhf[2], bhf[3], blf[2], blf[3]);
            }
        }

        __syncthreads();
        if (cc + 3 < 32) {
            #pragma unroll
            for (int p = 0; p < 2; p++)
                CPA16(Ab + soA[p], pA[p] + (cc + 3) * 64);
            #pragma unroll
            for (int p = 0; p < 4; p++)
                CPA16(Bb + soB[p], pB[p] + (cc + 3) * 64);
        }
        CPCOMMIT();
    }

    float p0 = 0.f, p1 = 0.f;
    #pragma unroll
    for (int nt = 0; nt < 8; nt++) {
        p0 += c[nt][0]*c[nt][0] + c[nt][1]*c[nt][1];
        p1 += c[nt][2]*c[nt][2] + c[nt][3]*c[nt][3];
    }
    p0 += __shfl_xor_sync(0xffffffffu, p0, 1);
    p0 += __shfl_xor_sync(0xffffffffu, p0, 2);
    p1 += __shfl_xor_sync(0xffffffffu, p1, 1);
    p1 += __shfl_xor_sync(0xffffffffu, p1, 2);
    float s0 = rsqrtf(p0 * (1.0f/64.0f) + 1e-6f);
    float s1 = rsqrtf(p1 * (1.0f/64.0f) + 1e-6f);

    __nv_bfloat16* C = wn ? Ckv : Cq;
    const int r = m0 + wm * 16 + g;
    #pragma unroll
    for (int nt = 0; nt < 8; nt++) {
        int col = nt * 8 + 2 * tig;
        float w0 = nws[wn * 64 + col], w1 = nws[wn * 64 + col + 1];
        int kc = col >> 5, p = col & 31;
        uint32_t hh, ll;
        size_t b0 = ((size_t)r * 2 + kc) * 64 + p;
        split2(c[nt][0]*s0*w0, c[nt][1]*s0*w1, hh, ll);
        *(uint32_t*)&C[b0] = hh;  *(uint32_t*)&C[b0 + 32] = ll;
        size_t b1 = ((size_t)(r + 8) * 2 + kc) * 64 + p;
        split2(c[nt][2]*s1*w0, c[nt][3]*s1*w1, hh, ll);
        *(uint32_t*)&C[b1] = hh;  *(uint32_t*)&C[b1 + 32] = ll;
    }
}

// ======================================================================
// attn_tc: flash attention, fp16 x2 mma.sync (unchanged core).
// Output ys now fp16 hi/lo split for the x2 out-projection.
// ======================================================================
#define ATTN_SMEM 65536

__global__ __launch_bounds__(256, 2) void attn_tc(
    const __half* __restrict__ qh_g, const __half* __restrict__ ql_g,
    const __half* __restrict__ kh_g, const __half* __restrict__ vh_g,
    __half* __restrict__ ys)
{
    extern __shared__ char smraw[];
    const uint32_t base = smem_u32(smraw);
    const uint32_t Qh = base, Ql = base + 16384;
    const uint32_t kvb = base + 32768;

    const int tid = threadIdx.x;
    const int w = tid >> 5, lane = tid & 31;
    const int g = lane >> 2, tig = lane & 3;
    const int l8 = lane & 7, sub = lane >> 3;
    const int r0 = w * 16;
    const int bh = blockIdx.y;
    const int q0 = blockIdx.x * 128;
    const size_t hb = (size_t)bh * SEQ;

    int rowp[2], chp[2];
    uint32_t sop[2];
    size_t offp[2];
    #pragma unroll
    for (int p = 0; p < 2; p++) {
        int idx = tid + p * 256;
        rowp[p] = idx >> 3; chp[p] = idx & 7;
        sop[p] = (uint32_t)rowp[p] * 128 +
                 (((uint32_t)chp[p] ^ ((uint32_t)rowp[p] & 7u)) << 4);
        offp[p] = (size_t)rowp[p] * 64 + chp[p] * 8;
    }
    const __half* pkh = kh_g + hb * 64;
    const __half* pvh = vh_g + hb * 64;

    #pragma unroll
    for (int p = 0; p < 4; p++) {
        int idx = tid + p * 256, row = idx >> 3, ch = idx & 7;
        size_t go = (hb + q0 + row) * 64 + ch * 8;
        CPA16(lda(Qh, row, ch), qh_g + go);
        CPA16(lda(Ql, row, ch), ql_g + go);
    }
    #pragma unroll
    for (int s = 0; s < 2; s++) {
        const uint32_t Kb = kvb + s * 16384;
        #pragma unroll
        for (int p = 0; p < 2; p++) {
            size_t go = (size_t)s * 4096 + offp[p];
            CPA16(Kb + sop[p],        pkh + go);
            CPA16(Kb + 8192 + sop[p], pvh + go);
        }
        CPCOMMIT();
    }

    float o[8][4] = {};
    float lsum0 = 0.f, lsum1 = 0.f;
    size_t goff = 2 * 4096;

    #pragma unroll 2
    for (int sc = 0; sc < 32; sc++) {
        const int bi = sc & 1;
        const uint32_t Kh = kvb + bi * 16384, Vh = Kh + 8192;
        CPWAIT(1);
        __syncthreads();

        float s[8][4] = {};
        #pragma unroll
        for (int ks = 0; ks < 4; ks++) {
            int arow = r0 + l8 + ((sub & 1) << 3);
            int ach  = 2 * ks + (sub >> 1);
            uint32_t ah[4], al[4];
            LDSM4(ah, lda(Qh, arow, ach));
            LDSM4(al, lda(Ql, arow, ach));
            #pragma unroll
            for (int ntp = 0; ntp < 4; ntp++) {
                int krow = ntp * 16 + ((sub >> 1) << 3) + l8;
                int kch  = 2 * ks + (sub & 1);
                uint32_t bhf[4];
                LDSM4(bhf, lda(Kh, krow, kch));
                MMAX2(s[2 * ntp],     ah, al, bhf[0], bhf[1]);
                MMAX2(s[2 * ntp + 1], ah, al, bhf[2], bhf[3]);
            }
        }

        #pragma unroll
        for (int ks = 0; ks < 4; ks++) {
            float e0 = ex2f(s[2*ks][0]),   e1 = ex2f(s[2*ks][1]);
            float e2 = ex2f(s[2*ks][2]),   e3 = ex2f(s[2*ks][3]);
            float e4 = ex2f(s[2*ks+1][0]), e5 = ex2f(s[2*ks+1][1]);
            float e6 = ex2f(s[2*ks+1][2]), e7 = ex2f(s[2*ks+1][3]);
            lsum0 += e0 + e1 + e4 + e5;
            lsum1 += e2 + e3 + e6 + e7;
            uint32_t ph[4], pl[4];
            split2h(e0, e1, ph[0], pl[0]);
            split2h(e2, e3, ph[1], pl[1]);
            split2h(e4, e5, ph[2], pl[2]);
            split2h(e6, e7, ph[3], pl[3]);
            #pragma unroll
            for (int ntp = 0; ntp < 4; ntp++) {
                int vrow = ks * 16 + ((sub & 1) << 3) + l8;
                int vch  = 2 * ntp + (sub >> 1);
                uint32_t vhf[4];
                LDSM4T(vhf, lda(Vh, vrow, vch));
                MMAX2(o[2 * ntp],     ph, pl, vhf[0], vhf[1]);
                MMAX2(o[2 * ntp + 1], ph, pl, vhf[2], vhf[3]);
            }
        }

        __syncthreads();
        if (sc + 2 < 32) {
            #pragma unroll
            for (int p = 0; p < 2; p++) {
                size_t go = goff + offp[p];
                CPA16(Kh + sop[p],        pkh + go);
                CPA16(Kh + 8192 + sop[p], pvh + go);
            }
        }
        CPCOMMIT();
        goff += 4096;
    }

    lsum0 += __shfl_xor_sync(0xffffffffu, lsum0, 1);
    lsum0 += __shfl_xor_sync(0xffffffffu, lsum0, 2);
    lsum1 += __shfl_xor_sync(0xffffffffu, lsum1, 1);
    lsum1 += __shfl_xor_sync(0xffffffffu, lsum1, 2);
    float inv0 = 1.0f / lsum0, inv1 = 1.0f / lsum1;

    const int b = bh >> 4, h = bh & 15;
    const size_t tok0 = (size_t)b * SEQ + q0 + r0 + g;
    #pragma unroll
    for (int nt = 0; nt < 8; nt++) {
        int col = nt * 8 + 2 * tig;
        int kc = 2 * h + (col >> 5), p = col & 31;
        uint32_t hh, ll;
        size_t b0 = (tok0 * 32 + kc) * 64 + p;
        split2h(o[nt][0] * inv0, o[nt][1] * inv0, hh, ll);
        *(uint32_t*)&ys[b0] = hh;  *(uint32_t*)&ys[b0 + 32] = ll;
        size_t b1 = ((tok0 + 8) * 32 + kc) * 64 + p;
        split2h(o[nt][2] * inv1, o[nt][3] * inv1, hh, ll);
        *(uint32_t*)&ys[b1] = hh;  *(uint32_t*)&ys[b1 + 32] = ll;
    }
}

// ---------------------------------------------------------------------------
extern "C" void kernel_launch(void* const* d_in, const int* in_sizes, int n_in,
                              void* d_out, int out_size)
{
    const float* x      = (const float*)d_in[0];
    const float* w_kv_a = (const float*)d_in[1];
    const float* w_kv_b = (const float*)d_in[2];
    const float* w_q_a  = (const float*)d_in[3];
    const float* w_q_b  = (const float*)d_in[4];
    const float* w_proj = (const float*)d_in[5];
    const float* kv_nw  = (const float*)d_in[6];
    const float* q_nw   = (const float*)d_in[7];
    float* out = (float*)d_out;

    __nv_bfloat16 *xs, *wlat_s, *qlat_s, *kvlat_s, *wq_s, *wkv_s;
    __half *wproj_h, *ysh, *qh, *ql, *kh, *vh;
    cudaGetSymbolAddress((void**)&xs,      g_xs);
    cudaGetSymbolAddress((void**)&wlat_s,  g_wlat_s);
    cudaGetSymbolAddress((void**)&qlat_s,  g_qlat_s);
    cudaGetSymbolAddress((void**)&kvlat_s, g_kvlat_s);
    cudaGetSymbolAddress((void**)&wq_s,    g_wq_s);
    cudaGetSymbolAddress((void**)&wkv_s,   g_wkv_s);
    cudaGetSymbolAddress((void**)&wproj_h, g_wproj_h);
    cudaGetSymbolAddress((void**)&ysh,     g_ysh);
    cudaGetSymbolAddress((void**)&qh, g_qh);  cudaGetSymbolAddress((void**)&ql, g_ql);
    cudaGetSymbolAddress((void**)&kh, g_kh);  cudaGetSymbolAddress((void**)&vh, g_vh);

    cudaFuncSetAttribute(attn_tc,     cudaFuncAttributeMaxDynamicSharedMemorySize, ATTN_SMEM);
    cudaFuncSetAttribute(gemm_up_all, cudaFuncAttributeMaxDynamicSharedMemorySize, GEMMBF_SMEM);
    cudaFuncSetAttribute(gemm_out_h,  cudaFuncAttributeMaxDynamicSharedMemorySize, GEMMOUT_SMEM);
    cudaFuncSetAttribute(gemm_latf2,  cudaFuncAttributeMaxDynamicSharedMemorySize, LATF_SMEM);

    // pre-split: x (big, own launch) + all five weights (one launch)
    wsplit<<<8192, 256>>>(x, xs, 1024, 2097152);
    wsplit5<<<1344, 256>>>(w_q_b, w_kv_b, w_q_a, w_kv_a, w_proj,
                           wq_s, wkv_s, wlat_s, wproj_h);

    // fused latent projections + rmsnorm -> split-interleaved latents
    gemm_latf2<<<128, 256, LATF_SMEM>>>(xs, wlat_s, q_nw, kv_nw, qlat_s, kvlat_s);

    // merged up-projections -> fp16 attention tensors
    gemm_up_all<<<dim3(24, 64), 256, GEMMBF_SMEM>>>(qlat_s, wq_s, kvlat_s, wkv_s,
                                                    qh, ql, kh, vh);

    // attention (fp16 x2) -> fp16 hi/lo split y
    attn_tc<<<dim3(16, 64), 256, ATTN_SMEM>>>(qh, ql, kh, vh, ysh);

    // output projection (fp16 x2, fp32 out)
    gemm_out_h<<<dim3(8, 64), 256, GEMMOUT_SMEM>>>(ysh, wproj_h, out);
}

// round 15
// speedup vs baseline: 1.5102x; 1.0273x over previous
#include <cuda_runtime.h>
#include <cuda_bf16.h>
#include <cuda_fp16.h>
#include <cstdint>

#define SEQ   2048
#define NTOK  8192

// ---------------- scratch (device globals: no runtime allocation) ----------
// fp16 split layout: [row][k/32][32 hi | 32 lo] (128B chunk-rows)
__device__ __half g_xs     [(size_t)NTOK * 2048];   // x split (K=1024)
__device__ __half g_qlat_h [(size_t)NTOK * 128];    // latents split (K=64)
__device__ __half g_kvlat_h[(size_t)NTOK * 128];
__device__ __half g_ysh    [(size_t)NTOK * 2048];   // y split (K=1024)
// plain fp16 weights [n][k] row-major
__device__ __half g_wlat_h [(size_t)128  * 1024];   // [Wq(64)|Wkv(64)]
__device__ __half g_wq_h   [(size_t)1024 * 64];
__device__ __half g_wkv_h  [(size_t)2048 * 64];
__device__ __half g_wproj_h[(size_t)1024 * 1024];
// attention tensors, per-head layout [(b*16+h)][seq][64]
__device__ __half g_qh[(size_t)NTOK * 1024];
__device__ __half g_ql[(size_t)NTOK * 1024];
__device__ __half g_kh[(size_t)NTOK * 1024];
__device__ __half g_vh[(size_t)NTOK * 1024];

#define QSCALE (0.125f * 1.4426950408889634f)   // fold softmax scale * log2e

// ---------------- helpers ---------------------------------------------------
static __device__ __forceinline__ uint32_t smem_u32(const void* p) {
    uint32_t a;
    asm("{ .reg .u64 t; cvta.to.shared.u64 t, %1; cvt.u32.u64 %0, t; }"
        : "=r"(a) : "l"(p));
    return a;
}
static __device__ __forceinline__ uint32_t hpack(float lo, float hi) {
    uint32_t r;
    asm("cvt.rn.f16x2.f32 %0, %1, %2;" : "=r"(r) : "f"(hi), "f"(lo));
    return r;
}
static __device__ __forceinline__ void split2h(float x, float y,
                                               uint32_t& h, uint32_t& l) {
    h = hpack(x, y);
    __half2 hb = *reinterpret_cast<__half2*>(&h);
    l = hpack(x - __half2float(hb.x), y - __half2float(hb.y));
}
static __device__ __forceinline__ float ex2f(float x) {
    float y; asm("ex2.approx.f32 %0, %1;" : "=f"(y) : "f"(x)); return y;
}
// swizzled smem addr: 128B rows of 8 x 16B chunks, chunk ^= row&7
static __device__ __forceinline__ uint32_t lda(uint32_t base, int row, int ch) {
    return base + row * 128 + (((uint32_t)ch ^ ((uint32_t)row & 7u)) << 4);
}
// paired-row layout for 64B rows: 2 rows per 128B line, conflict-free swizzle
static __device__ __forceinline__ uint32_t ldb(uint32_t base, int row, int ch) {
    return base + (uint32_t)(row >> 1) * 128 +
           (((((uint32_t)row & 1u) << 2 | (uint32_t)ch) ^ (((uint32_t)row >> 1) & 7u)) << 4);
}

#define MMAF(c, a0, a1, a2, a3, b0, b1)                                        \
    asm volatile("mma.sync.aligned.m16n8k16.row.col.f32.f16.f16.f32 "          \
        "{%0,%1,%2,%3},{%4,%5,%6,%7},{%8,%9},{%0,%1,%2,%3};"                   \
        : "+f"((c)[0]), "+f"((c)[1]), "+f"((c)[2]), "+f"((c)[3])               \
        : "r"(a0), "r"(a1), "r"(a2), "r"(a3), "r"(b0), "r"(b1))

// fp16 x2: A = hi+lo (exact), B = plain fp16
#define MMAX2(c, ah, al, b0, b1) do {                                          \
    MMAF(c, (ah)[0], (ah)[1], (ah)[2], (ah)[3], b0, b1);                       \
    MMAF(c, (al)[0], (al)[1], (al)[2], (al)[3], b0, b1);                       \
} while (0)

#define LDSM4(r, addr)                                                         \
    asm volatile("ldmatrix.sync.aligned.m8n8.x4.shared.b16 {%0,%1,%2,%3}, [%4];" \
        : "=r"((r)[0]), "=r"((r)[1]), "=r"((r)[2]), "=r"((r)[3]) : "r"(addr))
#define LDSM4T(r, addr)                                                        \
    asm volatile("ldmatrix.sync.aligned.m8n8.x4.trans.shared.b16 {%0,%1,%2,%3}, [%4];" \
        : "=r"((r)[0]), "=r"((r)[1]), "=r"((r)[2]), "=r"((r)[3]) : "r"(addr))
#define CPA16(dst, src)                                                        \
    asm volatile("cp.async.cg.shared.global [%0], [%1], 16;" :: "r"(dst), "l"(src))
#define CPCOMMIT() asm volatile("cp.async.commit_group;" ::: "memory")
#define CPWAIT(n)  asm volatile("cp.async.wait_group %0;" :: "n"(n) : "memory")

// ======================================================================
// split / convert kernels
// ======================================================================
// xsplit_h: X[n][K] fp32 -> O[n][K/32][32h|32l] fp16 (exact hi+lo)
__global__ __launch_bounds__(256) void xsplit_h(
    const float* __restrict__ X, __half* __restrict__ O,
    int K, int nf4)
{
    int idx = blockIdx.x * 256 + threadIdx.x;
    if (idx >= nf4) return;
    int K4 = K >> 2;
    int n = idx / K4, k4 = idx - n * K4;
    float4 v = *(const float4*)&X[(size_t)n * K + k4 * 4];
    int k = k4 * 4, kc = k >> 5, p = k & 31;
    size_t o = ((size_t)n * (K >> 5) + kc) * 64 + p;
    uint32_t h0, l0, h1, l1;
    split2h(v.x, v.y, h0, l0); split2h(v.z, v.w, h1, l1);
    *(uint32_t*)&O[o]      = h0;  *(uint32_t*)&O[o + 2]  = h1;
    *(uint32_t*)&O[o + 32] = l0;  *(uint32_t*)&O[o + 34] = l1;
}

static __device__ __forceinline__ void copy_h4(
    const float* __restrict__ W, __half* __restrict__ O, int rel)
{
    float4 v = *(const float4*)&W[(size_t)rel * 4];
    *(uint32_t*)&O[(size_t)rel * 4]     = hpack(v.x, v.y);
    *(uint32_t*)&O[(size_t)rel * 4 + 2] = hpack(v.z, v.w);
}

// all five weights -> plain fp16, one launch
__global__ __launch_bounds__(256) void wconv5(
    const float* __restrict__ wq_b,  const float* __restrict__ wkv_b,
    const float* __restrict__ w_q_a, const float* __restrict__ w_kv_a,
    const float* __restrict__ w_proj,
    __half* __restrict__ owq,   __half* __restrict__ owkv,
    __half* __restrict__ owlat, __half* __restrict__ owproj)
{
    int idx = blockIdx.x * 256 + threadIdx.x;
    if (idx < 16384)        copy_h4(wq_b,   owq,             idx);
    else if (idx < 49152)   copy_h4(wkv_b,  owkv,            idx - 16384);
    else if (idx < 65536)   copy_h4(w_q_a,  owlat,           idx - 49152);
    else if (idx < 81920)   copy_h4(w_kv_a, owlat + 65536,   idx - 65536);
    else if (idx < 344064)  copy_h4(w_proj, owproj,          idx - 81920);
}

// ======================================================================
// gemm_h_body<MODE,KC,NN>: C = A[M,K] @ B[N,K]^T, fp16 x2.
// A = fp16 hi/lo split [row][KC][32h|32l], B = plain fp16 [row][K].
// Stage = A 16KB + B 8KB = 24KB; 3-stage ring; 2 CTAs/SM.
// MODE 0: q-up -> qh/ql (QSCALE)  MODE 1: kv-up -> k/v  MODE 2: fp32 out
// ======================================================================
#define GEMMH_SMEM 73728

template<int MODE, int KC, int NN>
static __device__ __forceinline__ void gemm_h_body(
    const __half* __restrict__ A, const __half* __restrict__ B,
    float* __restrict__ Cf,
    __half* __restrict__ H, __half* __restrict__ L, __half* __restrict__ H2,
    int m0, int n0, uint32_t base)
{
    const int tid = threadIdx.x;
    const int w = tid >> 5, lane = tid & 31;
    const int g = lane >> 2, tig = lane & 3;
    const int l8 = lane & 7, sub = lane >> 3;
    const int wm = w & 1, wn = w >> 1;

    // A staging: 1024 16B pieces -> 4/thread
    int rowa[4], cha[4];
    uint32_t soa[4];
    const __half* pa[4];
    #pragma unroll
    for (int p = 0; p < 4; p++) {
        int idx = tid + p * 256;
        rowa[p] = idx >> 3; cha[p] = idx & 7;
        soa[p] = (uint32_t)rowa[p] * 128 +
                 (((uint32_t)cha[p] ^ ((uint32_t)rowa[p] & 7u)) << 4);
        pa[p] = A + (size_t)(m0 + rowa[p]) * KC * 64 + cha[p] * 8;
    }
    // B staging: 512 16B pieces -> 2/thread
    int rowb[2], chb[2];
    uint32_t sob[2];
    const __half* pb[2];
    #pragma unroll
    for (int p = 0; p < 2; p++) {
        int idx = tid + p * 256;
        rowb[p] = idx >> 2; chb[p] = idx & 3;
        sob[p] = ldb(0, rowb[p], chb[p]);
        pb[p] = B + (size_t)(n0 + rowb[p]) * KC * 32 + chb[p] * 8;
    }

    float c[4][4][4] = {};

    #pragma unroll
    for (int s = 0; s < 3; s++) {
        if (s < KC) {
            #pragma unroll
            for (int p = 0; p < 4; p++)
                CPA16(base + s * 24576 + soa[p], pa[p] + s * 64);
            #pragma unroll
            for (int p = 0; p < 2; p++)
                CPA16(base + s * 24576 + 16384 + sob[p], pb[p] + s * 32);
        }
        CPCOMMIT();
    }

    #pragma unroll 3
    for (int cc = 0; cc < KC; cc++) {
        const int rb = cc % 3;
        const uint32_t Ab = base + rb * 24576;
        const uint32_t Bb = Ab + 16384;
        CPWAIT(2);
        __syncthreads();

        #pragma unroll
        for (int ks = 0; ks < 2; ks++) {
            uint32_t ah[4][4], al[4][4];
            #pragma unroll
            for (int mt = 0; mt < 4; mt++) {
                int arow = wm * 64 + mt * 16 + l8 + ((sub & 1) << 3);
                int hch  = 2 * ks + (sub >> 1);
                LDSM4(ah[mt], lda(Ab, arow, hch));
                LDSM4(al[mt], lda(Ab, arow, hch + 4));
            }
            #pragma unroll
            for (int np = 0; np < 2; np++) {
                int brow = wn * 32 + np * 16 + ((sub >> 1) << 3) + l8;
                int bch  = 2 * ks + (sub & 1);
                uint32_t bhf[4];
                LDSM4(bhf, ldb(Bb, brow, bch));
                #pragma unroll
                for (int mt = 0; mt < 4; mt++) {
                    MMAX2(c[mt][2*np],   ah[mt], al[mt], bhf[0], bhf[1]);
                    MMAX2(c[mt][2*np+1], ah[mt], al[mt], bhf[2], bhf[3]);
                }
            }
        }

        __syncthreads();
        if (cc + 3 < KC) {
            #pragma unroll
            for (int p = 0; p < 4; p++)
                CPA16(Ab + soa[p], pa[p] + (cc + 3) * 64);
            #pragma unroll
            for (int p = 0; p < 2; p++)
                CPA16(Bb + sob[p], pb[p] + (cc + 3) * 32);
        }
        CPCOMMIT();
    }

    if (MODE == 2) {
        #pragma unroll
        for (int mt = 0; mt < 4; mt++)
            #pragma unroll
            for (int nt = 0; nt < 4; nt++) {
                int r0 = m0 + wm * 64 + mt * 16 + g;
                int col = n0 + wn * 32 + nt * 8 + 2 * tig;
                *(float2*)&Cf[(size_t)r0 * NN + col]       = make_float2(c[mt][nt][0], c[mt][nt][1]);
                *(float2*)&Cf[(size_t)(r0 + 8) * NN + col] = make_float2(c[mt][nt][2], c[mt][nt][3]);
            }
    } else if (MODE == 0) {
        #pragma unroll
        for (int mt = 0; mt < 4; mt++)
            #pragma unroll
            for (int nt = 0; nt < 4; nt++) {
                int tok = m0 + wm * 64 + mt * 16 + g;
                int col = n0 + wn * 32 + nt * 8 + 2 * tig;
                int b = tok >> 11, tn = tok & 2047;
                int h = col >> 6, d = col & 63;
                size_t a0 = (((size_t)b * 16 + h) * SEQ + tn) * 64 + d;
                size_t a1 = a0 + 8 * 64;
                uint32_t hp, lp;
                split2h(c[mt][nt][0] * QSCALE, c[mt][nt][1] * QSCALE, hp, lp);
                *(uint32_t*)&H[a0] = hp;  *(uint32_t*)&L[a0] = lp;
                split2h(c[mt][nt][2] * QSCALE, c[mt][nt][3] * QSCALE, hp, lp);
                *(uint32_t*)&H[a1] = hp;  *(uint32_t*)&L[a1] = lp;
            }
    } else {
        #pragma unroll
        for (int mt = 0; mt < 4; mt++)
            #pragma unroll
            for (int nt = 0; nt < 4; nt++) {
                int tok = m0 + wm * 64 + mt * 16 + g;
                int col = n0 + wn * 32 + nt * 8 + 2 * tig;
                int b = tok >> 11, tn = tok & 2047;
                int h = col >> 7, rr = col & 127, d = rr & 63;
                __half* D = (rr < 64) ? H : H2;   // k or v
                size_t a0 = (((size_t)b * 16 + h) * SEQ + tn) * 64 + d;
                size_t a1 = a0 + 8 * 64;
                *(uint32_t*)&D[a0] = hpack(c[mt][nt][0], c[mt][nt][1]);
                *(uint32_t*)&D[a1] = hpack(c[mt][nt][2], c[mt][nt][3]);
            }
    }
}

// merged q-up + kv-up: one launch, grid (24, 64)
__global__ __launch_bounds__(256, 2) void gemm_up_all(
    const __half* __restrict__ qlat,  const __half* __restrict__ wq,
    const __half* __restrict__ kvlat, const __half* __restrict__ wkv,
    __half* __restrict__ qh, __half* __restrict__ ql,
    __half* __restrict__ kh, __half* __restrict__ vh)
{
    extern __shared__ char smraw[];
    const uint32_t base = smem_u32(smraw);
    const int m0 = blockIdx.y * 128;
    if (blockIdx.x < 8)
        gemm_h_body<0, 2, 1024>(qlat, wq, nullptr, qh, ql, nullptr,
                                m0, blockIdx.x * 128, base);
    else
        gemm_h_body<1, 2, 2048>(kvlat, wkv, nullptr, kh, nullptr, vh,
                                m0, (blockIdx.x - 8) * 128, base);
}

// out-projection
__global__ __launch_bounds__(256, 2) void gemm_out_h(
    const __half* __restrict__ A, const __half* __restrict__ B,
    float* __restrict__ Cf)
{
    extern __shared__ char smraw[];
    const uint32_t base = smem_u32(smraw);
    gemm_h_body<2, 32, 1024>(A, B, Cf, nullptr, nullptr, nullptr,
                             blockIdx.y * 128, blockIdx.x * 128, base);
}

// ======================================================================
// gemm_latf3: fused latent projections, fp16 x2.
// A = xs fp16 split, B = wlat plain fp16 [128][1024].
// M-tile 64, N=128 = [Wq|Wkv], K=1024 -> 32 chunks. Warp tile 16x64.
// Stage = A 8KB + B 8KB = 16KB; ring 48KB.
// ======================================================================
#define LATF_SMEM 49152

__global__ __launch_bounds__(256, 2) void gemm_latf3(
    const __half* __restrict__ A, const __half* __restrict__ B,
    const float* __restrict__ nwq, const float* __restrict__ nwkv,
    __half* __restrict__ Cq, __half* __restrict__ Ckv)
{
    extern __shared__ char smraw[];
    const uint32_t base = smem_u32(smraw);
    __shared__ float nws[128];

    const int tid = threadIdx.x;
    const int w = tid >> 5, lane = tid & 31;
    const int g = lane >> 2, tig = lane & 3;
    const int l8 = lane & 7, sub = lane >> 3;
    const int wm = w >> 1, wn = w & 1;
    const int m0 = blockIdx.x * 64;

    if (tid < 64)       nws[tid] = nwq[tid];
    else if (tid < 128) nws[tid] = nwkv[tid - 64];

    // A: 512 pieces -> 2/thread; B: 512 pieces -> 2/thread
    int rowA[2], chA[2], rowB[2], chB[2];
    uint32_t soA[2], soB[2];
    const __half *pA[2], *pB[2];
    #pragma unroll
    for (int p = 0; p < 2; p++) {
        int idx = tid + p * 256;
        rowA[p] = idx >> 3; chA[p] = idx & 7;
        soA[p] = (uint32_t)rowA[p] * 128 +
                 (((uint32_t)chA[p] ^ ((uint32_t)rowA[p] & 7u)) << 4);
        pA[p] = A + (size_t)(m0 + rowA[p]) * 2048 + chA[p] * 8;
        rowB[p] = idx >> 2; chB[p] = idx & 3;
        soB[p] = ldb(0, rowB[p], chB[p]);
        pB[p] = B + (size_t)rowB[p] * 1024 + chB[p] * 8;
    }

    float c[8][4] = {};

    #pragma unroll
    for (int s = 0; s < 3; s++) {
        const uint32_t Ab = base + s * 16384, Bb = Ab + 8192;
        #pragma unroll
        for (int p = 0; p < 2; p++) {
            CPA16(Ab + soA[p], pA[p] + s * 64);
            CPA16(Bb + soB[p], pB[p] + s * 32);
        }
        CPCOMMIT();
    }

    #pragma unroll 3
    for (int cc = 0; cc < 32; cc++) {
        const int rb = cc % 3;
        const uint32_t Ab = base + rb * 16384, Bb = Ab + 8192;
        CPWAIT(2);
        __syncthreads();

        #pragma unroll
        for (int ks = 0; ks < 2; ks++) {
            uint32_t ah[4], al[4];
            {
                int arow = wm * 16 + l8 + ((sub & 1) << 3);
                int hch  = 2 * ks + (sub >> 1);
                LDSM4(ah, lda(Ab, arow, hch));
                LDSM4(al, lda(Ab, arow, hch + 4));
            }
            #pragma unroll
            for (int np = 0; np < 4; np++) {
                int brow = wn * 64 + np * 16 + ((sub >> 1) << 3) + l8;
                int bch  = 2 * ks + (sub & 1);
                uint32_t bhf[4];
                LDSM4(bhf, ldb(Bb, brow, bch));
                MMAX2(c[2*np],   ah, al, bhf[0], bhf[1]);
                MMAX2(c[2*np+1], ah, al, bhf[2], bhf[3]);
            }
        }

        __syncthreads();
        if (cc + 3 < 32) {
            #pragma unroll
            for (int p = 0; p < 2; p++) {
                CPA16(Ab + soA[p], pA[p] + (cc + 3) * 64);
                CPA16(Bb + soB[p], pB[p] + (cc + 3) * 32);
            }
        }
        CPCOMMIT();
    }

    // rmsnorm: whole 64-wide row lives in this warp -> shfl over tig
    float p0 = 0.f, p1 = 0.f;
    #pragma unroll
    for (int nt = 0; nt < 8; nt++) {
        p0 += c[nt][0]*c[nt][0] + c[nt][1]*c[nt][1];
        p1 += c[nt][2]*c[nt][2] + c[nt][3]*c[nt][3];
    }
    p0 += __shfl_xor_sync(0xffffffffu, p0, 1);
    p0 += __shfl_xor_sync(0xffffffffu, p0, 2);
    p1 += __shfl_xor_sync(0xffffffffu, p1, 1);
    p1 += __shfl_xor_sync(0xffffffffu, p1, 2);
    float s0 = rsqrtf(p0 * (1.0f/64.0f) + 1e-6f);
    float s1 = rsqrtf(p1 * (1.0f/64.0f) + 1e-6f);

    __half* C = wn ? Ckv : Cq;
    const int r = m0 + wm * 16 + g;
    #pragma unroll
    for (int nt = 0; nt < 8; nt++) {
        int col = nt * 8 + 2 * tig;
        float w0 = nws[wn * 64 + col], w1 = nws[wn * 64 + col + 1];
        int kc = col >> 5, p = col & 31;
        uint32_t hh, ll;
        size_t b0 = ((size_t)r * 2 + kc) * 64 + p;
        split2h(c[nt][0]*s0*w0, c[nt][1]*s0*w1, hh, ll);
        *(uint32_t*)&C[b0] = hh;  *(uint32_t*)&C[b0 + 32] = ll;
        size_t b1 = ((size_t)(r + 8) * 2 + kc) * 64 + p;
        split2h(c[nt][2]*s1*w0, c[nt][3]*s1*w1, hh, ll);
        *(uint32_t*)&C[b1] = hh;  *(uint32_t*)&C[b1 + 32] = ll;
    }
}

// ======================================================================
// attn_tc: flash attention, fp16 x2 mma.sync (unchanged from R14).
// ======================================================================
#define ATTN_SMEM 65536

__global__ __launch_bounds__(256, 2) void attn_tc(
    const __half* __restrict__ qh_g, const __half* __restrict__ ql_g,
    const __half* __restrict__ kh_g, const __half* __restrict__ vh_g,
    __half* __restrict__ ys)
{
    extern __shared__ char smraw[];
    const uint32_t base = smem_u32(smraw);
    const uint32_t Qh = base, Ql = base + 16384;
    const uint32_t kvb = base + 32768;

    const int tid = threadIdx.x;
    const int w = tid >> 5, lane = tid & 31;
    const int g = lane >> 2, tig = lane & 3;
    const int l8 = lane & 7, sub = lane >> 3;
    const int r0 = w * 16;
    const int bh = blockIdx.y;
    const int q0 = blockIdx.x * 128;
    const size_t hb = (size_t)bh * SEQ;

    int rowp[2], chp[2];
    uint32_t sop[2];
    size_t offp[2];
    #pragma unroll
    for (int p = 0; p < 2; p++) {
        int idx = tid + p * 256;
        rowp[p] = idx >> 3; chp[p] = idx & 7;
        sop[p] = (uint32_t)rowp[p] * 128 +
                 (((uint32_t)chp[p] ^ ((uint32_t)rowp[p] & 7u)) << 4);
        offp[p] = (size_t)rowp[p] * 64 + chp[p] * 8;
    }
    const __half* pkh = kh_g + hb * 64;
    const __half* pvh = vh_g + hb * 64;

    #pragma unroll
    for (int p = 0; p < 4; p++) {
        int idx = tid + p * 256, row = idx >> 3, ch = idx & 7;
        size_t go = (hb + q0 + row) * 64 + ch * 8;
        CPA16(lda(Qh, row, ch), qh_g + go);
        CPA16(lda(Ql, row, ch), ql_g + go);
    }
    #pragma unroll
    for (int s = 0; s < 2; s++) {
        const uint32_t Kb = kvb + s * 16384;
        #pragma unroll
        for (int p = 0; p < 2; p++) {
            size_t go = (size_t)s * 4096 + offp[p];
            CPA16(Kb + sop[p],        pkh + go);
            CPA16(Kb + 8192 + sop[p], pvh + go);
        }
        CPCOMMIT();
    }

    float o[8][4] = {};
    float lsum0 = 0.f, lsum1 = 0.f;
    size_t goff = 2 * 4096;

    #pragma unroll 2
    for (int sc = 0; sc < 32; sc++) {
        const int bi = sc & 1;
        const uint32_t Kh = kvb + bi * 16384, Vh = Kh + 8192;
        CPWAIT(1);
        __syncthreads();

        float s[8][4] = {};
        #pragma unroll
        for (int ks = 0; ks < 4; ks++) {
            int arow = r0 + l8 + ((sub & 1) << 3);
            int ach  = 2 * ks + (sub >> 1);
            uint32_t ah[4], al[4];
            LDSM4(ah, lda(Qh, arow, ach));
            LDSM4(al, lda(Ql, arow, ach));
            #pragma unroll
            for (int ntp = 0; ntp < 4; ntp++) {
                int krow = ntp * 16 + ((sub >> 1) << 3) + l8;
                int kch  = 2 * ks + (sub & 1);
                uint32_t bhf[4];
                LDSM4(bhf, lda(Kh, krow, kch));
                MMAX2(s[2 * ntp],     ah, al, bhf[0], bhf[1]);
                MMAX2(s[2 * ntp + 1], ah, al, bhf[2], bhf[3]);
            }
        }

        #pragma unroll
        for (int ks = 0; ks < 4; ks++) {
            float e0 = ex2f(s[2*ks][0]),   e1 = ex2f(s[2*ks][1]);
            float e2 = ex2f(s[2*ks][2]),   e3 = ex2f(s[2*ks][3]);
            float e4 = ex2f(s[2*ks+1][0]), e5 = ex2f(s[2*ks+1][1]);
            float e6 = ex2f(s[2*ks+1][2]), e7 = ex2f(s[2*ks+1][3]);
            lsum0 += e0 + e1 + e4 + e5;
            lsum1 += e2 + e3 + e6 + e7;
            uint32_t ph[4], pl[4];
            split2h(e0, e1, ph[0], pl[0]);
            split2h(e2, e3, ph[1], pl[1]);
            split2h(e4, e5, ph[2], pl[2]);
            split2h(e6, e7, ph[3], pl[3]);
            #pragma unroll
            for (int ntp = 0; ntp < 4; ntp++) {
                int vrow = ks * 16 + ((sub & 1) << 3) + l8;
                int vch  = 2 * ntp + (sub >> 1);
                uint32_t vhf[4];
                LDSM4T(vhf, lda(Vh, vrow, vch));
                MMAX2(o[2 * ntp],     ph, pl, vhf[0], vhf[1]);
                MMAX2(o[2 * ntp + 1], ph, pl, vhf[2], vhf[3]);
            }
        }

        __syncthreads();
        if (sc + 2 < 32) {
            #pragma unroll
            for (int p = 0; p < 2; p++) {
                size_t go = goff + offp[p];
                CPA16(Kh + sop[p],        pkh + go);
                CPA16(Kh + 8192 + sop[p], pvh + go);
            }
        }
        CPCOMMIT();
        goff += 4096;
    }

    lsum0 += __shfl_xor_sync(0xffffffffu, lsum0, 1);
    lsum0 += __shfl_xor_sync(0xffffffffu, lsum0, 2);
    lsum1 += __shfl_xor_sync(0xffffffffu, lsum1, 1);
    lsum1 += __shfl_xor_sync(0xffffffffu, lsum1, 2);
    float inv0 = 1.0f / lsum0, inv1 = 1.0f / lsum1;

    const int b = bh >> 4, h = bh & 15;
    const size_t tok0 = (size_t)b * SEQ + q0 + r0 + g;
    #pragma unroll
    for (int nt = 0; nt < 8; nt++) {
        int col = nt * 8 + 2 * tig;
        int kc = 2 * h + (col >> 5), p = col & 31;
        uint32_t hh, ll;
        size_t b0 = (tok0 * 32 + kc) * 64 + p;
        split2h(o[nt][0] * inv0, o[nt][1] * inv0, hh, ll);
        *(uint32_t*)&ys[b0] = hh;  *(uint32_t*)&ys[b0 + 32] = ll;
        size_t b1 = ((tok0 + 8) * 32 + kc) * 64 + p;
        split2h(o[nt][2] * inv1, o[nt][3] * inv1, hh, ll);
        *(uint32_t*)&ys[b1] = hh;  *(uint32_t*)&ys[b1 + 32] = ll;
    }
}

// ---------------------------------------------------------------------------
extern "C" void kernel_launch(void* const* d_in, const int* in_sizes, int n_in,
                              void* d_out, int out_size)
{
    const float* x      = (const float*)d_in[0];
    const float* w_kv_a = (const float*)d_in[1];
    const float* w_kv_b = (const float*)d_in[2];
    const float* w_q_a  = (const float*)d_in[3];
    const float* w_q_b  = (const float*)d_in[4];
    const float* w_proj = (const float*)d_in[5];
    const float* kv_nw  = (const float*)d_in[6];
    const float* q_nw   = (const float*)d_in[7];
    float* out = (float*)d_out;

    __half *xs, *wlat_h, *qlat_h, *kvlat_h, *wq_h, *wkv_h, *wproj_h, *ysh;
    __half *qh, *ql, *kh, *vh;
    cudaGetSymbolAddress((void**)&xs,      g_xs);
    cudaGetSymbolAddress((void**)&wlat_h,  g_wlat_h);
    cudaGetSymbolAddress((void**)&qlat_h,  g_qlat_h);
    cudaGetSymbolAddress((void**)&kvlat_h, g_kvlat_h);
    cudaGetSymbolAddress((void**)&wq_h,    g_wq_h);
    cudaGetSymbolAddress((void**)&wkv_h,   g_wkv_h);
    cudaGetSymbolAddress((void**)&wproj_h, g_wproj_h);
    cudaGetSymbolAddress((void**)&ysh,     g_ysh);
    cudaGetSymbolAddress((void**)&qh, g_qh);  cudaGetSymbolAddress((void**)&ql, g_ql);
    cudaGetSymbolAddress((void**)&kh, g_kh);  cudaGetSymbolAddress((void**)&vh, g_vh);

    cudaFuncSetAttribute(attn_tc,     cudaFuncAttributeMaxDynamicSharedMemorySize, ATTN_SMEM);
    cudaFuncSetAttribute(gemm_up_all, cudaFuncAttributeMaxDynamicSharedMemorySize, GEMMH_SMEM);
    cudaFuncSetAttribute(gemm_out_h,  cudaFuncAttributeMaxDynamicSharedMemorySize, GEMMH_SMEM);
    cudaFuncSetAttribute(gemm_latf3,  cudaFuncAttributeMaxDynamicSharedMemorySize, LATF_SMEM);

    // pre-convert: x -> fp16 split (own launch), weights -> plain fp16 (one launch)
    xsplit_h<<<8192, 256>>>(x, xs, 1024, 2097152);
    wconv5<<<1344, 256>>>(w_q_b, w_kv_b, w_q_a, w_kv_a, w_proj,
                          wq_h, wkv_h, wlat_h, wproj_h);

    // fused latent projections + rmsnorm (fp16 x2) -> fp16 split latents
    gemm_latf3<<<128, 256, LATF_SMEM>>>(xs, wlat_h, q_nw, kv_nw, qlat_h, kvlat_h);

    // merged up-projections (fp16 x2) -> fp16 attention tensors
    gemm_up_all<<<dim3(24, 64), 256, GEMMH_SMEM>>>(qlat_h, wq_h, kvlat_h, wkv_h,
                                                   qh, ql, kh, vh);

    // attention (fp16 x2) -> fp16 hi/lo split y
    attn_tc<<<dim3(16, 64), 256, ATTN_SMEM>>>(qh, ql, kh, vh, ysh);

    // output projection (fp16 x2, fp32 out)
    gemm_out_h<<<dim3(8, 64), 256, GEMMH_SMEM>>>(ysh, wproj_h, out);
}